// round 1
// baseline (speedup 1.0000x reference)
#include <cuda_runtime.h>
#include <math.h>

#define BB 4
#define TT 1024
#define DD 2048
#define NH 16
#define NKV 4
#define HD 128
#define MROWS (BB*TT)   // 4096

// Scratch (device globals; no runtime allocation)
__device__ float g_Q[MROWS * DD];          // [B*T, 16*128]
__device__ float g_K[MROWS * NKV * HD];    // [B*T, 4*128]
__device__ float g_V[MROWS * NKV * HD];
__device__ float g_Y[MROWS * DD];          // attention output, [B*T, 2048]

// ---------------------------------------------------------------------------
// SGEMM: C[M,N] = A[M,K] @ B[K,N], row-major fp32. 128x128x8 tile, 256 thr,
// 8x8 micro-tile with split-tile register mapping (conflict-free LDS.128).
// Requires M%128==0, N%128==0, K%8==0.
// ---------------------------------------------------------------------------
__global__ __launch_bounds__(256) void sgemm128(
    const float* __restrict__ A, const float* __restrict__ Bm,
    float* __restrict__ C, int M, int N, int K)
{
    __shared__ float As[8][128];
    __shared__ float Bs[8][128];
    const int tid = threadIdx.x;
    const int bm = blockIdx.y * 128;
    const int bn = blockIdx.x * 128;
    const int tr = tid >> 4;           // 0..15
    const int tc = tid & 15;           // 0..15

    const int ar = tid >> 1;           // 0..127
    const int ac = (tid & 1) * 4;      // 0 or 4
    const int br = tid >> 5;           // 0..7
    const int bc = (tid & 31) * 4;     // 0..124

    float acc[8][8];
#pragma unroll
    for (int i = 0; i < 8; i++)
#pragma unroll
        for (int j = 0; j < 8; j++) acc[i][j] = 0.f;

    for (int k0 = 0; k0 < K; k0 += 8) {
        float4 a = *(const float4*)(A + (size_t)(bm + ar) * K + k0 + ac);
        float4 b = *(const float4*)(Bm + (size_t)(k0 + br) * N + bn + bc);
        As[ac + 0][ar] = a.x; As[ac + 1][ar] = a.y;
        As[ac + 2][ar] = a.z; As[ac + 3][ar] = a.w;
        *(float4*)&Bs[br][bc] = b;
        __syncthreads();
#pragma unroll
        for (int kk = 0; kk < 8; kk++) {
            float4 a0 = *(const float4*)&As[kk][tr * 4];
            float4 a1 = *(const float4*)&As[kk][tr * 4 + 64];
            float4 b0 = *(const float4*)&Bs[kk][tc * 4];
            float4 b1 = *(const float4*)&Bs[kk][tc * 4 + 64];
            float av[8] = {a0.x, a0.y, a0.z, a0.w, a1.x, a1.y, a1.z, a1.w};
            float bv[8] = {b0.x, b0.y, b0.z, b0.w, b1.x, b1.y, b1.z, b1.w};
#pragma unroll
            for (int i = 0; i < 8; i++)
#pragma unroll
                for (int j = 0; j < 8; j++)
                    acc[i][j] = fmaf(av[i], bv[j], acc[i][j]);
        }
        __syncthreads();
    }
#pragma unroll
    for (int i = 0; i < 8; i++) {
        int row = bm + ((i < 4) ? (tr * 4 + i) : (64 + tr * 4 + i - 4));
#pragma unroll
        for (int jb = 0; jb < 2; jb++) {
            float4 o = make_float4(acc[i][jb * 4 + 0], acc[i][jb * 4 + 1],
                                   acc[i][jb * 4 + 2], acc[i][jb * 4 + 3]);
            *(float4*)(C + (size_t)row * N + bn + tc * 4 + jb * 64) = o;
        }
    }
}

// ---------------------------------------------------------------------------
// RoPE in place on X laid out [B*T, heads*128].
// grid: (B*T, heads), block: 128 threads (one per dim of one head vector)
// ---------------------------------------------------------------------------
__global__ void rope_kernel(float* __restrict__ X, int heads)
{
    int bt = blockIdx.x;
    int t  = bt & (TT - 1);
    int hh = blockIdx.y;
    float* v = X + ((size_t)bt * heads + hh) * HD;
    int d = threadIdx.x;
    int i = d & 63;
    float ang = (float)t * powf(10000.0f, -(float)i / 64.0f);
    float c, s;
    __sincosf(ang, &s, &c);
    // use precise versions for accuracy of table
    c = cosf(ang); s = sinf(ang);
    float x1 = v[d];
    float x2 = v[d ^ 64];
    __syncthreads();
    float rot = (d < 64) ? -x2 : x2;
    v[d] = x1 * c + rot * s;
}

// ---------------------------------------------------------------------------
// Flash attention, causal, GQA (16 q-heads over 4 kv-heads).
// grid: (T/64, NH, B), block 256 threads, dynamic smem 115200 B.
// Q layout [B*T, 16*128] (post-RoPE); K,V layout [B*T, 4*128].
// Output Y [B*T, 2048] with column h*128+d.
// ---------------------------------------------------------------------------
#define BQ 64
#define BS 64
#define ATTN_SMEM ((128*64 + 128*64 + 64*128 + 64*65 + 64) * 4)

__global__ __launch_bounds__(256) void attn_kernel(
    const float* __restrict__ Q, const float* __restrict__ K,
    const float* __restrict__ V, float* __restrict__ Y)
{
    extern __shared__ float sm[];
    float* Qs = sm;                 // [128][64]  d-major
    float* Ks = Qs + 128 * 64;      // [128][64]  d-major
    float* Vs = Ks + 128 * 64;      // [64][128]  s-major
    float* Ss = Vs + 64 * 128;      // [64][65]
    float* cw = Ss + 64 * 65;       // [64] correction factors
    __shared__ float mrow[64], lrow[64];

    const int tid = threadIdx.x;
    const int qt = gridDim.x - 1 - blockIdx.x;   // heavy blocks first
    const int hh = blockIdx.y;
    const int b  = blockIdx.z;
    const int gkv = hh >> 2;         // repeat: head hh -> kv head hh/4
    const int q0 = qt * BQ;

    // load Q tile transposed: Qs[d][q]
    for (int idx = tid; idx < BQ * 32; idx += 256) {
        int q = idx >> 5;
        int d4 = (idx & 31) * 4;
        float4 t4 = *(const float4*)&Q[((size_t)(b * TT + q0 + q) * NH + hh) * HD + d4];
        Qs[(d4 + 0) * 64 + q] = t4.x;
        Qs[(d4 + 1) * 64 + q] = t4.y;
        Qs[(d4 + 2) * 64 + q] = t4.z;
        Qs[(d4 + 3) * 64 + q] = t4.w;
    }
    if (tid < 64) { mrow[tid] = -1e30f; lrow[tid] = 0.f; }

    float acc[32];
#pragma unroll
    for (int i = 0; i < 32; i++) acc[i] = 0.f;

    const int r  = tid >> 2;          // PV output row
    const int cb = (tid & 3) * 32;    // PV output col base
    const int sr = (tid >> 4) * 4;    // S micro rows
    const int sc = (tid & 15) * 4;    // S micro cols
    const float scale = 0.08838834764831845f;  // 1/sqrt(128)

    __syncthreads();

    const int ntiles = qt + 1;
    for (int st = 0; st < ntiles; st++) {
        const int s0 = st * BS;
        // load K (transposed) and V
        for (int idx = tid; idx < BS * 32; idx += 256) {
            int s = idx >> 5;
            int d4 = (idx & 31) * 4;
            const float* kp = &K[((size_t)(b * TT + s0 + s) * NKV + gkv) * HD + d4];
            float4 kv = *(const float4*)kp;
            Ks[(d4 + 0) * 64 + s] = kv.x;
            Ks[(d4 + 1) * 64 + s] = kv.y;
            Ks[(d4 + 2) * 64 + s] = kv.z;
            Ks[(d4 + 3) * 64 + s] = kv.w;
            float4 vv = *(const float4*)&V[((size_t)(b * TT + s0 + s) * NKV + gkv) * HD + d4];
            *(float4*)&Vs[s * 128 + d4] = vv;
        }
        __syncthreads();

        // S = Q @ K^T (64x64), 4x4 micro per thread
        float sv[4][4];
#pragma unroll
        for (int i = 0; i < 4; i++)
#pragma unroll
            for (int j = 0; j < 4; j++) sv[i][j] = 0.f;
#pragma unroll 8
        for (int d = 0; d < 128; d++) {
            float4 a = *(const float4*)&Qs[d * 64 + sr];
            float4 bb = *(const float4*)&Ks[d * 64 + sc];
            float av[4] = {a.x, a.y, a.z, a.w};
            float bv[4] = {bb.x, bb.y, bb.z, bb.w};
#pragma unroll
            for (int i = 0; i < 4; i++)
#pragma unroll
                for (int j = 0; j < 4; j++)
                    sv[i][j] = fmaf(av[i], bv[j], sv[i][j]);
        }
        // mask + scale -> Ss
#pragma unroll
        for (int i = 0; i < 4; i++) {
            int qq = q0 + sr + i;
#pragma unroll
            for (int j = 0; j < 4; j++) {
                int ss = s0 + sc + j;
                Ss[(sr + i) * 65 + sc + j] = (ss <= qq) ? sv[i][j] * scale : -1e30f;
            }
        }
        __syncthreads();

        // online softmax: one thread per q row
        if (tid < 64) {
            float m_old = mrow[tid];
            float mx = m_old;
            const float* srow = &Ss[tid * 65];
#pragma unroll 8
            for (int j = 0; j < 64; j++) mx = fmaxf(mx, srow[j]);
            float sum = 0.f;
            float* prow = &Ss[tid * 65];
#pragma unroll 8
            for (int j = 0; j < 64; j++) {
                float p = __expf(prow[j] - mx);
                prow[j] = p;
                sum += p;
            }
            float corr = __expf(m_old - mx);
            lrow[tid] = lrow[tid] * corr + sum;
            mrow[tid] = mx;
            cw[tid] = corr;
        }
        __syncthreads();

        // O = O*corr + P @ V
        float corr = cw[r];
#pragma unroll
        for (int i = 0; i < 32; i++) acc[i] *= corr;
        const float* prow = &Ss[r * 65];
#pragma unroll 4
        for (int s = 0; s < 64; s++) {
            float p = prow[s];
            const float* vrow = &Vs[s * 128 + cb];
#pragma unroll
            for (int i = 0; i < 32; i += 4) {
                float4 v4 = *(const float4*)&vrow[i];
                acc[i + 0] = fmaf(p, v4.x, acc[i + 0]);
                acc[i + 1] = fmaf(p, v4.y, acc[i + 1]);
                acc[i + 2] = fmaf(p, v4.z, acc[i + 2]);
                acc[i + 3] = fmaf(p, v4.w, acc[i + 3]);
            }
        }
        __syncthreads();
    }

    // epilogue
    float linv = 1.f / lrow[r];
    float* yp = &Y[(size_t)(b * TT + q0 + r) * DD + hh * HD + cb];
#pragma unroll
    for (int i = 0; i < 32; i += 4) {
        float4 o = make_float4(acc[i] * linv, acc[i + 1] * linv,
                               acc[i + 2] * linv, acc[i + 3] * linv);
        *(float4*)&yp[i] = o;
    }
}

// ---------------------------------------------------------------------------
extern "C" void kernel_launch(void* const* d_in, const int* in_sizes, int n_in,
                              void* d_out, int out_size)
{
    const float* x  = (const float*)d_in[0];
    const float* Wq = (const float*)d_in[1];
    const float* Wk = (const float*)d_in[2];
    const float* Wv = (const float*)d_in[3];
    const float* Wo = (const float*)d_in[4];
    float* out = (float*)d_out;

    float *Qp, *Kp, *Vp, *Yp;
    cudaGetSymbolAddress((void**)&Qp, g_Q);
    cudaGetSymbolAddress((void**)&Kp, g_K);
    cudaGetSymbolAddress((void**)&Vp, g_V);
    cudaGetSymbolAddress((void**)&Yp, g_Y);

    static bool attr_set = false;
    if (!attr_set) {
        cudaFuncSetAttribute(attn_kernel,
                             cudaFuncAttributeMaxDynamicSharedMemorySize,
                             ATTN_SMEM);
        attr_set = true;
    }

    // Projections
    sgemm128<<<dim3(DD / 128, MROWS / 128), 256>>>(x, Wq, Qp, MROWS, DD, DD);
    sgemm128<<<dim3((NKV * HD) / 128, MROWS / 128), 256>>>(x, Wk, Kp, MROWS, NKV * HD, DD);
    sgemm128<<<dim3((NKV * HD) / 128, MROWS / 128), 256>>>(x, Wv, Vp, MROWS, NKV * HD, DD);

    // RoPE on Q and K
    rope_kernel<<<dim3(MROWS, NH), 128>>>(Qp, NH);
    rope_kernel<<<dim3(MROWS, NKV), 128>>>(Kp, NKV);

    // Attention
    attn_kernel<<<dim3(TT / BQ, NH, BB), 256, ATTN_SMEM>>>(Qp, Kp, Vp, Yp);

    // Output projection
    sgemm128<<<dim3(DD / 128, MROWS / 128), 256>>>(Yp, Wo, out, MROWS, DD, DD);
}

// round 2
// speedup vs baseline: 1.4166x; 1.4166x over previous
#include <cuda_runtime.h>
#include <math.h>
#include <stdint.h>

#define BB 4
#define TT 1024
#define DD 2048
#define NH 16
#define NKV 4
#define HD 128
#define MROWS (BB*TT)   // 4096

// Scratch (device globals; no runtime allocation)
__device__ float g_Q[MROWS * DD];          // [B*T, 16*128]
__device__ float g_K[MROWS * NKV * HD];    // [B*T, 4*128]
__device__ float g_V[MROWS * NKV * HD];
__device__ float g_Y[MROWS * DD];          // attention output, [B*T, 2048]

// ---------------------------------------------------------------------------
// TF32 tensor-core GEMM: C[M,N] = A[M,K] @ B[K,N], row-major fp32 in/out.
// CTA tile 128x128, KT=32, 256 threads = 8 warps (4 M x 2 N), warp tile 32x64.
// mma.sync.m16n8k8 tf32, cvt.rna rounding at smem-store time.
// Requires M%128==0, N%128==0, K%32==0.
// ---------------------------------------------------------------------------
#define KT 32
#define ASTR 36
#define BSTR 136
#define ABUF (128*ASTR)      // 4608 words
#define BBUF (KT*BSTR)       // 4352 words
#define GEMM_SMEM ((ABUF + BBUF) * 2 * 4)   // 71680 bytes

__device__ __forceinline__ uint32_t f2tf32(float f) {
    uint32_t r;
    asm("cvt.rna.tf32.f32 %0, %1;" : "=r"(r) : "f"(f));
    return r;
}

__global__ __launch_bounds__(256, 1) void gemm_tf32(
    const float* __restrict__ A, const float* __restrict__ B,
    float* __restrict__ C, int M, int N, int K)
{
    extern __shared__ uint32_t smg[];
    uint32_t* As = smg;              // [2][ABUF]
    uint32_t* Bs = smg + 2 * ABUF;   // [2][BBUF]

    const int tid  = threadIdx.x;
    const int bm   = blockIdx.y * 128;
    const int bn   = blockIdx.x * 128;
    const int warp = tid >> 5, lane = tid & 31;
    const int wm   = (warp & 3) * 32;    // warp M offset
    const int wn   = (warp >> 2) * 64;   // warp N offset
    const int gID  = lane >> 2, tig = lane & 3;

    const int arow = tid >> 3,  acol = (tid & 7) << 2;   // A staging map
    const int brow = tid >> 5,  bcol = (tid & 31) << 2;  // B staging map
    const float* Ag = A + (size_t)(bm + arow) * K + acol;
    const float* Bg = B + (size_t)brow * N + bn + bcol;

    float ra[4][4], rb[4][4];
    float acc[2][8][4];
#pragma unroll
    for (int i = 0; i < 2; i++)
#pragma unroll
        for (int j = 0; j < 8; j++)
#pragma unroll
            for (int l = 0; l < 4; l++) acc[i][j][l] = 0.f;

    const int NT = K / KT;

    auto LDG = [&](int kt) {
        const float* a = Ag + kt * KT;
#pragma unroll
        for (int i = 0; i < 4; i++)
            *(float4*)ra[i] = *(const float4*)(a + (size_t)(32 * i) * K);
        const float* b = Bg + (size_t)kt * KT * N;
#pragma unroll
        for (int i = 0; i < 4; i++)
            *(float4*)rb[i] = *(const float4*)(b + (size_t)(8 * i) * N);
    };
    auto STS = [&](int buf) {
        uint32_t* as = As + buf * ABUF;
#pragma unroll
        for (int i = 0; i < 4; i++)
#pragma unroll
            for (int j = 0; j < 4; j++)
                as[(arow + 32 * i) * ASTR + acol + j] = f2tf32(ra[i][j]);
        uint32_t* bs = Bs + buf * BBUF;
#pragma unroll
        for (int i = 0; i < 4; i++)
#pragma unroll
            for (int j = 0; j < 4; j++)
                bs[(brow + 8 * i) * BSTR + bcol + j] = f2tf32(rb[i][j]);
    };

    LDG(0); STS(0); __syncthreads();

    for (int kt = 0; kt < NT; kt++) {
        const int buf = kt & 1;
        if (kt + 1 < NT) LDG(kt + 1);

        const uint32_t* as = As + buf * ABUF + (wm + gID) * ASTR;
        const uint32_t* bs = Bs + buf * BBUF + wn + gID;
#pragma unroll
        for (int kk = 0; kk < 4; kk++) {
            const int k0 = kk * 8;
            uint32_t af[2][4], bf[8][2];
#pragma unroll
            for (int mi = 0; mi < 2; mi++) {
                const uint32_t* ap = as + mi * 16 * ASTR + k0 + tig;
                af[mi][0] = ap[0];
                af[mi][1] = ap[8 * ASTR];
                af[mi][2] = ap[4];
                af[mi][3] = ap[8 * ASTR + 4];
            }
#pragma unroll
            for (int ni = 0; ni < 8; ni++) {
                const uint32_t* bp = bs + (k0 + tig) * BSTR + ni * 8;
                bf[ni][0] = bp[0];
                bf[ni][1] = bp[4 * BSTR];
            }
#pragma unroll
            for (int mi = 0; mi < 2; mi++)
#pragma unroll
                for (int ni = 0; ni < 8; ni++)
                    asm volatile(
                        "mma.sync.aligned.m16n8k8.row.col.f32.tf32.tf32.f32 "
                        "{%0,%1,%2,%3}, {%4,%5,%6,%7}, {%8,%9}, {%0,%1,%2,%3};"
                        : "+f"(acc[mi][ni][0]), "+f"(acc[mi][ni][1]),
                          "+f"(acc[mi][ni][2]), "+f"(acc[mi][ni][3])
                        : "r"(af[mi][0]), "r"(af[mi][1]),
                          "r"(af[mi][2]), "r"(af[mi][3]),
                          "r"(bf[ni][0]), "r"(bf[ni][1]));
        }
        if (kt + 1 < NT) STS(buf ^ 1);
        __syncthreads();
    }

    // Epilogue: c0/c1 at (row, 2*tig), c2/c3 at (row+8, 2*tig)
#pragma unroll
    for (int mi = 0; mi < 2; mi++) {
        const int r0 = bm + wm + mi * 16 + gID;
#pragma unroll
        for (int ni = 0; ni < 8; ni++) {
            const int c = bn + wn + ni * 8 + tig * 2;
            *(float2*)&C[(size_t)r0 * N + c] =
                make_float2(acc[mi][ni][0], acc[mi][ni][1]);
            *(float2*)&C[(size_t)(r0 + 8) * N + c] =
                make_float2(acc[mi][ni][2], acc[mi][ni][3]);
        }
    }
}

// ---------------------------------------------------------------------------
// RoPE in place on X laid out [B*T, heads*128].
// ---------------------------------------------------------------------------
__global__ void rope_kernel(float* __restrict__ X, int heads)
{
    int bt = blockIdx.x;
    int t  = bt & (TT - 1);
    int hh = blockIdx.y;
    float* v = X + ((size_t)bt * heads + hh) * HD;
    int d = threadIdx.x;
    int i = d & 63;
    float ang = (float)t * powf(10000.0f, -(float)i / 64.0f);
    float c = cosf(ang), s = sinf(ang);
    float x1 = v[d];
    float x2 = v[d ^ 64];
    __syncthreads();
    float rot = (d < 64) ? -x2 : x2;
    v[d] = x1 * c + rot * s;
}

// ---------------------------------------------------------------------------
// Flash attention, causal, GQA (16 q-heads over 4 kv-heads). fp32 SIMT.
// ---------------------------------------------------------------------------
#define BQ 64
#define BS 64
#define ATTN_SMEM ((128*64 + 128*64 + 64*128 + 64*65 + 64) * 4)

__global__ __launch_bounds__(256) void attn_kernel(
    const float* __restrict__ Q, const float* __restrict__ K,
    const float* __restrict__ V, float* __restrict__ Y)
{
    extern __shared__ float sma[];
    float* Qs = sma;                // [128][64]  d-major
    float* Ks = Qs + 128 * 64;      // [128][64]  d-major
    float* Vs = Ks + 128 * 64;      // [64][128]  s-major
    float* Ss = Vs + 64 * 128;      // [64][65]
    float* cw = Ss + 64 * 65;       // [64]
    __shared__ float mrow[64], lrow[64];

    const int tid = threadIdx.x;
    const int qt = gridDim.x - 1 - blockIdx.x;
    const int hh = blockIdx.y;
    const int b  = blockIdx.z;
    const int gkv = hh >> 2;
    const int q0 = qt * BQ;

    for (int idx = tid; idx < BQ * 32; idx += 256) {
        int q = idx >> 5;
        int d4 = (idx & 31) * 4;
        float4 t4 = *(const float4*)&Q[((size_t)(b * TT + q0 + q) * NH + hh) * HD + d4];
        Qs[(d4 + 0) * 64 + q] = t4.x;
        Qs[(d4 + 1) * 64 + q] = t4.y;
        Qs[(d4 + 2) * 64 + q] = t4.z;
        Qs[(d4 + 3) * 64 + q] = t4.w;
    }
    if (tid < 64) { mrow[tid] = -1e30f; lrow[tid] = 0.f; }

    float acc[32];
#pragma unroll
    for (int i = 0; i < 32; i++) acc[i] = 0.f;

    const int r  = tid >> 2;
    const int cb = (tid & 3) * 32;
    const int sr = (tid >> 4) * 4;
    const int sc = (tid & 15) * 4;
    const float scale = 0.08838834764831845f;

    __syncthreads();

    const int ntiles = qt + 1;
    for (int st = 0; st < ntiles; st++) {
        const int s0 = st * BS;
        for (int idx = tid; idx < BS * 32; idx += 256) {
            int s = idx >> 5;
            int d4 = (idx & 31) * 4;
            float4 kv = *(const float4*)&K[((size_t)(b * TT + s0 + s) * NKV + gkv) * HD + d4];
            Ks[(d4 + 0) * 64 + s] = kv.x;
            Ks[(d4 + 1) * 64 + s] = kv.y;
            Ks[(d4 + 2) * 64 + s] = kv.z;
            Ks[(d4 + 3) * 64 + s] = kv.w;
            float4 vv = *(const float4*)&V[((size_t)(b * TT + s0 + s) * NKV + gkv) * HD + d4];
            *(float4*)&Vs[s * 128 + d4] = vv;
        }
        __syncthreads();

        float sv[4][4];
#pragma unroll
        for (int i = 0; i < 4; i++)
#pragma unroll
            for (int j = 0; j < 4; j++) sv[i][j] = 0.f;
#pragma unroll 8
        for (int d = 0; d < 128; d++) {
            float4 a  = *(const float4*)&Qs[d * 64 + sr];
            float4 bb = *(const float4*)&Ks[d * 64 + sc];
            float av[4] = {a.x, a.y, a.z, a.w};
            float bv[4] = {bb.x, bb.y, bb.z, bb.w};
#pragma unroll
            for (int i = 0; i < 4; i++)
#pragma unroll
                for (int j = 0; j < 4; j++)
                    sv[i][j] = fmaf(av[i], bv[j], sv[i][j]);
        }
#pragma unroll
        for (int i = 0; i < 4; i++) {
            int qq = q0 + sr + i;
#pragma unroll
            for (int j = 0; j < 4; j++) {
                int ss = s0 + sc + j;
                Ss[(sr + i) * 65 + sc + j] = (ss <= qq) ? sv[i][j] * scale : -1e30f;
            }
        }
        __syncthreads();

        if (tid < 64) {
            float m_old = mrow[tid];
            float mx = m_old;
            const float* srow = &Ss[tid * 65];
#pragma unroll 8
            for (int j = 0; j < 64; j++) mx = fmaxf(mx, srow[j]);
            float sum = 0.f;
            float* prow = &Ss[tid * 65];
#pragma unroll 8
            for (int j = 0; j < 64; j++) {
                float p = __expf(prow[j] - mx);
                prow[j] = p;
                sum += p;
            }
            float corr = __expf(m_old - mx);
            lrow[tid] = lrow[tid] * corr + sum;
            mrow[tid] = mx;
            cw[tid] = corr;
        }
        __syncthreads();

        float corr = cw[r];
#pragma unroll
        for (int i = 0; i < 32; i++) acc[i] *= corr;
        const float* prow = &Ss[r * 65];
#pragma unroll 4
        for (int s = 0; s < 64; s++) {
            float p = prow[s];
            const float* vrow = &Vs[s * 128 + cb];
#pragma unroll
            for (int i = 0; i < 32; i += 4) {
                float4 v4 = *(const float4*)&vrow[i];
                acc[i + 0] = fmaf(p, v4.x, acc[i + 0]);
                acc[i + 1] = fmaf(p, v4.y, acc[i + 1]);
                acc[i + 2] = fmaf(p, v4.z, acc[i + 2]);
                acc[i + 3] = fmaf(p, v4.w, acc[i + 3]);
            }
        }
        __syncthreads();
    }

    float linv = 1.f / lrow[r];
    float* yp = &Y[(size_t)(b * TT + q0 + r) * DD + hh * HD + cb];
#pragma unroll
    for (int i = 0; i < 32; i += 4) {
        float4 o = make_float4(acc[i] * linv, acc[i + 1] * linv,
                               acc[i + 2] * linv, acc[i + 3] * linv);
        *(float4*)&yp[i] = o;
    }
}

// ---------------------------------------------------------------------------
extern "C" void kernel_launch(void* const* d_in, const int* in_sizes, int n_in,
                              void* d_out, int out_size)
{
    const float* x  = (const float*)d_in[0];
    const float* Wq = (const float*)d_in[1];
    const float* Wk = (const float*)d_in[2];
    const float* Wv = (const float*)d_in[3];
    const float* Wo = (const float*)d_in[4];
    float* out = (float*)d_out;

    float *Qp, *Kp, *Vp, *Yp;
    cudaGetSymbolAddress((void**)&Qp, g_Q);
    cudaGetSymbolAddress((void**)&Kp, g_K);
    cudaGetSymbolAddress((void**)&Vp, g_V);
    cudaGetSymbolAddress((void**)&Yp, g_Y);

    static bool attr_set = false;
    if (!attr_set) {
        cudaFuncSetAttribute(attn_kernel,
                             cudaFuncAttributeMaxDynamicSharedMemorySize,
                             ATTN_SMEM);
        cudaFuncSetAttribute(gemm_tf32,
                             cudaFuncAttributeMaxDynamicSharedMemorySize,
                             GEMM_SMEM);
        attr_set = true;
    }

    // Projections (tensor cores, tf32)
    gemm_tf32<<<dim3(DD / 128, MROWS / 128), 256, GEMM_SMEM>>>(x, Wq, Qp, MROWS, DD, DD);
    gemm_tf32<<<dim3((NKV * HD) / 128, MROWS / 128), 256, GEMM_SMEM>>>(x, Wk, Kp, MROWS, NKV * HD, DD);
    gemm_tf32<<<dim3((NKV * HD) / 128, MROWS / 128), 256, GEMM_SMEM>>>(x, Wv, Vp, MROWS, NKV * HD, DD);

    // RoPE on Q and K
    rope_kernel<<<dim3(MROWS, NH), 128>>>(Qp, NH);
    rope_kernel<<<dim3(MROWS, NKV), 128>>>(Kp, NKV);

    // Attention (fp32 SIMT flash)
    attn_kernel<<<dim3(TT / BQ, NH, BB), 256, ATTN_SMEM>>>(Qp, Kp, Vp, Yp);

    // Output projection
    gemm_tf32<<<dim3(DD / 128, MROWS / 128), 256, GEMM_SMEM>>>(Yp, Wo, out, MROWS, DD, DD);
}

// round 3
// speedup vs baseline: 5.5233x; 3.8991x over previous
#include <cuda_runtime.h>
#include <math.h>
#include <stdint.h>

#define BB 4
#define TT 1024
#define DD 2048
#define NH 16
#define NKV 4
#define HD 128
#define MROWS (BB*TT)   // 4096

// Scratch (device globals; no runtime allocation)
__device__ float g_Q[MROWS * DD];          // [B*T, 16*128]
__device__ float g_K[MROWS * NKV * HD];    // [B*T, 4*128]
__device__ float g_V[MROWS * NKV * HD];
__device__ float g_Y[MROWS * DD];          // attention output
__device__ float g_cos[TT * 64];
__device__ float g_sin[TT * 64];

__device__ __forceinline__ uint32_t f2tf32(float f) {
    uint32_t r;
    asm("cvt.rna.tf32.f32 %0, %1;" : "=r"(r) : "f"(f));
    return r;
}

#define MMA_TF32(ACC, A0, A1, A2, A3, B0, B1)                                  \
    asm volatile(                                                              \
        "mma.sync.aligned.m16n8k8.row.col.f32.tf32.tf32.f32 "                  \
        "{%0,%1,%2,%3}, {%4,%5,%6,%7}, {%8,%9}, {%0,%1,%2,%3};"                \
        : "+f"((ACC)[0]), "+f"((ACC)[1]), "+f"((ACC)[2]), "+f"((ACC)[3])       \
        : "r"(A0), "r"(A1), "r"(A2), "r"(A3), "r"(B0), "r"(B1))

// ---------------------------------------------------------------------------
// TF32 tensor-core GEMM (unchanged from round 2)
// ---------------------------------------------------------------------------
#define KT 32
#define ASTR 36
#define BSTR 136
#define ABUF (128*ASTR)
#define BBUF (KT*BSTR)
#define GEMM_SMEM ((ABUF + BBUF) * 2 * 4)

__global__ __launch_bounds__(256, 1) void gemm_tf32(
    const float* __restrict__ A, const float* __restrict__ B,
    float* __restrict__ C, int M, int N, int K)
{
    extern __shared__ uint32_t smg[];
    uint32_t* As = smg;
    uint32_t* Bs = smg + 2 * ABUF;

    const int tid  = threadIdx.x;
    const int bm   = blockIdx.y * 128;
    const int bn   = blockIdx.x * 128;
    const int warp = tid >> 5, lane = tid & 31;
    const int wm   = (warp & 3) * 32;
    const int wn   = (warp >> 2) * 64;
    const int gID  = lane >> 2, tig = lane & 3;

    const int arow = tid >> 3,  acol = (tid & 7) << 2;
    const int brow = tid >> 5,  bcol = (tid & 31) << 2;
    const float* Ag = A + (size_t)(bm + arow) * K + acol;
    const float* Bg = B + (size_t)brow * N + bn + bcol;

    float ra[4][4], rb[4][4];
    float acc[2][8][4];
#pragma unroll
    for (int i = 0; i < 2; i++)
#pragma unroll
        for (int j = 0; j < 8; j++)
#pragma unroll
            for (int l = 0; l < 4; l++) acc[i][j][l] = 0.f;

    const int NT = K / KT;

    auto LDG = [&](int kt) {
        const float* a = Ag + kt * KT;
#pragma unroll
        for (int i = 0; i < 4; i++)
            *(float4*)ra[i] = *(const float4*)(a + (size_t)(32 * i) * K);
        const float* b = Bg + (size_t)kt * KT * N;
#pragma unroll
        for (int i = 0; i < 4; i++)
            *(float4*)rb[i] = *(const float4*)(b + (size_t)(8 * i) * N);
    };
    auto STS = [&](int buf) {
        uint32_t* as = As + buf * ABUF;
#pragma unroll
        for (int i = 0; i < 4; i++)
#pragma unroll
            for (int j = 0; j < 4; j++)
                as[(arow + 32 * i) * ASTR + acol + j] = f2tf32(ra[i][j]);
        uint32_t* bs = Bs + buf * BBUF;
#pragma unroll
        for (int i = 0; i < 4; i++)
#pragma unroll
            for (int j = 0; j < 4; j++)
                bs[(brow + 8 * i) * BSTR + bcol + j] = f2tf32(rb[i][j]);
    };

    LDG(0); STS(0); __syncthreads();

    for (int kt = 0; kt < NT; kt++) {
        const int buf = kt & 1;
        if (kt + 1 < NT) LDG(kt + 1);

        const uint32_t* as = As + buf * ABUF + (wm + gID) * ASTR;
        const uint32_t* bs = Bs + buf * BBUF + wn + gID;
#pragma unroll
        for (int kk = 0; kk < 4; kk++) {
            const int k0 = kk * 8;
            uint32_t af[2][4], bf[8][2];
#pragma unroll
            for (int mi = 0; mi < 2; mi++) {
                const uint32_t* ap = as + mi * 16 * ASTR + k0 + tig;
                af[mi][0] = ap[0];
                af[mi][1] = ap[8 * ASTR];
                af[mi][2] = ap[4];
                af[mi][3] = ap[8 * ASTR + 4];
            }
#pragma unroll
            for (int ni = 0; ni < 8; ni++) {
                const uint32_t* bp = bs + (k0 + tig) * BSTR + ni * 8;
                bf[ni][0] = bp[0];
                bf[ni][1] = bp[4 * BSTR];
            }
#pragma unroll
            for (int mi = 0; mi < 2; mi++)
#pragma unroll
                for (int ni = 0; ni < 8; ni++)
                    MMA_TF32(acc[mi][ni], af[mi][0], af[mi][1], af[mi][2],
                             af[mi][3], bf[ni][0], bf[ni][1]);
        }
        if (kt + 1 < NT) STS(buf ^ 1);
        __syncthreads();
    }

#pragma unroll
    for (int mi = 0; mi < 2; mi++) {
        const int r0 = bm + wm + mi * 16 + gID;
#pragma unroll
        for (int ni = 0; ni < 8; ni++) {
            const int c = bn + wn + ni * 8 + tig * 2;
            *(float2*)&C[(size_t)r0 * N + c] =
                make_float2(acc[mi][ni][0], acc[mi][ni][1]);
            *(float2*)&C[(size_t)(r0 + 8) * N + c] =
                make_float2(acc[mi][ni][2], acc[mi][ni][3]);
        }
    }
}

// ---------------------------------------------------------------------------
// RoPE table: g_cos/g_sin[t][i], i in [0,64)
// ---------------------------------------------------------------------------
__global__ void rope_table_kernel()
{
    int t = blockIdx.x;
    int i = threadIdx.x;
    float inv = powf(10000.0f, -(float)i / 64.0f);
    float ang = (float)t * inv;
    g_cos[t * 64 + i] = cosf(ang);
    g_sin[t * 64 + i] = sinf(ang);
}

// ---------------------------------------------------------------------------
// Tensor-core flash attention, causal, GQA. RoPE fused at load via tables.
// BQ=128 q rows / CTA, BS=64 kv per iter, 256 threads = 8 warps x 16 rows.
// ---------------------------------------------------------------------------
#define AQ_STR 132
#define AK_STR 132
#define AV_STR 136
#define AP_STR 68
#define ATTN_SMEM ((128*AQ_STR + 64*AK_STR + 64*AV_STR + 128*AP_STR) * 4)

__global__ __launch_bounds__(256, 1) void attn_tc(
    const float* __restrict__ Q, const float* __restrict__ K,
    const float* __restrict__ V, float* __restrict__ Y)
{
    extern __shared__ uint32_t sma[];
    uint32_t* Qs = sma;                       // [128][AQ_STR] q-major tf32
    uint32_t* Ks = Qs + 128 * AQ_STR;         // [64][AK_STR]  s-major tf32
    uint32_t* Vs = Ks + 64 * AK_STR;          // [64][AV_STR]  s-major tf32
    uint32_t* Ps = Vs + 64 * AV_STR;          // [128][AP_STR] q-major tf32

    const int tid  = threadIdx.x;
    const int warp = tid >> 5, lane = tid & 31;
    const int gID  = lane >> 2, tig = lane & 3;
    const int qt   = (gridDim.x - 1) - blockIdx.x;   // heavy first
    const int hh   = blockIdx.y;
    const int b    = blockIdx.z;
    const int gkv  = hh >> 2;
    const int q0   = qt * 128;
    const int wm   = warp * 16;
    const int row0 = q0 + wm + gID;                  // global q row (lo)

    // ---- load Q tile with fused RoPE ----
    for (int idx = tid; idx < 128 * 32; idx += 256) {
        int q  = idx >> 5;
        int d4 = (idx & 31) << 2;
        int t  = q0 + q;
        const float* qp = Q + (size_t)(b * TT + t) * DD + hh * HD;
        float4 x1 = *(const float4*)(qp + d4);
        float4 x2 = *(const float4*)(qp + (d4 ^ 64));
        float4 c4 = *(const float4*)(g_cos + t * 64 + (d4 & 63));
        float4 s4 = *(const float4*)(g_sin + t * 64 + (d4 & 63));
        float sg = (d4 < 64) ? -1.f : 1.f;
        uint4 o;
        o.x = f2tf32(fmaf(x1.x, c4.x, sg * x2.x * s4.x));
        o.y = f2tf32(fmaf(x1.y, c4.y, sg * x2.y * s4.y));
        o.z = f2tf32(fmaf(x1.z, c4.z, sg * x2.z * s4.z));
        o.w = f2tf32(fmaf(x1.w, c4.w, sg * x2.w * s4.w));
        *(uint4*)&Qs[q * AQ_STR + d4] = o;
    }

    float m0 = -1e30f, m1 = -1e30f, l0 = 0.f, l1 = 0.f;
    float oacc[16][4];
#pragma unroll
    for (int i = 0; i < 16; i++)
#pragma unroll
        for (int j = 0; j < 4; j++) oacc[i][j] = 0.f;

    const float scale = 0.08838834764831845f;  // 1/sqrt(128)
    const int ntiles = 2 * qt + 2;

    for (int st = 0; st < ntiles; st++) {
        const int s0 = st * 64;

        // ---- load K (fused RoPE) and V tiles, tf32 ----
#pragma unroll
        for (int p = 0; p < 8; p++) {
            int idx = tid + p * 256;
            int s  = idx >> 5;
            int d4 = (idx & 31) << 2;
            int t  = s0 + s;
            const float* kp = K + (size_t)(b * TT + t) * (NKV * HD) + gkv * HD;
            const float* vp = V + (size_t)(b * TT + t) * (NKV * HD) + gkv * HD;
            float4 x1 = *(const float4*)(kp + d4);
            float4 x2 = *(const float4*)(kp + (d4 ^ 64));
            float4 vv = *(const float4*)(vp + d4);
            float4 c4 = *(const float4*)(g_cos + t * 64 + (d4 & 63));
            float4 s4 = *(const float4*)(g_sin + t * 64 + (d4 & 63));
            float sg = (d4 < 64) ? -1.f : 1.f;
            uint4 ko, vo;
            ko.x = f2tf32(fmaf(x1.x, c4.x, sg * x2.x * s4.x));
            ko.y = f2tf32(fmaf(x1.y, c4.y, sg * x2.y * s4.y));
            ko.z = f2tf32(fmaf(x1.z, c4.z, sg * x2.z * s4.z));
            ko.w = f2tf32(fmaf(x1.w, c4.w, sg * x2.w * s4.w));
            vo.x = f2tf32(vv.x); vo.y = f2tf32(vv.y);
            vo.z = f2tf32(vv.z); vo.w = f2tf32(vv.w);
            *(uint4*)&Ks[s * AK_STR + d4] = ko;
            *(uint4*)&Vs[s * AV_STR + d4] = vo;
        }
        __syncthreads();   // tiles ready (also orders Qs on first iter)

        // warps whose rows are entirely masked skip compute
        bool anyvalid = (row0 + 8 >= s0) || (row0 >= s0);  // max row = row0+8
        if (q0 + wm + 15 >= s0) {
            // ---- S = Q @ K^T : per-warp 16x64 ----
            float sacc[8][4];
#pragma unroll
            for (int i = 0; i < 8; i++)
#pragma unroll
                for (int j = 0; j < 4; j++) sacc[i][j] = 0.f;

            const uint32_t* qrow = Qs + (wm + gID) * AQ_STR;
#pragma unroll
            for (int kk = 0; kk < 16; kk++) {
                const int k0 = kk * 8;
                uint32_t a0 = qrow[k0 + tig];
                uint32_t a1 = qrow[8 * AQ_STR + k0 + tig];
                uint32_t a2 = qrow[k0 + tig + 4];
                uint32_t a3 = qrow[8 * AQ_STR + k0 + tig + 4];
#pragma unroll
                for (int ni = 0; ni < 8; ni++) {
                    const uint32_t* kp2 = Ks + (gID + ni * 8) * AK_STR + k0 + tig;
                    uint32_t b0 = kp2[0];
                    uint32_t b1 = kp2[4];
                    MMA_TF32(sacc[ni], a0, a1, a2, a3, b0, b1);
                }
            }

            // ---- softmax (registers + shfl over tig group) ----
            const int lim0 = row0 - s0;
            const int lim1 = lim0 + 8;
            const bool diag = (st >= 2 * qt);
            float mx0 = -1e30f, mx1 = -1e30f;
#pragma unroll
            for (int ni = 0; ni < 8; ni++) {
#pragma unroll
                for (int c = 0; c < 2; c++) {
                    int j = ni * 8 + tig * 2 + c;
                    float v0 = sacc[ni][c] * scale;
                    float v1 = sacc[ni][2 + c] * scale;
                    if (diag) {
                        if (j > lim0) v0 = -1e30f;
                        if (j > lim1) v1 = -1e30f;
                    }
                    sacc[ni][c]     = v0;
                    sacc[ni][2 + c] = v1;
                    mx0 = fmaxf(mx0, v0);
                    mx1 = fmaxf(mx1, v1);
                }
            }
            mx0 = fmaxf(mx0, __shfl_xor_sync(0xffffffffu, mx0, 1));
            mx0 = fmaxf(mx0, __shfl_xor_sync(0xffffffffu, mx0, 2));
            mx1 = fmaxf(mx1, __shfl_xor_sync(0xffffffffu, mx1, 1));
            mx1 = fmaxf(mx1, __shfl_xor_sync(0xffffffffu, mx1, 2));
            float mn0 = fmaxf(m0, mx0), mn1 = fmaxf(m1, mx1);
            float cr0 = __expf(m0 - mn0), cr1 = __expf(m1 - mn1);
            float sum0 = 0.f, sum1 = 0.f;
#pragma unroll
            for (int ni = 0; ni < 8; ni++) {
#pragma unroll
                for (int c = 0; c < 2; c++) {
                    float p0 = __expf(sacc[ni][c] - mn0);
                    float p1 = __expf(sacc[ni][2 + c] - mn1);
                    sacc[ni][c]     = p0;
                    sacc[ni][2 + c] = p1;
                    sum0 += p0;
                    sum1 += p1;
                }
            }
            sum0 += __shfl_xor_sync(0xffffffffu, sum0, 1);
            sum0 += __shfl_xor_sync(0xffffffffu, sum0, 2);
            sum1 += __shfl_xor_sync(0xffffffffu, sum1, 1);
            sum1 += __shfl_xor_sync(0xffffffffu, sum1, 2);
            l0 = l0 * cr0 + sum0;
            l1 = l1 * cr1 + sum1;
            m0 = mn0; m1 = mn1;

            // rescale O accumulators
#pragma unroll
            for (int ni = 0; ni < 16; ni++) {
                oacc[ni][0] *= cr0; oacc[ni][1] *= cr0;
                oacc[ni][2] *= cr1; oacc[ni][3] *= cr1;
            }

            // ---- write P (tf32) ----
            uint32_t* pr0 = Ps + (wm + gID) * AP_STR;
            uint32_t* pr1 = pr0 + 8 * AP_STR;
#pragma unroll
            for (int ni = 0; ni < 8; ni++) {
                int c = ni * 8 + tig * 2;
                pr0[c]     = f2tf32(sacc[ni][0]);
                pr0[c + 1] = f2tf32(sacc[ni][1]);
                pr1[c]     = f2tf32(sacc[ni][2]);
                pr1[c + 1] = f2tf32(sacc[ni][3]);
            }
            __syncwarp();

            // ---- O += P @ V ----
            const uint32_t* prow = Ps + (wm + gID) * AP_STR;
#pragma unroll
            for (int kk = 0; kk < 8; kk++) {
                const int k0 = kk * 8;
                uint32_t a0 = prow[k0 + tig];
                uint32_t a1 = prow[8 * AP_STR + k0 + tig];
                uint32_t a2 = prow[k0 + tig + 4];
                uint32_t a3 = prow[8 * AP_STR + k0 + tig + 4];
#pragma unroll
                for (int ni = 0; ni < 16; ni++) {
                    const uint32_t* vp2 = Vs + (k0 + tig) * AV_STR + gID + ni * 8;
                    uint32_t b0 = vp2[0];
                    uint32_t b1 = vp2[4 * AV_STR];
                    MMA_TF32(oacc[ni], a0, a1, a2, a3, b0, b1);
                }
            }
        }
        (void)anyvalid;
        __syncthreads();   // all readers done before next tile overwrite
    }

    // ---- epilogue ----
    float li0 = 1.f / l0, li1 = 1.f / l1;
    float* y0 = Y + (size_t)(b * TT + row0) * DD + hh * HD;
    float* y1 = y0 + (size_t)8 * DD;
#pragma unroll
    for (int ni = 0; ni < 16; ni++) {
        int c = ni * 8 + tig * 2;
        *(float2*)(y0 + c) = make_float2(oacc[ni][0] * li0, oacc[ni][1] * li0);
        *(float2*)(y1 + c) = make_float2(oacc[ni][2] * li1, oacc[ni][3] * li1);
    }
}

// ---------------------------------------------------------------------------
extern "C" void kernel_launch(void* const* d_in, const int* in_sizes, int n_in,
                              void* d_out, int out_size)
{
    const float* x  = (const float*)d_in[0];
    const float* Wq = (const float*)d_in[1];
    const float* Wk = (const float*)d_in[2];
    const float* Wv = (const float*)d_in[3];
    const float* Wo = (const float*)d_in[4];
    float* out = (float*)d_out;

    float *Qp, *Kp, *Vp, *Yp;
    cudaGetSymbolAddress((void**)&Qp, g_Q);
    cudaGetSymbolAddress((void**)&Kp, g_K);
    cudaGetSymbolAddress((void**)&Vp, g_V);
    cudaGetSymbolAddress((void**)&Yp, g_Y);

    static bool attr_set = false;
    if (!attr_set) {
        cudaFuncSetAttribute(gemm_tf32,
                             cudaFuncAttributeMaxDynamicSharedMemorySize,
                             GEMM_SMEM);
        cudaFuncSetAttribute(attn_tc,
                             cudaFuncAttributeMaxDynamicSharedMemorySize,
                             ATTN_SMEM);
        attr_set = true;
    }

    rope_table_kernel<<<TT, 64>>>();

    gemm_tf32<<<dim3(DD / 128, MROWS / 128), 256, GEMM_SMEM>>>(x, Wq, Qp, MROWS, DD, DD);
    gemm_tf32<<<dim3((NKV * HD) / 128, MROWS / 128), 256, GEMM_SMEM>>>(x, Wk, Kp, MROWS, NKV * HD, DD);
    gemm_tf32<<<dim3((NKV * HD) / 128, MROWS / 128), 256, GEMM_SMEM>>>(x, Wv, Vp, MROWS, NKV * HD, DD);

    attn_tc<<<dim3(TT / 128, NH, BB), 256, ATTN_SMEM>>>(Qp, Kp, Vp, Yp);

    gemm_tf32<<<dim3(DD / 128, MROWS / 128), 256, GEMM_SMEM>>>(Yp, Wo, out, MROWS, DD, DD);
}

// round 4
// speedup vs baseline: 5.8246x; 1.0545x over previous
#include <cuda_runtime.h>
#include <math.h>
#include <stdint.h>

#define BB 4
#define TT 1024
#define DD 2048
#define NH 16
#define NKV 4
#define HD 128
#define MROWS (BB*TT)    // 4096
#define NQKV 3072        // packed Q|K|V output cols

// Scratch (device globals; no runtime allocation)
__device__ uint32_t g_xT[MROWS * DD];        // x in tf32 bits
__device__ uint32_t g_Wqkv[DD * NQKV];       // packed [Wq|Wk|Wv] tf32 bits
__device__ uint32_t g_WoT[DD * DD];          // Wo tf32 bits
__device__ float    g_QKV[MROWS * NQKV];     // projection output (fp32)
__device__ uint32_t g_Y[MROWS * DD];         // attention output (tf32 bits)
__device__ float    g_cos[TT * 64];
__device__ float    g_sin[TT * 64];

__device__ __forceinline__ uint32_t f2tf32(float f) {
    uint32_t r;
    asm("cvt.rna.tf32.f32 %0, %1;" : "=r"(r) : "f"(f));
    return r;
}

#define MMA_TF32(ACC, A0, A1, A2, A3, B0, B1)                                  \
    asm volatile(                                                              \
        "mma.sync.aligned.m16n8k8.row.col.f32.tf32.tf32.f32 "                  \
        "{%0,%1,%2,%3}, {%4,%5,%6,%7}, {%8,%9}, {%0,%1,%2,%3};"                \
        : "+f"((ACC)[0]), "+f"((ACC)[1]), "+f"((ACC)[2]), "+f"((ACC)[3])       \
        : "r"(A0), "r"(A1), "r"(A2), "r"(A3), "r"(B0), "r"(B1))

__device__ __forceinline__ void cp16(uint32_t dst, const void* src) {
    asm volatile("cp.async.cg.shared.global [%0], [%1], 16;" ::
                 "r"(dst), "l"(src));
}

// ---------------------------------------------------------------------------
// Pipelined TF32 GEMM on pre-converted tf32 operands.
// C[M,N] = A[M,K] @ B[K,N]. 128x128 CTA tile, KT=32, 4-stage cp.async.
// 256 threads = 8 warps (4M x 2N), warp tile 32x64.
// ---------------------------------------------------------------------------
#define ASTR 36
#define BSTR 136
#define AW (128*ASTR)            // 4608 words per A stage
#define STG (AW + 32*BSTR)       // 8960 words per stage
#define GEMM_SMEM (4*STG*4)      // 143360 bytes

__global__ __launch_bounds__(256, 1) void gemm_pre(
    const uint32_t* __restrict__ A, const uint32_t* __restrict__ B,
    float* __restrict__ C, int M, int N, int K)
{
    extern __shared__ uint32_t smg[];
    const uint32_t smaddr = (uint32_t)__cvta_generic_to_shared(smg);

    const int tid  = threadIdx.x;
    const int bm   = blockIdx.y * 128;
    const int bn   = blockIdx.x * 128;
    const int warp = tid >> 5, lane = tid & 31;
    const int wm   = (warp & 3) * 32;
    const int wn   = (warp >> 2) * 64;
    const int gID  = lane >> 2, tig = lane & 3;
    const int NT   = K >> 5;

    float acc[2][8][4];
#pragma unroll
    for (int i = 0; i < 2; i++)
#pragma unroll
        for (int j = 0; j < 8; j++)
#pragma unroll
            for (int l = 0; l < 4; l++) acc[i][j][l] = 0.f;

    auto LOAD = [&](int kt, int s) {
        uint32_t abase = smaddr + (uint32_t)(s * STG) * 4;
#pragma unroll
        for (int p = 0; p < 4; p++) {
            int id = tid + p * 256;
            int m = id >> 3, kc = (id & 7) << 2;
            cp16(abase + (uint32_t)(m * ASTR + kc) * 4,
                 A + (size_t)(bm + m) * K + kt * 32 + kc);
        }
        uint32_t bbase = abase + AW * 4;
#pragma unroll
        for (int p = 0; p < 4; p++) {
            int id = tid + p * 256;
            int k = id >> 5, nc = (id & 31) << 2;
            cp16(bbase + (uint32_t)(k * BSTR + nc) * 4,
                 B + (size_t)(kt * 32 + k) * N + bn + nc);
        }
        asm volatile("cp.async.commit_group;");
    };

    LOAD(0, 0); LOAD(1, 1); LOAD(2, 2);

    for (int kt = 0; kt < NT; kt++) {
        asm volatile("cp.async.wait_group 2;");
        __syncthreads();

        const int nk = kt + 3;
        if (nk < NT) LOAD(nk, nk & 3);
        else asm volatile("cp.async.commit_group;");

        const uint32_t* as = smg + (kt & 3) * STG + (wm + gID) * ASTR;
        const uint32_t* bs = smg + (kt & 3) * STG + AW + wn + gID;
#pragma unroll
        for (int kk = 0; kk < 4; kk++) {
            const int k0 = kk * 8;
            uint32_t af[2][4], bf[8][2];
#pragma unroll
            for (int mi = 0; mi < 2; mi++) {
                const uint32_t* ap = as + mi * 16 * ASTR + k0 + tig;
                af[mi][0] = ap[0];
                af[mi][1] = ap[8 * ASTR];
                af[mi][2] = ap[4];
                af[mi][3] = ap[8 * ASTR + 4];
            }
#pragma unroll
            for (int ni = 0; ni < 8; ni++) {
                const uint32_t* bp = bs + (k0 + tig) * BSTR + ni * 8;
                bf[ni][0] = bp[0];
                bf[ni][1] = bp[4 * BSTR];
            }
#pragma unroll
            for (int mi = 0; mi < 2; mi++)
#pragma unroll
                for (int ni = 0; ni < 8; ni++)
                    MMA_TF32(acc[mi][ni], af[mi][0], af[mi][1], af[mi][2],
                             af[mi][3], bf[ni][0], bf[ni][1]);
        }
    }

#pragma unroll
    for (int mi = 0; mi < 2; mi++) {
        const int r0 = bm + wm + mi * 16 + gID;
#pragma unroll
        for (int ni = 0; ni < 8; ni++) {
            const int c = bn + wn + ni * 8 + tig * 2;
            *(float2*)&C[(size_t)r0 * N + c] =
                make_float2(acc[mi][ni][0], acc[mi][ni][1]);
            *(float2*)&C[(size_t)(r0 + 8) * N + c] =
                make_float2(acc[mi][ni][2], acc[mi][ni][3]);
        }
    }
}

// ---------------------------------------------------------------------------
// Conversion / packing / rope-table kernels
// ---------------------------------------------------------------------------
__global__ void cvt_kernel(const float* __restrict__ in,
                           uint32_t* __restrict__ out)
{
    int i = (blockIdx.x * 256 + threadIdx.x) * 4;
    float4 v = *(const float4*)(in + i);
    uint4 o;
    o.x = f2tf32(v.x); o.y = f2tf32(v.y);
    o.z = f2tf32(v.z); o.w = f2tf32(v.w);
    *(uint4*)(out + i) = o;
}

__global__ void pack_w_kernel(const float* __restrict__ Wq,
                              const float* __restrict__ Wk,
                              const float* __restrict__ Wv,
                              uint32_t* __restrict__ W)
{
    int idx = (blockIdx.x * 256 + threadIdx.x) * 4;   // over 2048*3072
    int r = idx / NQKV, c = idx - r * NQKV;
    const float* src;
    if (c < 2048)      src = Wq + (size_t)r * 2048 + c;
    else if (c < 2560) src = Wk + (size_t)r * 512 + (c - 2048);
    else               src = Wv + (size_t)r * 512 + (c - 2560);
    float4 v = *(const float4*)src;
    uint4 o;
    o.x = f2tf32(v.x); o.y = f2tf32(v.y);
    o.z = f2tf32(v.z); o.w = f2tf32(v.w);
    *(uint4*)(W + idx) = o;
}

__global__ void rope_table_kernel()
{
    int t = blockIdx.x;
    int i = threadIdx.x;
    float inv = powf(10000.0f, -(float)i / 64.0f);
    float ang = (float)t * inv;
    g_cos[t * 64 + i] = cosf(ang);
    g_sin[t * 64 + i] = sinf(ang);
}

// ---------------------------------------------------------------------------
// Tensor-core flash attention, causal, GQA. RoPE fused at load via tables.
// Reads packed QKV [4096][3072]; writes Y as tf32 bits.
// ---------------------------------------------------------------------------
#define AQ_STR 132
#define AK_STR 132
#define AV_STR 136
#define AP_STR 68
#define ATTN_SMEM ((128*AQ_STR + 64*AK_STR + 64*AV_STR + 128*AP_STR) * 4)

__global__ __launch_bounds__(256, 1) void attn_tc(
    const float* __restrict__ QKV, uint32_t* __restrict__ Y)
{
    extern __shared__ uint32_t sma[];
    uint32_t* Qs = sma;
    uint32_t* Ks = Qs + 128 * AQ_STR;
    uint32_t* Vs = Ks + 64 * AK_STR;
    uint32_t* Ps = Vs + 64 * AV_STR;

    const int tid  = threadIdx.x;
    const int warp = tid >> 5, lane = tid & 31;
    const int gID  = lane >> 2, tig = lane & 3;
    const int qt   = (gridDim.x - 1) - blockIdx.x;
    const int hh   = blockIdx.y;
    const int b    = blockIdx.z;
    const int gkv  = hh >> 2;
    const int q0   = qt * 128;
    const int wm   = warp * 16;
    const int row0 = q0 + wm + gID;

    // ---- load Q tile with fused RoPE ----
    for (int idx = tid; idx < 128 * 32; idx += 256) {
        int q  = idx >> 5;
        int d4 = (idx & 31) << 2;
        int t  = q0 + q;
        const float* qp = QKV + (size_t)(b * TT + t) * NQKV + hh * HD;
        float4 x1 = *(const float4*)(qp + d4);
        float4 x2 = *(const float4*)(qp + (d4 ^ 64));
        float4 c4 = *(const float4*)(g_cos + t * 64 + (d4 & 63));
        float4 s4 = *(const float4*)(g_sin + t * 64 + (d4 & 63));
        float sg = (d4 < 64) ? -1.f : 1.f;
        uint4 o;
        o.x = f2tf32(fmaf(x1.x, c4.x, sg * x2.x * s4.x));
        o.y = f2tf32(fmaf(x1.y, c4.y, sg * x2.y * s4.y));
        o.z = f2tf32(fmaf(x1.z, c4.z, sg * x2.z * s4.z));
        o.w = f2tf32(fmaf(x1.w, c4.w, sg * x2.w * s4.w));
        *(uint4*)&Qs[q * AQ_STR + d4] = o;
    }

    float m0 = -1e30f, m1 = -1e30f, l0 = 0.f, l1 = 0.f;
    float oacc[16][4];
#pragma unroll
    for (int i = 0; i < 16; i++)
#pragma unroll
        for (int j = 0; j < 4; j++) oacc[i][j] = 0.f;

    const float scale = 0.08838834764831845f;
    const int ntiles = 2 * qt + 2;

    for (int st = 0; st < ntiles; st++) {
        const int s0 = st * 64;

#pragma unroll
        for (int p = 0; p < 8; p++) {
            int idx = tid + p * 256;
            int s  = idx >> 5;
            int d4 = (idx & 31) << 2;
            int t  = s0 + s;
            const float* kp = QKV + (size_t)(b * TT + t) * NQKV + 2048 + gkv * HD;
            const float* vp = QKV + (size_t)(b * TT + t) * NQKV + 2560 + gkv * HD;
            float4 x1 = *(const float4*)(kp + d4);
            float4 x2 = *(const float4*)(kp + (d4 ^ 64));
            float4 vv = *(const float4*)(vp + d4);
            float4 c4 = *(const float4*)(g_cos + t * 64 + (d4 & 63));
            float4 s4 = *(const float4*)(g_sin + t * 64 + (d4 & 63));
            float sg = (d4 < 64) ? -1.f : 1.f;
            uint4 ko, vo;
            ko.x = f2tf32(fmaf(x1.x, c4.x, sg * x2.x * s4.x));
            ko.y = f2tf32(fmaf(x1.y, c4.y, sg * x2.y * s4.y));
            ko.z = f2tf32(fmaf(x1.z, c4.z, sg * x2.z * s4.z));
            ko.w = f2tf32(fmaf(x1.w, c4.w, sg * x2.w * s4.w));
            vo.x = f2tf32(vv.x); vo.y = f2tf32(vv.y);
            vo.z = f2tf32(vv.z); vo.w = f2tf32(vv.w);
            *(uint4*)&Ks[s * AK_STR + d4] = ko;
            *(uint4*)&Vs[s * AV_STR + d4] = vo;
        }
        __syncthreads();

        if (q0 + wm + 15 >= s0) {
            float sacc[8][4];
#pragma unroll
            for (int i = 0; i < 8; i++)
#pragma unroll
                for (int j = 0; j < 4; j++) sacc[i][j] = 0.f;

            const uint32_t* qrow = Qs + (wm + gID) * AQ_STR;
#pragma unroll
            for (int kk = 0; kk < 16; kk++) {
                const int k0 = kk * 8;
                uint32_t a0 = qrow[k0 + tig];
                uint32_t a1 = qrow[8 * AQ_STR + k0 + tig];
                uint32_t a2 = qrow[k0 + tig + 4];
                uint32_t a3 = qrow[8 * AQ_STR + k0 + tig + 4];
#pragma unroll
                for (int ni = 0; ni < 8; ni++) {
                    const uint32_t* kp2 = Ks + (gID + ni * 8) * AK_STR + k0 + tig;
                    MMA_TF32(sacc[ni], a0, a1, a2, a3, kp2[0], kp2[4]);
                }
            }

            const int lim0 = row0 - s0;
            const int lim1 = lim0 + 8;
            const bool diag = (st >= 2 * qt);
            float mx0 = -1e30f, mx1 = -1e30f;
#pragma unroll
            for (int ni = 0; ni < 8; ni++) {
#pragma unroll
                for (int c = 0; c < 2; c++) {
                    int j = ni * 8 + tig * 2 + c;
                    float v0 = sacc[ni][c] * scale;
                    float v1 = sacc[ni][2 + c] * scale;
                    if (diag) {
                        if (j > lim0) v0 = -1e30f;
                        if (j > lim1) v1 = -1e30f;
                    }
                    sacc[ni][c]     = v0;
                    sacc[ni][2 + c] = v1;
                    mx0 = fmaxf(mx0, v0);
                    mx1 = fmaxf(mx1, v1);
                }
            }
            mx0 = fmaxf(mx0, __shfl_xor_sync(0xffffffffu, mx0, 1));
            mx0 = fmaxf(mx0, __shfl_xor_sync(0xffffffffu, mx0, 2));
            mx1 = fmaxf(mx1, __shfl_xor_sync(0xffffffffu, mx1, 1));
            mx1 = fmaxf(mx1, __shfl_xor_sync(0xffffffffu, mx1, 2));
            float mn0 = fmaxf(m0, mx0), mn1 = fmaxf(m1, mx1);
            float cr0 = __expf(m0 - mn0), cr1 = __expf(m1 - mn1);
            float sum0 = 0.f, sum1 = 0.f;
#pragma unroll
            for (int ni = 0; ni < 8; ni++) {
#pragma unroll
                for (int c = 0; c < 2; c++) {
                    float p0 = __expf(sacc[ni][c] - mn0);
                    float p1 = __expf(sacc[ni][2 + c] - mn1);
                    sacc[ni][c]     = p0;
                    sacc[ni][2 + c] = p1;
                    sum0 += p0;
                    sum1 += p1;
                }
            }
            sum0 += __shfl_xor_sync(0xffffffffu, sum0, 1);
            sum0 += __shfl_xor_sync(0xffffffffu, sum0, 2);
            sum1 += __shfl_xor_sync(0xffffffffu, sum1, 1);
            sum1 += __shfl_xor_sync(0xffffffffu, sum1, 2);
            l0 = l0 * cr0 + sum0;
            l1 = l1 * cr1 + sum1;
            m0 = mn0; m1 = mn1;

#pragma unroll
            for (int ni = 0; ni < 16; ni++) {
                oacc[ni][0] *= cr0; oacc[ni][1] *= cr0;
                oacc[ni][2] *= cr1; oacc[ni][3] *= cr1;
            }

            uint32_t* pr0 = Ps + (wm + gID) * AP_STR;
            uint32_t* pr1 = pr0 + 8 * AP_STR;
#pragma unroll
            for (int ni = 0; ni < 8; ni++) {
                int c = ni * 8 + tig * 2;
                pr0[c]     = f2tf32(sacc[ni][0]);
                pr0[c + 1] = f2tf32(sacc[ni][1]);
                pr1[c]     = f2tf32(sacc[ni][2]);
                pr1[c + 1] = f2tf32(sacc[ni][3]);
            }
            __syncwarp();

            const uint32_t* prow = Ps + (wm + gID) * AP_STR;
#pragma unroll
            for (int kk = 0; kk < 8; kk++) {
                const int k0 = kk * 8;
                uint32_t a0 = prow[k0 + tig];
                uint32_t a1 = prow[8 * AP_STR + k0 + tig];
                uint32_t a2 = prow[k0 + tig + 4];
                uint32_t a3 = prow[8 * AP_STR + k0 + tig + 4];
#pragma unroll
                for (int ni = 0; ni < 16; ni++) {
                    const uint32_t* vp2 = Vs + (k0 + tig) * AV_STR + gID + ni * 8;
                    MMA_TF32(oacc[ni], a0, a1, a2, a3, vp2[0], vp2[4 * AV_STR]);
                }
            }
        }
        __syncthreads();
    }

    float li0 = 1.f / l0, li1 = 1.f / l1;
    uint32_t* y0 = Y + (size_t)(b * TT + row0) * DD + hh * HD;
    uint32_t* y1 = y0 + (size_t)8 * DD;
#pragma unroll
    for (int ni = 0; ni < 16; ni++) {
        int c = ni * 8 + tig * 2;
        uint2 o0, o1;
        o0.x = f2tf32(oacc[ni][0] * li0); o0.y = f2tf32(oacc[ni][1] * li0);
        o1.x = f2tf32(oacc[ni][2] * li1); o1.y = f2tf32(oacc[ni][3] * li1);
        *(uint2*)(y0 + c) = o0;
        *(uint2*)(y1 + c) = o1;
    }
}

// ---------------------------------------------------------------------------
extern "C" void kernel_launch(void* const* d_in, const int* in_sizes, int n_in,
                              void* d_out, int out_size)
{
    const float* x  = (const float*)d_in[0];
    const float* Wq = (const float*)d_in[1];
    const float* Wk = (const float*)d_in[2];
    const float* Wv = (const float*)d_in[3];
    const float* Wo = (const float*)d_in[4];
    float* out = (float*)d_out;

    uint32_t *xT, *Wqkv, *WoT, *Yp;
    float *QKVp;
    cudaGetSymbolAddress((void**)&xT,   g_xT);
    cudaGetSymbolAddress((void**)&Wqkv, g_Wqkv);
    cudaGetSymbolAddress((void**)&WoT,  g_WoT);
    cudaGetSymbolAddress((void**)&QKVp, g_QKV);
    cudaGetSymbolAddress((void**)&Yp,   g_Y);

    static bool attr_set = false;
    if (!attr_set) {
        cudaFuncSetAttribute(gemm_pre,
                             cudaFuncAttributeMaxDynamicSharedMemorySize,
                             GEMM_SMEM);
        cudaFuncSetAttribute(attn_tc,
                             cudaFuncAttributeMaxDynamicSharedMemorySize,
                             ATTN_SMEM);
        attr_set = true;
    }

    rope_table_kernel<<<TT, 64>>>();
    cvt_kernel<<<(MROWS * DD) / 1024, 256>>>(x, xT);
    pack_w_kernel<<<(DD * NQKV) / 1024, 256>>>(Wq, Wk, Wv, Wqkv);
    cvt_kernel<<<(DD * DD) / 1024, 256>>>(Wo, WoT);

    // Fused Q|K|V projection: [4096,2048] @ [2048,3072]
    gemm_pre<<<dim3(NQKV / 128, MROWS / 128), 256, GEMM_SMEM>>>(
        xT, Wqkv, QKVp, MROWS, NQKV, DD);

    attn_tc<<<dim3(TT / 128, NH, BB), 256, ATTN_SMEM>>>(QKVp, Yp);

    // Output projection: [4096,2048] @ [2048,2048]
    gemm_pre<<<dim3(DD / 128, MROWS / 128), 256, GEMM_SMEM>>>(
        Yp, WoT, out, MROWS, DD, DD);
}

// round 5
// speedup vs baseline: 6.4523x; 1.1078x over previous
#include <cuda_runtime.h>
#include <math.h>
#include <stdint.h>

#define BB 4
#define TT 1024
#define DD 2048
#define NH 16
#define NKV 4
#define HD 128
#define MROWS (BB*TT)    // 4096
#define NQKV 3072        // packed Q|K|V output cols

// Scratch (device globals; no runtime allocation)
__device__ uint32_t g_xT[MROWS * DD];        // x in tf32 bits
__device__ uint32_t g_Wqkv[DD * NQKV];       // packed [Wq|Wk|Wv] tf32 bits
__device__ uint32_t g_WoT[DD * DD];          // Wo tf32 bits
__device__ float    g_QKV[MROWS * NQKV];     // projection output (fp32)
__device__ uint32_t g_Y[MROWS * DD];         // attention output (tf32 bits)
__device__ float    g_cos[TT * 64];
__device__ float    g_sin[TT * 64];

__device__ __forceinline__ uint32_t f2tf32(float f) {
    uint32_t r;
    asm("cvt.rna.tf32.f32 %0, %1;" : "=r"(r) : "f"(f));
    return r;
}

#define MMA_TF32(ACC, A0, A1, A2, A3, B0, B1)                                  \
    asm volatile(                                                              \
        "mma.sync.aligned.m16n8k8.row.col.f32.tf32.tf32.f32 "                  \
        "{%0,%1,%2,%3}, {%4,%5,%6,%7}, {%8,%9}, {%0,%1,%2,%3};"                \
        : "+f"((ACC)[0]), "+f"((ACC)[1]), "+f"((ACC)[2]), "+f"((ACC)[3])       \
        : "r"(A0), "r"(A1), "r"(A2), "r"(A3), "r"(B0), "r"(B1))

__device__ __forceinline__ void cp16(uint32_t dst, const void* src) {
    asm volatile("cp.async.cg.shared.global [%0], [%1], 16;" ::
                 "r"(dst), "l"(src));
}

// ---------------------------------------------------------------------------
// Pipelined TF32 GEMM on pre-converted tf32 operands.
// C[M,N] = A[M,K] @ B[K,N]. 256x128 CTA tile, KT=32, 4-stage cp.async.
// 256 threads = 8 warps (4M x 2N), warp tile 64x64 (32 LDS / 32 MMA per kk).
// ---------------------------------------------------------------------------
#define ASTR 36
#define BSTR 136
#define AW (256*ASTR)            // 9216 words per A stage
#define STG (AW + 32*BSTR)       // 13568 words per stage
#define GEMM_SMEM (4*STG*4)      // 217088 bytes

__global__ __launch_bounds__(256, 1) void gemm_pre(
    const uint32_t* __restrict__ A, const uint32_t* __restrict__ B,
    float* __restrict__ C, int M, int N, int K)
{
    extern __shared__ uint32_t smg[];
    const uint32_t smaddr = (uint32_t)__cvta_generic_to_shared(smg);

    const int tid  = threadIdx.x;
    const int bm   = blockIdx.y * 256;
    const int bn   = blockIdx.x * 128;
    const int warp = tid >> 5, lane = tid & 31;
    const int wm   = (warp & 3) * 64;
    const int wn   = (warp >> 2) * 64;
    const int gID  = lane >> 2, tig = lane & 3;
    const int NT   = K >> 5;

    float acc[4][8][4];
#pragma unroll
    for (int i = 0; i < 4; i++)
#pragma unroll
        for (int j = 0; j < 8; j++)
#pragma unroll
            for (int l = 0; l < 4; l++) acc[i][j][l] = 0.f;

    auto LOAD = [&](int kt, int s) {
        uint32_t abase = smaddr + (uint32_t)(s * STG) * 4;
#pragma unroll
        for (int p = 0; p < 8; p++) {
            int id = tid + p * 256;
            int m = id >> 3, kc = (id & 7) << 2;
            cp16(abase + (uint32_t)(m * ASTR + kc) * 4,
                 A + (size_t)(bm + m) * K + kt * 32 + kc);
        }
        uint32_t bbase = abase + AW * 4;
#pragma unroll
        for (int p = 0; p < 4; p++) {
            int id = tid + p * 256;
            int k = id >> 5, nc = (id & 31) << 2;
            cp16(bbase + (uint32_t)(k * BSTR + nc) * 4,
                 B + (size_t)(kt * 32 + k) * N + bn + nc);
        }
        asm volatile("cp.async.commit_group;");
    };

    LOAD(0, 0); LOAD(1, 1); LOAD(2, 2);

    for (int kt = 0; kt < NT; kt++) {
        asm volatile("cp.async.wait_group 2;");
        __syncthreads();

        const int nk = kt + 3;
        if (nk < NT) LOAD(nk, nk & 3);
        else asm volatile("cp.async.commit_group;");

        const uint32_t* as = smg + (kt & 3) * STG + (wm + gID) * ASTR;
        const uint32_t* bs = smg + (kt & 3) * STG + AW + wn + gID;
#pragma unroll
        for (int kk = 0; kk < 4; kk++) {
            const int k0 = kk * 8;
            uint32_t af[4][4], bf[8][2];
#pragma unroll
            for (int mi = 0; mi < 4; mi++) {
                const uint32_t* ap = as + mi * 16 * ASTR + k0 + tig;
                af[mi][0] = ap[0];
                af[mi][1] = ap[8 * ASTR];
                af[mi][2] = ap[4];
                af[mi][3] = ap[8 * ASTR + 4];
            }
#pragma unroll
            for (int ni = 0; ni < 8; ni++) {
                const uint32_t* bp = bs + (k0 + tig) * BSTR + ni * 8;
                bf[ni][0] = bp[0];
                bf[ni][1] = bp[4 * BSTR];
            }
#pragma unroll
            for (int mi = 0; mi < 4; mi++)
#pragma unroll
                for (int ni = 0; ni < 8; ni++)
                    MMA_TF32(acc[mi][ni], af[mi][0], af[mi][1], af[mi][2],
                             af[mi][3], bf[ni][0], bf[ni][1]);
        }
    }

#pragma unroll
    for (int mi = 0; mi < 4; mi++) {
        const int r0 = bm + wm + mi * 16 + gID;
#pragma unroll
        for (int ni = 0; ni < 8; ni++) {
            const int c = bn + wn + ni * 8 + tig * 2;
            *(float2*)&C[(size_t)r0 * N + c] =
                make_float2(acc[mi][ni][0], acc[mi][ni][1]);
            *(float2*)&C[(size_t)(r0 + 8) * N + c] =
                make_float2(acc[mi][ni][2], acc[mi][ni][3]);
        }
    }
}

// ---------------------------------------------------------------------------
// Conversion / packing / rope-table kernels
// ---------------------------------------------------------------------------
__global__ void cvt_kernel(const float* __restrict__ in,
                           uint32_t* __restrict__ out)
{
    int i = (blockIdx.x * 256 + threadIdx.x) * 4;
    float4 v = *(const float4*)(in + i);
    uint4 o;
    o.x = f2tf32(v.x); o.y = f2tf32(v.y);
    o.z = f2tf32(v.z); o.w = f2tf32(v.w);
    *(uint4*)(out + i) = o;
}

__global__ void pack_w_kernel(const float* __restrict__ Wq,
                              const float* __restrict__ Wk,
                              const float* __restrict__ Wv,
                              uint32_t* __restrict__ W)
{
    int idx = (blockIdx.x * 256 + threadIdx.x) * 4;   // over 2048*3072
    int r = idx / NQKV, c = idx - r * NQKV;
    const float* src;
    if (c < 2048)      src = Wq + (size_t)r * 2048 + c;
    else if (c < 2560) src = Wk + (size_t)r * 512 + (c - 2048);
    else               src = Wv + (size_t)r * 512 + (c - 2560);
    float4 v = *(const float4*)src;
    uint4 o;
    o.x = f2tf32(v.x); o.y = f2tf32(v.y);
    o.z = f2tf32(v.z); o.w = f2tf32(v.w);
    *(uint4*)(W + idx) = o;
}

__global__ void rope_table_kernel()
{
    int t = blockIdx.x;
    int i = threadIdx.x;
    float inv = powf(10000.0f, -(float)i / 64.0f);
    float ang = (float)t * inv;
    g_cos[t * 64 + i] = cosf(ang);
    g_sin[t * 64 + i] = sinf(ang);
}

// ---------------------------------------------------------------------------
// Tensor-core flash attention, causal, GQA. RoPE fused at load via tables.
// Reads packed QKV [4096][3072]; writes Y as tf32 bits.
// ---------------------------------------------------------------------------
#define AQ_STR 132
#define AK_STR 132
#define AV_STR 136
#define AP_STR 68
#define ATTN_SMEM ((128*AQ_STR + 64*AK_STR + 64*AV_STR + 128*AP_STR) * 4)

__global__ __launch_bounds__(256, 1) void attn_tc(
    const float* __restrict__ QKV, uint32_t* __restrict__ Y)
{
    extern __shared__ uint32_t sma[];
    uint32_t* Qs = sma;
    uint32_t* Ks = Qs + 128 * AQ_STR;
    uint32_t* Vs = Ks + 64 * AK_STR;
    uint32_t* Ps = Vs + 64 * AV_STR;

    const int tid  = threadIdx.x;
    const int warp = tid >> 5, lane = tid & 31;
    const int gID  = lane >> 2, tig = lane & 3;
    const int qt   = (gridDim.x - 1) - blockIdx.x;
    const int hh   = blockIdx.y;
    const int b    = blockIdx.z;
    const int gkv  = hh >> 2;
    const int q0   = qt * 128;
    const int wm   = warp * 16;
    const int row0 = q0 + wm + gID;

    // ---- load Q tile with fused RoPE ----
    for (int idx = tid; idx < 128 * 32; idx += 256) {
        int q  = idx >> 5;
        int d4 = (idx & 31) << 2;
        int t  = q0 + q;
        const float* qp = QKV + (size_t)(b * TT + t) * NQKV + hh * HD;
        float4 x1 = *(const float4*)(qp + d4);
        float4 x2 = *(const float4*)(qp + (d4 ^ 64));
        float4 c4 = *(const float4*)(g_cos + t * 64 + (d4 & 63));
        float4 s4 = *(const float4*)(g_sin + t * 64 + (d4 & 63));
        float sg = (d4 < 64) ? -1.f : 1.f;
        uint4 o;
        o.x = f2tf32(fmaf(x1.x, c4.x, sg * x2.x * s4.x));
        o.y = f2tf32(fmaf(x1.y, c4.y, sg * x2.y * s4.y));
        o.z = f2tf32(fmaf(x1.z, c4.z, sg * x2.z * s4.z));
        o.w = f2tf32(fmaf(x1.w, c4.w, sg * x2.w * s4.w));
        *(uint4*)&Qs[q * AQ_STR + d4] = o;
    }

    float m0 = -1e30f, m1 = -1e30f, l0 = 0.f, l1 = 0.f;
    float oacc[16][4];
#pragma unroll
    for (int i = 0; i < 16; i++)
#pragma unroll
        for (int j = 0; j < 4; j++) oacc[i][j] = 0.f;

    const float scale = 0.08838834764831845f;
    const int ntiles = 2 * qt + 2;

    for (int st = 0; st < ntiles; st++) {
        const int s0 = st * 64;

#pragma unroll
        for (int p = 0; p < 8; p++) {
            int idx = tid + p * 256;
            int s  = idx >> 5;
            int d4 = (idx & 31) << 2;
            int t  = s0 + s;
            const float* kp = QKV + (size_t)(b * TT + t) * NQKV + 2048 + gkv * HD;
            const float* vp = QKV + (size_t)(b * TT + t) * NQKV + 2560 + gkv * HD;
            float4 x1 = *(const float4*)(kp + d4);
            float4 x2 = *(const float4*)(kp + (d4 ^ 64));
            float4 vv = *(const float4*)(vp + d4);
            float4 c4 = *(const float4*)(g_cos + t * 64 + (d4 & 63));
            float4 s4 = *(const float4*)(g_sin + t * 64 + (d4 & 63));
            float sg = (d4 < 64) ? -1.f : 1.f;
            uint4 ko, vo;
            ko.x = f2tf32(fmaf(x1.x, c4.x, sg * x2.x * s4.x));
            ko.y = f2tf32(fmaf(x1.y, c4.y, sg * x2.y * s4.y));
            ko.z = f2tf32(fmaf(x1.z, c4.z, sg * x2.z * s4.z));
            ko.w = f2tf32(fmaf(x1.w, c4.w, sg * x2.w * s4.w));
            vo.x = f2tf32(vv.x); vo.y = f2tf32(vv.y);
            vo.z = f2tf32(vv.z); vo.w = f2tf32(vv.w);
            *(uint4*)&Ks[s * AK_STR + d4] = ko;
            *(uint4*)&Vs[s * AV_STR + d4] = vo;
        }
        __syncthreads();

        if (q0 + wm + 15 >= s0) {
            float sacc[8][4];
#pragma unroll
            for (int i = 0; i < 8; i++)
#pragma unroll
                for (int j = 0; j < 4; j++) sacc[i][j] = 0.f;

            const uint32_t* qrow = Qs + (wm + gID) * AQ_STR;
#pragma unroll
            for (int kk = 0; kk < 16; kk++) {
                const int k0 = kk * 8;
                uint32_t a0 = qrow[k0 + tig];
                uint32_t a1 = qrow[8 * AQ_STR + k0 + tig];
                uint32_t a2 = qrow[k0 + tig + 4];
                uint32_t a3 = qrow[8 * AQ_STR + k0 + tig + 4];
#pragma unroll
                for (int ni = 0; ni < 8; ni++) {
                    const uint32_t* kp2 = Ks + (gID + ni * 8) * AK_STR + k0 + tig;
                    MMA_TF32(sacc[ni], a0, a1, a2, a3, kp2[0], kp2[4]);
                }
            }

            const int lim0 = row0 - s0;
            const int lim1 = lim0 + 8;
            const bool diag = (st >= 2 * qt);
            float mx0 = -1e30f, mx1 = -1e30f;
#pragma unroll
            for (int ni = 0; ni < 8; ni++) {
#pragma unroll
                for (int c = 0; c < 2; c++) {
                    int j = ni * 8 + tig * 2 + c;
                    float v0 = sacc[ni][c] * scale;
                    float v1 = sacc[ni][2 + c] * scale;
                    if (diag) {
                        if (j > lim0) v0 = -1e30f;
                        if (j > lim1) v1 = -1e30f;
                    }
                    sacc[ni][c]     = v0;
                    sacc[ni][2 + c] = v1;
                    mx0 = fmaxf(mx0, v0);
                    mx1 = fmaxf(mx1, v1);
                }
            }
            mx0 = fmaxf(mx0, __shfl_xor_sync(0xffffffffu, mx0, 1));
            mx0 = fmaxf(mx0, __shfl_xor_sync(0xffffffffu, mx0, 2));
            mx1 = fmaxf(mx1, __shfl_xor_sync(0xffffffffu, mx1, 1));
            mx1 = fmaxf(mx1, __shfl_xor_sync(0xffffffffu, mx1, 2));
            float mn0 = fmaxf(m0, mx0), mn1 = fmaxf(m1, mx1);
            float cr0 = __expf(m0 - mn0), cr1 = __expf(m1 - mn1);
            float sum0 = 0.f, sum1 = 0.f;
#pragma unroll
            for (int ni = 0; ni < 8; ni++) {
#pragma unroll
                for (int c = 0; c < 2; c++) {
                    float p0 = __expf(sacc[ni][c] - mn0);
                    float p1 = __expf(sacc[ni][2 + c] - mn1);
                    sacc[ni][c]     = p0;
                    sacc[ni][2 + c] = p1;
                    sum0 += p0;
                    sum1 += p1;
                }
            }
            sum0 += __shfl_xor_sync(0xffffffffu, sum0, 1);
            sum0 += __shfl_xor_sync(0xffffffffu, sum0, 2);
            sum1 += __shfl_xor_sync(0xffffffffu, sum1, 1);
            sum1 += __shfl_xor_sync(0xffffffffu, sum1, 2);
            l0 = l0 * cr0 + sum0;
            l1 = l1 * cr1 + sum1;
            m0 = mn0; m1 = mn1;

#pragma unroll
            for (int ni = 0; ni < 16; ni++) {
                oacc[ni][0] *= cr0; oacc[ni][1] *= cr0;
                oacc[ni][2] *= cr1; oacc[ni][3] *= cr1;
            }

            uint32_t* pr0 = Ps + (wm + gID) * AP_STR;
            uint32_t* pr1 = pr0 + 8 * AP_STR;
#pragma unroll
            for (int ni = 0; ni < 8; ni++) {
                int c = ni * 8 + tig * 2;
                pr0[c]     = f2tf32(sacc[ni][0]);
                pr0[c + 1] = f2tf32(sacc[ni][1]);
                pr1[c]     = f2tf32(sacc[ni][2]);
                pr1[c + 1] = f2tf32(sacc[ni][3]);
            }
            __syncwarp();

            const uint32_t* prow = Ps + (wm + gID) * AP_STR;
#pragma unroll
            for (int kk = 0; kk < 8; kk++) {
                const int k0 = kk * 8;
                uint32_t a0 = prow[k0 + tig];
                uint32_t a1 = prow[8 * AP_STR + k0 + tig];
                uint32_t a2 = prow[k0 + tig + 4];
                uint32_t a3 = prow[8 * AP_STR + k0 + tig + 4];
#pragma unroll
                for (int ni = 0; ni < 16; ni++) {
                    const uint32_t* vp2 = Vs + (k0 + tig) * AV_STR + gID + ni * 8;
                    MMA_TF32(oacc[ni], a0, a1, a2, a3, vp2[0], vp2[4 * AV_STR]);
                }
            }
        }
        __syncthreads();
    }

    float li0 = 1.f / l0, li1 = 1.f / l1;
    uint32_t* y0 = Y + (size_t)(b * TT + row0) * DD + hh * HD;
    uint32_t* y1 = y0 + (size_t)8 * DD;
#pragma unroll
    for (int ni = 0; ni < 16; ni++) {
        int c = ni * 8 + tig * 2;
        uint2 o0, o1;
        o0.x = f2tf32(oacc[ni][0] * li0); o0.y = f2tf32(oacc[ni][1] * li0);
        o1.x = f2tf32(oacc[ni][2] * li1); o1.y = f2tf32(oacc[ni][3] * li1);
        *(uint2*)(y0 + c) = o0;
        *(uint2*)(y1 + c) = o1;
    }
}

// ---------------------------------------------------------------------------
extern "C" void kernel_launch(void* const* d_in, const int* in_sizes, int n_in,
                              void* d_out, int out_size)
{
    const float* x  = (const float*)d_in[0];
    const float* Wq = (const float*)d_in[1];
    const float* Wk = (const float*)d_in[2];
    const float* Wv = (const float*)d_in[3];
    const float* Wo = (const float*)d_in[4];
    float* out = (float*)d_out;

    uint32_t *xT, *Wqkv, *WoT, *Yp;
    float *QKVp;
    cudaGetSymbolAddress((void**)&xT,   g_xT);
    cudaGetSymbolAddress((void**)&Wqkv, g_Wqkv);
    cudaGetSymbolAddress((void**)&WoT,  g_WoT);
    cudaGetSymbolAddress((void**)&QKVp, g_QKV);
    cudaGetSymbolAddress((void**)&Yp,   g_Y);

    static bool attr_set = false;
    if (!attr_set) {
        cudaFuncSetAttribute(gemm_pre,
                             cudaFuncAttributeMaxDynamicSharedMemorySize,
                             GEMM_SMEM);
        cudaFuncSetAttribute(attn_tc,
                             cudaFuncAttributeMaxDynamicSharedMemorySize,
                             ATTN_SMEM);
        attr_set = true;
    }

    rope_table_kernel<<<TT, 64>>>();
    cvt_kernel<<<(MROWS * DD) / 1024, 256>>>(x, xT);
    pack_w_kernel<<<(DD * NQKV) / 1024, 256>>>(Wq, Wk, Wv, Wqkv);
    cvt_kernel<<<(DD * DD) / 1024, 256>>>(Wo, WoT);

    // Fused Q|K|V projection: [4096,2048] @ [2048,3072]
    gemm_pre<<<dim3(NQKV / 128, MROWS / 256), 256, GEMM_SMEM>>>(
        xT, Wqkv, QKVp, MROWS, NQKV, DD);

    attn_tc<<<dim3(TT / 128, NH, BB), 256, ATTN_SMEM>>>(QKVp, Yp);

    // Output projection: [4096,2048] @ [2048,2048]
    gemm_pre<<<dim3(DD / 128, MROWS / 256), 256, GEMM_SMEM>>>(
        Yp, WoT, out, MROWS, DD, DD);
}

// round 6
// speedup vs baseline: 6.7365x; 1.0440x over previous
#include <cuda_runtime.h>
#include <math.h>
#include <stdint.h>

#define BB 4
#define TT 1024
#define DD 2048
#define NH 16
#define NKV 4
#define HD 128
#define MROWS (BB*TT)    // 4096
#define NQKV 3072        // packed Q|K|V output cols

// Scratch (device globals; no runtime allocation)
__device__ uint32_t g_xT[MROWS * DD];          // x in tf32 bits
__device__ uint32_t g_Wqkv[DD * NQKV];         // packed [Wq|Wk|Wv] tf32 bits
__device__ uint32_t g_WoT[DD * DD];            // Wo tf32 bits
__device__ uint32_t g_Qr[BB * NH * TT * HD];   // roped Q, tf32, [b][h][t][d]
__device__ uint32_t g_Kr[BB * NKV * TT * HD];  // roped K, tf32, [b][g][t][d]
__device__ uint32_t g_Vr[BB * NKV * TT * HD];  // V, tf32, [b][g][t][d]
__device__ uint32_t g_Y[MROWS * DD];           // attention output (tf32 bits)
__device__ float    g_cos[TT * 64];
__device__ float    g_sin[TT * 64];

__device__ __forceinline__ uint32_t f2tf32(float f) {
    uint32_t r;
    asm("cvt.rna.tf32.f32 %0, %1;" : "=r"(r) : "f"(f));
    return r;
}

#define MMA_TF32(ACC, A0, A1, A2, A3, B0, B1)                                  \
    asm volatile(                                                              \
        "mma.sync.aligned.m16n8k8.row.col.f32.tf32.tf32.f32 "                  \
        "{%0,%1,%2,%3}, {%4,%5,%6,%7}, {%8,%9}, {%0,%1,%2,%3};"                \
        : "+f"((ACC)[0]), "+f"((ACC)[1]), "+f"((ACC)[2]), "+f"((ACC)[3])       \
        : "r"(A0), "r"(A1), "r"(A2), "r"(A3), "r"(B0), "r"(B1))

__device__ __forceinline__ void cp16(uint32_t dst, const void* src) {
    asm volatile("cp.async.cg.shared.global [%0], [%1], 16;" ::
                 "r"(dst), "l"(src));
}
#define CP_COMMIT() asm volatile("cp.async.commit_group;")
#define CP_WAIT(n)  asm volatile("cp.async.wait_group %0;" :: "n"(n))

// ---------------------------------------------------------------------------
// GEMM common: 256x128 CTA tile, KT=32, 4-stage cp.async, warp tile 64x64.
// ---------------------------------------------------------------------------
#define ASTR 36
#define BSTR 136
#define AW (256*ASTR)            // 9216 words per A stage
#define STG (AW + 32*BSTR)       // 13568 words per stage
#define GEMM_SMEM (4*STG*4)      // 217088 bytes

// Mainloop body shared by both GEMM kernels (acc must be named acc).
#define GEMM_MAINLOOP(Aptr, Bptr, Nn, Kk)                                      \
    const int NT = (Kk) >> 5;                                                  \
    auto LOAD = [&](int kt, int s) {                                           \
        uint32_t abase = smaddr + (uint32_t)(s * STG) * 4;                     \
        _Pragma("unroll")                                                      \
        for (int p = 0; p < 8; p++) {                                          \
            int id = tid + p * 256;                                            \
            int m = id >> 3, kc = (id & 7) << 2;                               \
            cp16(abase + (uint32_t)(m * ASTR + kc) * 4,                        \
                 (Aptr) + (size_t)(bm + m) * (Kk) + kt * 32 + kc);             \
        }                                                                      \
        uint32_t bbase = abase + AW * 4;                                       \
        _Pragma("unroll")                                                      \
        for (int p = 0; p < 4; p++) {                                          \
            int id = tid + p * 256;                                            \
            int k = id >> 5, nc = (id & 31) << 2;                              \
            cp16(bbase + (uint32_t)(k * BSTR + nc) * 4,                        \
                 (Bptr) + (size_t)(kt * 32 + k) * (Nn) + bn + nc);             \
        }                                                                      \
        CP_COMMIT();                                                           \
    };                                                                         \
    LOAD(0, 0); LOAD(1, 1); LOAD(2, 2);                                        \
    for (int kt = 0; kt < NT; kt++) {                                          \
        CP_WAIT(2);                                                            \
        __syncthreads();                                                       \
        const int nk = kt + 3;                                                 \
        if (nk < NT) LOAD(nk, nk & 3);                                         \
        else CP_COMMIT();                                                      \
        const uint32_t* as = smg + (kt & 3) * STG + (wm + gID) * ASTR;         \
        const uint32_t* bs = smg + (kt & 3) * STG + AW + wn + gID;             \
        _Pragma("unroll")                                                      \
        for (int kk = 0; kk < 4; kk++) {                                       \
            const int k0 = kk * 8;                                             \
            uint32_t af[4][4], bf[8][2];                                       \
            _Pragma("unroll")                                                  \
            for (int mi = 0; mi < 4; mi++) {                                   \
                const uint32_t* ap = as + mi * 16 * ASTR + k0 + tig;           \
                af[mi][0] = ap[0];                                             \
                af[mi][1] = ap[8 * ASTR];                                      \
                af[mi][2] = ap[4];                                             \
                af[mi][3] = ap[8 * ASTR + 4];                                  \
            }                                                                  \
            _Pragma("unroll")                                                  \
            for (int ni = 0; ni < 8; ni++) {                                   \
                const uint32_t* bp = bs + (k0 + tig) * BSTR + ni * 8;          \
                bf[ni][0] = bp[0];                                             \
                bf[ni][1] = bp[4 * BSTR];                                      \
            }                                                                  \
            _Pragma("unroll")                                                  \
            for (int mi = 0; mi < 4; mi++)                                     \
                _Pragma("unroll")                                              \
                for (int ni = 0; ni < 8; ni++)                                 \
                    MMA_TF32(acc[mi][ni], af[mi][0], af[mi][1], af[mi][2],     \
                             af[mi][3], bf[ni][0], bf[ni][1]);                 \
        }                                                                      \
    }

// ---------------------------------------------------------------------------
// Fused QKV projection: C = x @ [Wq|Wk|Wv], epilogue applies RoPE (Q,K) and
// writes tf32 bits to head-major Qr/Kr/Vr. Each 128-col N tile == one head.
// ---------------------------------------------------------------------------
__global__ __launch_bounds__(256, 1) void gemm_qkv(
    const uint32_t* __restrict__ A, const uint32_t* __restrict__ B,
    uint32_t* __restrict__ Qr, uint32_t* __restrict__ Kr,
    uint32_t* __restrict__ Vr)
{
    extern __shared__ uint32_t smg[];
    const uint32_t smaddr = (uint32_t)__cvta_generic_to_shared(smg);

    const int tid  = threadIdx.x;
    const int bm   = blockIdx.y * 256;
    const int bn   = blockIdx.x * 128;
    const int warp = tid >> 5, lane = tid & 31;
    const int wm   = (warp & 3) * 64;
    const int wn   = (warp >> 2) * 64;
    const int gID  = lane >> 2, tig = lane & 3;

    float acc[4][8][4];
#pragma unroll
    for (int i = 0; i < 4; i++)
#pragma unroll
        for (int j = 0; j < 8; j++)
#pragma unroll
            for (int l = 0; l < 4; l++) acc[i][j][l] = 0.f;

    GEMM_MAINLOOP(A, B, NQKV, DD)

    // ---- epilogue: stage fp32 tile in smem, rope+cvt, write head-major ----
    __syncthreads();
    uint32_t* Cs = smg;           // 256*132 = 33792 words, reuses stages 0-2
#pragma unroll
    for (int mi = 0; mi < 4; mi++) {
        const int r0 = wm + mi * 16 + gID;
#pragma unroll
        for (int ni = 0; ni < 8; ni++) {
            const int c = wn + ni * 8 + tig * 2;
            Cs[r0 * 132 + c]     = __float_as_uint(acc[mi][ni][0]);
            Cs[r0 * 132 + c + 1] = __float_as_uint(acc[mi][ni][1]);
            Cs[(r0 + 8) * 132 + c]     = __float_as_uint(acc[mi][ni][2]);
            Cs[(r0 + 8) * 132 + c + 1] = __float_as_uint(acc[mi][ni][3]);
        }
    }
    __syncthreads();

    uint32_t* dst;
    int head, hs, doRope;
    if (bn < 2048)      { head = bn >> 7;          dst = Qr; hs = NH;  doRope = 1; }
    else if (bn < 2560) { head = (bn - 2048) >> 7; dst = Kr; hs = NKV; doRope = 1; }
    else                { head = (bn - 2560) >> 7; dst = Vr; hs = NKV; doRope = 0; }

#pragma unroll 4
    for (int p = 0; p < 32; p++) {
        int idx = tid + p * 256;
        int r = idx >> 5;
        int d2 = (idx & 31) << 1;       // even d pair base: 0..62
        int bt = bm + r;
        int bb = bt >> 10;
        int t  = bt & (TT - 1);
        float lo0 = __uint_as_float(Cs[r * 132 + d2]);
        float lo1 = __uint_as_float(Cs[r * 132 + d2 + 1]);
        float hi0 = __uint_as_float(Cs[r * 132 + d2 + 64]);
        float hi1 = __uint_as_float(Cs[r * 132 + d2 + 65]);
        float c0 = 1.f, c1 = 1.f, s0 = 0.f, s1 = 0.f;
        if (doRope) {
            float2 cc = *(const float2*)(g_cos + t * 64 + d2);
            float2 ss = *(const float2*)(g_sin + t * 64 + d2);
            c0 = cc.x; c1 = cc.y; s0 = ss.x; s1 = ss.y;
        }
        uint32_t* o = dst + ((size_t)(bb * hs + head) * TT + t) * HD;
        uint2 olo, ohi;
        olo.x = f2tf32(lo0 * c0 - hi0 * s0);
        olo.y = f2tf32(lo1 * c1 - hi1 * s1);
        ohi.x = f2tf32(hi0 * c0 + lo0 * s0);
        ohi.y = f2tf32(hi1 * c1 + lo1 * s1);
        *(uint2*)(o + d2)      = olo;
        *(uint2*)(o + d2 + 64) = ohi;
    }
}

// ---------------------------------------------------------------------------
// Generic GEMM (Wo projection): C fp32 = A(tf32 bits) @ B(tf32 bits)
// ---------------------------------------------------------------------------
__global__ __launch_bounds__(256, 1) void gemm_pre(
    const uint32_t* __restrict__ A, const uint32_t* __restrict__ B,
    float* __restrict__ C, int M, int N, int K)
{
    extern __shared__ uint32_t smg[];
    const uint32_t smaddr = (uint32_t)__cvta_generic_to_shared(smg);

    const int tid  = threadIdx.x;
    const int bm   = blockIdx.y * 256;
    const int bn   = blockIdx.x * 128;
    const int warp = tid >> 5, lane = tid & 31;
    const int wm   = (warp & 3) * 64;
    const int wn   = (warp >> 2) * 64;
    const int gID  = lane >> 2, tig = lane & 3;

    float acc[4][8][4];
#pragma unroll
    for (int i = 0; i < 4; i++)
#pragma unroll
        for (int j = 0; j < 8; j++)
#pragma unroll
            for (int l = 0; l < 4; l++) acc[i][j][l] = 0.f;

    GEMM_MAINLOOP(A, B, N, K)

#pragma unroll
    for (int mi = 0; mi < 4; mi++) {
        const int r0 = bm + wm + mi * 16 + gID;
#pragma unroll
        for (int ni = 0; ni < 8; ni++) {
            const int c = bn + wn + ni * 8 + tig * 2;
            *(float2*)&C[(size_t)r0 * N + c] =
                make_float2(acc[mi][ni][0], acc[mi][ni][1]);
            *(float2*)&C[(size_t)(r0 + 8) * N + c] =
                make_float2(acc[mi][ni][2], acc[mi][ni][3]);
        }
    }
}

// ---------------------------------------------------------------------------
// Prep kernels
// ---------------------------------------------------------------------------
__global__ void cvt_kernel(const float* __restrict__ in,
                           uint32_t* __restrict__ out)
{
    int i = (blockIdx.x * 256 + threadIdx.x) * 4;
    float4 v = *(const float4*)(in + i);
    uint4 o;
    o.x = f2tf32(v.x); o.y = f2tf32(v.y);
    o.z = f2tf32(v.z); o.w = f2tf32(v.w);
    *(uint4*)(out + i) = o;
}

__global__ void pack_w_kernel(const float* __restrict__ Wq,
                              const float* __restrict__ Wk,
                              const float* __restrict__ Wv,
                              uint32_t* __restrict__ W)
{
    int idx = (blockIdx.x * 256 + threadIdx.x) * 4;
    int r = idx / NQKV, c = idx - r * NQKV;
    const float* src;
    if (c < 2048)      src = Wq + (size_t)r * 2048 + c;
    else if (c < 2560) src = Wk + (size_t)r * 512 + (c - 2048);
    else               src = Wv + (size_t)r * 512 + (c - 2560);
    float4 v = *(const float4*)src;
    uint4 o;
    o.x = f2tf32(v.x); o.y = f2tf32(v.y);
    o.z = f2tf32(v.z); o.w = f2tf32(v.w);
    *(uint4*)(W + idx) = o;
}

__global__ void rope_table_kernel()
{
    int t = blockIdx.x;
    int i = threadIdx.x;
    float inv = powf(10000.0f, -(float)i / 64.0f);
    float ang = (float)t * inv;
    g_cos[t * 64 + i] = cosf(ang);
    g_sin[t * 64 + i] = sinf(ang);
}

// ---------------------------------------------------------------------------
// Tensor-core flash attention, causal, GQA. Inputs pre-roped tf32 head-major.
// cp.async pipelined: K single-buffered (prefetch after S), V double-buffered.
// ---------------------------------------------------------------------------
#define AQ_STR 132
#define AK_STR 132
#define AV_STR 136
#define AP_STR 68
// Qs 128*132 + Ks 64*132 + Vs 2*64*136 + Ps 128*68 = 51456 words
#define ATTN_SMEM (51456 * 4)

__global__ __launch_bounds__(256, 1) void attn_tc(
    const uint32_t* __restrict__ Qr, const uint32_t* __restrict__ Kr,
    const uint32_t* __restrict__ Vr, uint32_t* __restrict__ Y)
{
    extern __shared__ uint32_t sma[];
    uint32_t* Qs  = sma;
    uint32_t* Ks  = Qs + 128 * AQ_STR;
    uint32_t* Vsb = Ks + 64 * AK_STR;          // [2][64*AV_STR]
    uint32_t* Ps  = Vsb + 2 * 64 * AV_STR;
    const uint32_t smaddr = (uint32_t)__cvta_generic_to_shared(sma);
    const uint32_t Qs_a = smaddr;
    const uint32_t Ks_a = Qs_a + 128 * AQ_STR * 4;
    const uint32_t Vs_a = Ks_a + 64 * AK_STR * 4;

    const int tid  = threadIdx.x;
    const int warp = tid >> 5, lane = tid & 31;
    const int gID  = lane >> 2, tig = lane & 3;
    const int qt   = (gridDim.x - 1) - blockIdx.x;   // heavy first
    const int hh   = blockIdx.y;
    const int b    = blockIdx.z;
    const int gkv  = hh >> 2;
    const int q0   = qt * 128;
    const int wm   = warp * 16;
    const int row0 = q0 + wm + gID;

    const uint32_t* Qbase = Qr + ((size_t)(b * NH + hh) * TT + q0) * HD;
    const uint32_t* Kbase = Kr + (size_t)(b * NKV + gkv) * TT * HD;
    const uint32_t* Vbase = Vr + (size_t)(b * NKV + gkv) * TT * HD;

    auto LOADQ = [&]() {
#pragma unroll
        for (int p = 0; p < 16; p++) {
            int id = tid + p * 256;
            int q = id >> 5, c = (id & 31) << 2;
            cp16(Qs_a + (uint32_t)(q * AQ_STR + c) * 4, Qbase + q * HD + c);
        }
    };
    auto LOADK = [&](int st) {
        const uint32_t* src = Kbase + (size_t)st * 64 * HD;
#pragma unroll
        for (int p = 0; p < 8; p++) {
            int id = tid + p * 256;
            int s = id >> 5, c = (id & 31) << 2;
            cp16(Ks_a + (uint32_t)(s * AK_STR + c) * 4, src + s * HD + c);
        }
    };
    auto LOADV = [&](int st) {
        const uint32_t* src = Vbase + (size_t)st * 64 * HD;
        uint32_t dbase = Vs_a + (uint32_t)((st & 1) * 64 * AV_STR) * 4;
#pragma unroll
        for (int p = 0; p < 8; p++) {
            int id = tid + p * 256;
            int s = id >> 5, c = (id & 31) << 2;
            cp16(dbase + (uint32_t)(s * AV_STR + c) * 4, src + s * HD + c);
        }
    };

    const int ntiles = 2 * qt + 2;

    LOADQ(); LOADK(0); LOADV(0); CP_COMMIT();   // C0
    LOADV(1); CP_COMMIT();                      // C1 (tile 1 always exists)

    float m0 = -1e30f, m1 = -1e30f, l0 = 0.f, l1 = 0.f;
    float oacc[16][4];
#pragma unroll
    for (int i = 0; i < 16; i++)
#pragma unroll
        for (int j = 0; j < 4; j++) oacc[i][j] = 0.f;

    const float scale = 0.08838834764831845f;   // 1/sqrt(128)

    for (int st = 0; st < ntiles; st++) {
        const int s0 = st * 64;
        const bool active = (q0 + wm + 15 >= s0);

        CP_WAIT(1);          // K(st), V(st), (and Q on st=0) ready
        __syncthreads();

        float sacc[8][4];
        if (active) {
#pragma unroll
            for (int i = 0; i < 8; i++)
#pragma unroll
                for (int j = 0; j < 4; j++) sacc[i][j] = 0.f;

            const uint32_t* qrow = Qs + (wm + gID) * AQ_STR;
#pragma unroll
            for (int kk = 0; kk < 16; kk++) {
                const int k0 = kk * 8;
                uint32_t a0 = qrow[k0 + tig];
                uint32_t a1 = qrow[8 * AQ_STR + k0 + tig];
                uint32_t a2 = qrow[k0 + tig + 4];
                uint32_t a3 = qrow[8 * AQ_STR + k0 + tig + 4];
#pragma unroll
                for (int ni = 0; ni < 8; ni++) {
                    const uint32_t* kp2 = Ks + (gID + ni * 8) * AK_STR + k0 + tig;
                    MMA_TF32(sacc[ni], a0, a1, a2, a3, kp2[0], kp2[4]);
                }
            }
        }
        __syncthreads();     // all warps done reading Ks

        if (st + 1 < ntiles) LOADK(st + 1);
        CP_COMMIT();

        if (active) {
            const int lim0 = row0 - s0;
            const int lim1 = lim0 + 8;
            const bool diag = (st >= 2 * qt);
            float mx0 = -1e30f, mx1 = -1e30f;
#pragma unroll
            for (int ni = 0; ni < 8; ni++) {
#pragma unroll
                for (int c = 0; c < 2; c++) {
                    int j = ni * 8 + tig * 2 + c;
                    float v0 = sacc[ni][c] * scale;
                    float v1 = sacc[ni][2 + c] * scale;
                    if (diag) {
                        if (j > lim0) v0 = -1e30f;
                        if (j > lim1) v1 = -1e30f;
                    }
                    sacc[ni][c]     = v0;
                    sacc[ni][2 + c] = v1;
                    mx0 = fmaxf(mx0, v0);
                    mx1 = fmaxf(mx1, v1);
                }
            }
            mx0 = fmaxf(mx0, __shfl_xor_sync(0xffffffffu, mx0, 1));
            mx0 = fmaxf(mx0, __shfl_xor_sync(0xffffffffu, mx0, 2));
            mx1 = fmaxf(mx1, __shfl_xor_sync(0xffffffffu, mx1, 1));
            mx1 = fmaxf(mx1, __shfl_xor_sync(0xffffffffu, mx1, 2));
            float mn0 = fmaxf(m0, mx0), mn1 = fmaxf(m1, mx1);
            float cr0 = __expf(m0 - mn0), cr1 = __expf(m1 - mn1);
            float sum0 = 0.f, sum1 = 0.f;
#pragma unroll
            for (int ni = 0; ni < 8; ni++) {
#pragma unroll
                for (int c = 0; c < 2; c++) {
                    float p0 = __expf(sacc[ni][c] - mn0);
                    float p1 = __expf(sacc[ni][2 + c] - mn1);
                    sacc[ni][c]     = p0;
                    sacc[ni][2 + c] = p1;
                    sum0 += p0;
                    sum1 += p1;
                }
            }
            sum0 += __shfl_xor_sync(0xffffffffu, sum0, 1);
            sum0 += __shfl_xor_sync(0xffffffffu, sum0, 2);
            sum1 += __shfl_xor_sync(0xffffffffu, sum1, 1);
            sum1 += __shfl_xor_sync(0xffffffffu, sum1, 2);
            l0 = l0 * cr0 + sum0;
            l1 = l1 * cr1 + sum1;
            m0 = mn0; m1 = mn1;

#pragma unroll
            for (int ni = 0; ni < 16; ni++) {
                oacc[ni][0] *= cr0; oacc[ni][1] *= cr0;
                oacc[ni][2] *= cr1; oacc[ni][3] *= cr1;
            }

            uint32_t* pr0 = Ps + (wm + gID) * AP_STR;
            uint32_t* pr1 = pr0 + 8 * AP_STR;
#pragma unroll
            for (int ni = 0; ni < 8; ni++) {
                int c = ni * 8 + tig * 2;
                pr0[c]     = f2tf32(sacc[ni][0]);
                pr0[c + 1] = f2tf32(sacc[ni][1]);
                pr1[c]     = f2tf32(sacc[ni][2]);
                pr1[c + 1] = f2tf32(sacc[ni][3]);
            }
            __syncwarp();

            const uint32_t* vbuf = Vsb + (st & 1) * 64 * AV_STR;
            const uint32_t* prow = Ps + (wm + gID) * AP_STR;
#pragma unroll
            for (int kk = 0; kk < 8; kk++) {
                const int k0 = kk * 8;
                uint32_t a0 = prow[k0 + tig];
                uint32_t a1 = prow[8 * AP_STR + k0 + tig];
                uint32_t a2 = prow[k0 + tig + 4];
                uint32_t a3 = prow[8 * AP_STR + k0 + tig + 4];
#pragma unroll
                for (int ni = 0; ni < 16; ni++) {
                    const uint32_t* vp2 = vbuf + (k0 + tig) * AV_STR + gID + ni * 8;
                    MMA_TF32(oacc[ni], a0, a1, a2, a3, vp2[0], vp2[4 * AV_STR]);
                }
            }
        }
        __syncthreads();     // PV done -> V(st) buffer free

        if (st + 2 < ntiles) LOADV(st + 2);
        CP_COMMIT();
    }

    float li0 = 1.f / l0, li1 = 1.f / l1;
    uint32_t* y0 = Y + (size_t)(b * TT + row0) * DD + hh * HD;
    uint32_t* y1 = y0 + (size_t)8 * DD;
#pragma unroll
    for (int ni = 0; ni < 16; ni++) {
        int c = ni * 8 + tig * 2;
        uint2 o0, o1;
        o0.x = f2tf32(oacc[ni][0] * li0); o0.y = f2tf32(oacc[ni][1] * li0);
        o1.x = f2tf32(oacc[ni][2] * li1); o1.y = f2tf32(oacc[ni][3] * li1);
        *(uint2*)(y0 + c) = o0;
        *(uint2*)(y1 + c) = o1;
    }
}

// ---------------------------------------------------------------------------
extern "C" void kernel_launch(void* const* d_in, const int* in_sizes, int n_in,
                              void* d_out, int out_size)
{
    const float* x  = (const float*)d_in[0];
    const float* Wq = (const float*)d_in[1];
    const float* Wk = (const float*)d_in[2];
    const float* Wv = (const float*)d_in[3];
    const float* Wo = (const float*)d_in[4];
    float* out = (float*)d_out;

    uint32_t *xT, *Wqkv, *WoT, *Qr, *Kr, *Vr, *Yp;
    cudaGetSymbolAddress((void**)&xT,   g_xT);
    cudaGetSymbolAddress((void**)&Wqkv, g_Wqkv);
    cudaGetSymbolAddress((void**)&WoT,  g_WoT);
    cudaGetSymbolAddress((void**)&Qr,   g_Qr);
    cudaGetSymbolAddress((void**)&Kr,   g_Kr);
    cudaGetSymbolAddress((void**)&Vr,   g_Vr);
    cudaGetSymbolAddress((void**)&Yp,   g_Y);

    static bool attr_set = false;
    if (!attr_set) {
        cudaFuncSetAttribute(gemm_qkv,
                             cudaFuncAttributeMaxDynamicSharedMemorySize,
                             GEMM_SMEM);
        cudaFuncSetAttribute(gemm_pre,
                             cudaFuncAttributeMaxDynamicSharedMemorySize,
                             GEMM_SMEM);
        cudaFuncSetAttribute(attn_tc,
                             cudaFuncAttributeMaxDynamicSharedMemorySize,
                             ATTN_SMEM);
        attr_set = true;
    }

    rope_table_kernel<<<TT, 64>>>();
    cvt_kernel<<<(MROWS * DD) / 1024, 256>>>(x, xT);
    pack_w_kernel<<<(DD * NQKV) / 1024, 256>>>(Wq, Wk, Wv, Wqkv);
    cvt_kernel<<<(DD * DD) / 1024, 256>>>(Wo, WoT);

    // Fused Q|K|V projection + RoPE + head-major tf32 scatter
    gemm_qkv<<<dim3(NQKV / 128, MROWS / 256), 256, GEMM_SMEM>>>(
        xT, Wqkv, Qr, Kr, Vr);

    attn_tc<<<dim3(TT / 128, NH, BB), 256, ATTN_SMEM>>>(Qr, Kr, Vr, Yp);

    // Output projection
    gemm_pre<<<dim3(DD / 128, MROWS / 256), 256, GEMM_SMEM>>>(
        Yp, WoT, out, MROWS, DD, DD);
}

// round 7
// speedup vs baseline: 7.1842x; 1.0665x over previous
#include <cuda_runtime.h>
#include <math.h>
#include <stdint.h>

#define BB 4
#define TT 1024
#define DD 2048
#define NH 16
#define NKV 4
#define HD 128
#define MROWS (BB*TT)    // 4096
#define NQKV 3072        // packed Q|K|V output cols

// Scratch (device globals; no runtime allocation)
__device__ uint32_t g_xT[MROWS * DD];          // x in tf32 bits
__device__ uint32_t g_Wqkv[DD * NQKV];         // packed [Wq|Wk|Wv] tf32 bits
__device__ uint32_t g_WoT[DD * DD];            // Wo tf32 bits
__device__ uint32_t g_Qr[BB * NH * TT * HD];   // roped Q, tf32, [b][h][t][d]
__device__ uint32_t g_Kr[BB * NKV * TT * HD];  // roped K, tf32, [b][g][t][d]
__device__ uint32_t g_Vr[BB * NKV * TT * HD];  // V, tf32, [b][g][t][d]
__device__ uint32_t g_Y[MROWS * DD];           // attention output (tf32 bits)
__device__ float    g_cos[TT * 64];
__device__ float    g_sin[TT * 64];

__device__ __forceinline__ uint32_t f2tf32(float f) {
    uint32_t r;
    asm("cvt.rna.tf32.f32 %0, %1;" : "=r"(r) : "f"(f));
    return r;
}

#define MMA_TF32(ACC, A0, A1, A2, A3, B0, B1)                                  \
    asm volatile(                                                              \
        "mma.sync.aligned.m16n8k8.row.col.f32.tf32.tf32.f32 "                  \
        "{%0,%1,%2,%3}, {%4,%5,%6,%7}, {%8,%9}, {%0,%1,%2,%3};"                \
        : "+f"((ACC)[0]), "+f"((ACC)[1]), "+f"((ACC)[2]), "+f"((ACC)[3])       \
        : "r"(A0), "r"(A1), "r"(A2), "r"(A3), "r"(B0), "r"(B1))

__device__ __forceinline__ void cp16(uint32_t dst, const void* src) {
    asm volatile("cp.async.cg.shared.global [%0], [%1], 16;" ::
                 "r"(dst), "l"(src));
}
#define CP_COMMIT() asm volatile("cp.async.commit_group;")
#define CP_WAIT(n)  asm volatile("cp.async.wait_group %0;" :: "n"(n))

// ---------------------------------------------------------------------------
// GEMM common: 128x128 CTA tile, 128 threads (4 warps, 2Mx2N, warp 64x64),
// KT=32, 3-stage cp.async, 2 CTAs/SM.
// ---------------------------------------------------------------------------
#define ASTR 36
#define BSTR 136
#define AW (128*ASTR)            // 4608 words per A stage
#define STG (AW + 32*BSTR)       // 8960 words per stage
#define GEMM_SMEM (3*STG*4)      // 107520 bytes per CTA

// Mainloop body shared by both GEMM kernels (acc must be named acc).
#define GEMM_MAINLOOP(Aptr, Bptr, Nn, Kk)                                      \
    const int NT = (Kk) >> 5;                                                  \
    auto LOAD = [&](int kt, int s) {                                           \
        uint32_t abase = smaddr + (uint32_t)(s * STG) * 4;                     \
        _Pragma("unroll")                                                      \
        for (int p = 0; p < 8; p++) {                                          \
            int id = tid + p * 128;                                            \
            int m = id >> 3, kc = (id & 7) << 2;                               \
            cp16(abase + (uint32_t)(m * ASTR + kc) * 4,                        \
                 (Aptr) + (size_t)(bm + m) * (Kk) + kt * 32 + kc);             \
        }                                                                      \
        uint32_t bbase = abase + AW * 4;                                       \
        _Pragma("unroll")                                                      \
        for (int p = 0; p < 8; p++) {                                          \
            int id = tid + p * 128;                                            \
            int k = id >> 5, nc = (id & 31) << 2;                              \
            cp16(bbase + (uint32_t)(k * BSTR + nc) * 4,                        \
                 (Bptr) + (size_t)(kt * 32 + k) * (Nn) + bn + nc);             \
        }                                                                      \
        CP_COMMIT();                                                           \
    };                                                                         \
    LOAD(0, 0); LOAD(1, 1);                                                    \
    int s_cur = 0, s_nxt = 2;                                                  \
    for (int kt = 0; kt < NT; kt++) {                                          \
        CP_WAIT(1);                                                            \
        __syncthreads();                                                       \
        if (kt + 2 < NT) LOAD(kt + 2, s_nxt);                                  \
        else CP_COMMIT();                                                      \
        const uint32_t* as = smg + s_cur * STG + (wm + gID) * ASTR;            \
        const uint32_t* bs = smg + s_cur * STG + AW + wn + gID;                \
        _Pragma("unroll")                                                      \
        for (int kk = 0; kk < 4; kk++) {                                       \
            const int k0 = kk * 8;                                             \
            uint32_t af[4][4], bf[8][2];                                       \
            _Pragma("unroll")                                                  \
            for (int mi = 0; mi < 4; mi++) {                                   \
                const uint32_t* ap = as + mi * 16 * ASTR + k0 + tig;           \
                af[mi][0] = ap[0];                                             \
                af[mi][1] = ap[8 * ASTR];                                      \
                af[mi][2] = ap[4];                                             \
                af[mi][3] = ap[8 * ASTR + 4];                                  \
            }                                                                  \
            _Pragma("unroll")                                                  \
            for (int ni = 0; ni < 8; ni++) {                                   \
                const uint32_t* bp = bs + (k0 + tig) * BSTR + ni * 8;          \
                bf[ni][0] = bp[0];                                             \
                bf[ni][1] = bp[4 * BSTR];                                      \
            }                                                                  \
            _Pragma("unroll")                                                  \
            for (int mi = 0; mi < 4; mi++)                                     \
                _Pragma("unroll")                                              \
                for (int ni = 0; ni < 8; ni++)                                 \
                    MMA_TF32(acc[mi][ni], af[mi][0], af[mi][1], af[mi][2],     \
                             af[mi][3], bf[ni][0], bf[ni][1]);                 \
        }                                                                      \
        s_cur = (s_cur == 2) ? 0 : s_cur + 1;                                  \
        s_nxt = (s_nxt == 2) ? 0 : s_nxt + 1;                                  \
    }

// ---------------------------------------------------------------------------
// Fused QKV projection: C = x @ [Wq|Wk|Wv], epilogue applies RoPE (Q,K) and
// writes tf32 bits to head-major Qr/Kr/Vr. Each 128-col N tile == one head.
// ---------------------------------------------------------------------------
__global__ __launch_bounds__(128, 2) void gemm_qkv(
    const uint32_t* __restrict__ A, const uint32_t* __restrict__ B,
    uint32_t* __restrict__ Qr, uint32_t* __restrict__ Kr,
    uint32_t* __restrict__ Vr)
{
    extern __shared__ uint32_t smg[];
    const uint32_t smaddr = (uint32_t)__cvta_generic_to_shared(smg);

    const int tid  = threadIdx.x;
    const int bm   = blockIdx.y * 128;
    const int bn   = blockIdx.x * 128;
    const int warp = tid >> 5, lane = tid & 31;
    const int wm   = (warp & 1) * 64;
    const int wn   = (warp >> 1) * 64;
    const int gID  = lane >> 2, tig = lane & 3;

    float acc[4][8][4];
#pragma unroll
    for (int i = 0; i < 4; i++)
#pragma unroll
        for (int j = 0; j < 8; j++)
#pragma unroll
            for (int l = 0; l < 4; l++) acc[i][j][l] = 0.f;

    GEMM_MAINLOOP(A, B, NQKV, DD)

    // ---- epilogue: stage fp32 tile in smem, rope+cvt, write head-major ----
    __syncthreads();
    uint32_t* Cs = smg;           // 128*132 = 16896 words < 3*8960
#pragma unroll
    for (int mi = 0; mi < 4; mi++) {
        const int r0 = wm + mi * 16 + gID;
#pragma unroll
        for (int ni = 0; ni < 8; ni++) {
            const int c = wn + ni * 8 + tig * 2;
            Cs[r0 * 132 + c]     = __float_as_uint(acc[mi][ni][0]);
            Cs[r0 * 132 + c + 1] = __float_as_uint(acc[mi][ni][1]);
            Cs[(r0 + 8) * 132 + c]     = __float_as_uint(acc[mi][ni][2]);
            Cs[(r0 + 8) * 132 + c + 1] = __float_as_uint(acc[mi][ni][3]);
        }
    }
    __syncthreads();

    uint32_t* dst;
    int head, hs, doRope;
    if (bn < 2048)      { head = bn >> 7;          dst = Qr; hs = NH;  doRope = 1; }
    else if (bn < 2560) { head = (bn - 2048) >> 7; dst = Kr; hs = NKV; doRope = 1; }
    else                { head = (bn - 2560) >> 7; dst = Vr; hs = NKV; doRope = 0; }

#pragma unroll 4
    for (int p = 0; p < 32; p++) {
        int idx = tid + p * 128;
        int r = idx >> 5;
        int d2 = (idx & 31) << 1;       // even d pair base: 0..62
        int bt = bm + r;
        int bb = bt >> 10;
        int t  = bt & (TT - 1);
        float lo0 = __uint_as_float(Cs[r * 132 + d2]);
        float lo1 = __uint_as_float(Cs[r * 132 + d2 + 1]);
        float hi0 = __uint_as_float(Cs[r * 132 + d2 + 64]);
        float hi1 = __uint_as_float(Cs[r * 132 + d2 + 65]);
        float c0 = 1.f, c1 = 1.f, s0 = 0.f, s1 = 0.f;
        if (doRope) {
            float2 cc = *(const float2*)(g_cos + t * 64 + d2);
            float2 ss = *(const float2*)(g_sin + t * 64 + d2);
            c0 = cc.x; c1 = cc.y; s0 = ss.x; s1 = ss.y;
        }
        uint32_t* o = dst + ((size_t)(bb * hs + head) * TT + t) * HD;
        uint2 olo, ohi;
        olo.x = f2tf32(lo0 * c0 - hi0 * s0);
        olo.y = f2tf32(lo1 * c1 - hi1 * s1);
        ohi.x = f2tf32(hi0 * c0 + lo0 * s0);
        ohi.y = f2tf32(hi1 * c1 + lo1 * s1);
        *(uint2*)(o + d2)      = olo;
        *(uint2*)(o + d2 + 64) = ohi;
    }
}

// ---------------------------------------------------------------------------
// Generic GEMM (Wo projection): C fp32 = A(tf32 bits) @ B(tf32 bits)
// ---------------------------------------------------------------------------
__global__ __launch_bounds__(128, 2) void gemm_pre(
    const uint32_t* __restrict__ A, const uint32_t* __restrict__ B,
    float* __restrict__ C, int M, int N, int K)
{
    extern __shared__ uint32_t smg[];
    const uint32_t smaddr = (uint32_t)__cvta_generic_to_shared(smg);

    const int tid  = threadIdx.x;
    const int bm   = blockIdx.y * 128;
    const int bn   = blockIdx.x * 128;
    const int warp = tid >> 5, lane = tid & 31;
    const int wm   = (warp & 1) * 64;
    const int wn   = (warp >> 1) * 64;
    const int gID  = lane >> 2, tig = lane & 3;

    float acc[4][8][4];
#pragma unroll
    for (int i = 0; i < 4; i++)
#pragma unroll
        for (int j = 0; j < 8; j++)
#pragma unroll
            for (int l = 0; l < 4; l++) acc[i][j][l] = 0.f;

    GEMM_MAINLOOP(A, B, N, K)

#pragma unroll
    for (int mi = 0; mi < 4; mi++) {
        const int r0 = bm + wm + mi * 16 + gID;
#pragma unroll
        for (int ni = 0; ni < 8; ni++) {
            const int c = bn + wn + ni * 8 + tig * 2;
            *(float2*)&C[(size_t)r0 * N + c] =
                make_float2(acc[mi][ni][0], acc[mi][ni][1]);
            *(float2*)&C[(size_t)(r0 + 8) * N + c] =
                make_float2(acc[mi][ni][2], acc[mi][ni][3]);
        }
    }
}

// ---------------------------------------------------------------------------
// Prep kernels
// ---------------------------------------------------------------------------
__global__ void cvt_kernel(const float* __restrict__ in,
                           uint32_t* __restrict__ out)
{
    int i = (blockIdx.x * 256 + threadIdx.x) * 4;
    float4 v = *(const float4*)(in + i);
    uint4 o;
    o.x = f2tf32(v.x); o.y = f2tf32(v.y);
    o.z = f2tf32(v.z); o.w = f2tf32(v.w);
    *(uint4*)(out + i) = o;
}

__global__ void pack_w_kernel(const float* __restrict__ Wq,
                              const float* __restrict__ Wk,
                              const float* __restrict__ Wv,
                              uint32_t* __restrict__ W)
{
    int idx = (blockIdx.x * 256 + threadIdx.x) * 4;
    int r = idx / NQKV, c = idx - r * NQKV;
    const float* src;
    if (c < 2048)      src = Wq + (size_t)r * 2048 + c;
    else if (c < 2560) src = Wk + (size_t)r * 512 + (c - 2048);
    else               src = Wv + (size_t)r * 512 + (c - 2560);
    float4 v = *(const float4*)src;
    uint4 o;
    o.x = f2tf32(v.x); o.y = f2tf32(v.y);
    o.z = f2tf32(v.z); o.w = f2tf32(v.w);
    *(uint4*)(W + idx) = o;
}

__global__ void rope_table_kernel()
{
    int t = blockIdx.x;
    int i = threadIdx.x;
    float inv = powf(10000.0f, -(float)i / 64.0f);
    float ang = (float)t * inv;
    g_cos[t * 64 + i] = cosf(ang);
    g_sin[t * 64 + i] = sinf(ang);
}

// ---------------------------------------------------------------------------
// Tensor-core flash attention, causal, GQA. Inputs pre-roped tf32 head-major.
// cp.async pipelined: K single-buffered (prefetch after S), V double-buffered.
// ---------------------------------------------------------------------------
#define AQ_STR 132
#define AK_STR 132
#define AV_STR 136
#define AP_STR 68
// Qs 128*132 + Ks 64*132 + Vs 2*64*136 + Ps 128*68 = 51456 words
#define ATTN_SMEM (51456 * 4)

__global__ __launch_bounds__(256, 1) void attn_tc(
    const uint32_t* __restrict__ Qr, const uint32_t* __restrict__ Kr,
    const uint32_t* __restrict__ Vr, uint32_t* __restrict__ Y)
{
    extern __shared__ uint32_t sma[];
    uint32_t* Qs  = sma;
    uint32_t* Ks  = Qs + 128 * AQ_STR;
    uint32_t* Vsb = Ks + 64 * AK_STR;          // [2][64*AV_STR]
    uint32_t* Ps  = Vsb + 2 * 64 * AV_STR;
    const uint32_t smaddr = (uint32_t)__cvta_generic_to_shared(sma);
    const uint32_t Qs_a = smaddr;
    const uint32_t Ks_a = Qs_a + 128 * AQ_STR * 4;
    const uint32_t Vs_a = Ks_a + 64 * AK_STR * 4;

    const int tid  = threadIdx.x;
    const int warp = tid >> 5, lane = tid & 31;
    const int gID  = lane >> 2, tig = lane & 3;
    const int qt   = (gridDim.x - 1) - blockIdx.x;   // heavy first
    const int hh   = blockIdx.y;
    const int b    = blockIdx.z;
    const int gkv  = hh >> 2;
    const int q0   = qt * 128;
    const int wm   = warp * 16;
    const int row0 = q0 + wm + gID;

    const uint32_t* Qbase = Qr + ((size_t)(b * NH + hh) * TT + q0) * HD;
    const uint32_t* Kbase = Kr + (size_t)(b * NKV + gkv) * TT * HD;
    const uint32_t* Vbase = Vr + (size_t)(b * NKV + gkv) * TT * HD;

    auto LOADQ = [&]() {
#pragma unroll
        for (int p = 0; p < 16; p++) {
            int id = tid + p * 256;
            int q = id >> 5, c = (id & 31) << 2;
            cp16(Qs_a + (uint32_t)(q * AQ_STR + c) * 4, Qbase + q * HD + c);
        }
    };
    auto LOADK = [&](int st) {
        const uint32_t* src = Kbase + (size_t)st * 64 * HD;
#pragma unroll
        for (int p = 0; p < 8; p++) {
            int id = tid + p * 256;
            int s = id >> 5, c = (id & 31) << 2;
            cp16(Ks_a + (uint32_t)(s * AK_STR + c) * 4, src + s * HD + c);
        }
    };
    auto LOADV = [&](int st) {
        const uint32_t* src = Vbase + (size_t)st * 64 * HD;
        uint32_t dbase = Vs_a + (uint32_t)((st & 1) * 64 * AV_STR) * 4;
#pragma unroll
        for (int p = 0; p < 8; p++) {
            int id = tid + p * 256;
            int s = id >> 5, c = (id & 31) << 2;
            cp16(dbase + (uint32_t)(s * AV_STR + c) * 4, src + s * HD + c);
        }
    };

    const int ntiles = 2 * qt + 2;

    LOADQ(); LOADK(0); LOADV(0); CP_COMMIT();   // C0
    LOADV(1); CP_COMMIT();                      // C1 (tile 1 always exists)

    float m0 = -1e30f, m1 = -1e30f, l0 = 0.f, l1 = 0.f;
    float oacc[16][4];
#pragma unroll
    for (int i = 0; i < 16; i++)
#pragma unroll
        for (int j = 0; j < 4; j++) oacc[i][j] = 0.f;

    const float scale = 0.08838834764831845f;   // 1/sqrt(128)

    for (int st = 0; st < ntiles; st++) {
        const int s0 = st * 64;
        const bool active = (q0 + wm + 15 >= s0);

        CP_WAIT(1);          // K(st), V(st), (and Q on st=0) ready
        __syncthreads();

        float sacc[8][4];
        if (active) {
#pragma unroll
            for (int i = 0; i < 8; i++)
#pragma unroll
                for (int j = 0; j < 4; j++) sacc[i][j] = 0.f;

            const uint32_t* qrow = Qs + (wm + gID) * AQ_STR;
#pragma unroll
            for (int kk = 0; kk < 16; kk++) {
                const int k0 = kk * 8;
                uint32_t a0 = qrow[k0 + tig];
                uint32_t a1 = qrow[8 * AQ_STR + k0 + tig];
                uint32_t a2 = qrow[k0 + tig + 4];
                uint32_t a3 = qrow[8 * AQ_STR + k0 + tig + 4];
#pragma unroll
                for (int ni = 0; ni < 8; ni++) {
                    const uint32_t* kp2 = Ks + (gID + ni * 8) * AK_STR + k0 + tig;
                    MMA_TF32(sacc[ni], a0, a1, a2, a3, kp2[0], kp2[4]);
                }
            }
        }
        __syncthreads();     // all warps done reading Ks

        if (st + 1 < ntiles) LOADK(st + 1);
        CP_COMMIT();

        if (active) {
            const int lim0 = row0 - s0;
            const int lim1 = lim0 + 8;
            const bool diag = (st >= 2 * qt);
            float mx0 = -1e30f, mx1 = -1e30f;
#pragma unroll
            for (int ni = 0; ni < 8; ni++) {
#pragma unroll
                for (int c = 0; c < 2; c++) {
                    int j = ni * 8 + tig * 2 + c;
                    float v0 = sacc[ni][c] * scale;
                    float v1 = sacc[ni][2 + c] * scale;
                    if (diag) {
                        if (j > lim0) v0 = -1e30f;
                        if (j > lim1) v1 = -1e30f;
                    }
                    sacc[ni][c]     = v0;
                    sacc[ni][2 + c] = v1;
                    mx0 = fmaxf(mx0, v0);
                    mx1 = fmaxf(mx1, v1);
                }
            }
            mx0 = fmaxf(mx0, __shfl_xor_sync(0xffffffffu, mx0, 1));
            mx0 = fmaxf(mx0, __shfl_xor_sync(0xffffffffu, mx0, 2));
            mx1 = fmaxf(mx1, __shfl_xor_sync(0xffffffffu, mx1, 1));
            mx1 = fmaxf(mx1, __shfl_xor_sync(0xffffffffu, mx1, 2));
            float mn0 = fmaxf(m0, mx0), mn1 = fmaxf(m1, mx1);
            float cr0 = __expf(m0 - mn0), cr1 = __expf(m1 - mn1);
            float sum0 = 0.f, sum1 = 0.f;
#pragma unroll
            for (int ni = 0; ni < 8; ni++) {
#pragma unroll
                for (int c = 0; c < 2; c++) {
                    float p0 = __expf(sacc[ni][c] - mn0);
                    float p1 = __expf(sacc[ni][2 + c] - mn1);
                    sacc[ni][c]     = p0;
                    sacc[ni][2 + c] = p1;
                    sum0 += p0;
                    sum1 += p1;
                }
            }
            sum0 += __shfl_xor_sync(0xffffffffu, sum0, 1);
            sum0 += __shfl_xor_sync(0xffffffffu, sum0, 2);
            sum1 += __shfl_xor_sync(0xffffffffu, sum1, 1);
            sum1 += __shfl_xor_sync(0xffffffffu, sum1, 2);
            l0 = l0 * cr0 + sum0;
            l1 = l1 * cr1 + sum1;
            m0 = mn0; m1 = mn1;

#pragma unroll
            for (int ni = 0; ni < 16; ni++) {
                oacc[ni][0] *= cr0; oacc[ni][1] *= cr0;
                oacc[ni][2] *= cr1; oacc[ni][3] *= cr1;
            }

            uint32_t* pr0 = Ps + (wm + gID) * AP_STR;
            uint32_t* pr1 = pr0 + 8 * AP_STR;
#pragma unroll
            for (int ni = 0; ni < 8; ni++) {
                int c = ni * 8 + tig * 2;
                pr0[c]     = f2tf32(sacc[ni][0]);
                pr0[c + 1] = f2tf32(sacc[ni][1]);
                pr1[c]     = f2tf32(sacc[ni][2]);
                pr1[c + 1] = f2tf32(sacc[ni][3]);
            }
            __syncwarp();

            const uint32_t* vbuf = Vsb + (st & 1) * 64 * AV_STR;
            const uint32_t* prow = Ps + (wm + gID) * AP_STR;
#pragma unroll
            for (int kk = 0; kk < 8; kk++) {
                const int k0 = kk * 8;
                uint32_t a0 = prow[k0 + tig];
                uint32_t a1 = prow[8 * AP_STR + k0 + tig];
                uint32_t a2 = prow[k0 + tig + 4];
                uint32_t a3 = prow[8 * AP_STR + k0 + tig + 4];
#pragma unroll
                for (int ni = 0; ni < 16; ni++) {
                    const uint32_t* vp2 = vbuf + (k0 + tig) * AV_STR + gID + ni * 8;
                    MMA_TF32(oacc[ni], a0, a1, a2, a3, vp2[0], vp2[4 * AV_STR]);
                }
            }
        }
        __syncthreads();     // PV done -> V(st) buffer free

        if (st + 2 < ntiles) LOADV(st + 2);
        CP_COMMIT();
    }

    float li0 = 1.f / l0, li1 = 1.f / l1;
    uint32_t* y0 = Y + (size_t)(b * TT + row0) * DD + hh * HD;
    uint32_t* y1 = y0 + (size_t)8 * DD;
#pragma unroll
    for (int ni = 0; ni < 16; ni++) {
        int c = ni * 8 + tig * 2;
        uint2 o0, o1;
        o0.x = f2tf32(oacc[ni][0] * li0); o0.y = f2tf32(oacc[ni][1] * li0);
        o1.x = f2tf32(oacc[ni][2] * li1); o1.y = f2tf32(oacc[ni][3] * li1);
        *(uint2*)(y0 + c) = o0;
        *(uint2*)(y1 + c) = o1;
    }
}

// ---------------------------------------------------------------------------
extern "C" void kernel_launch(void* const* d_in, const int* in_sizes, int n_in,
                              void* d_out, int out_size)
{
    const float* x  = (const float*)d_in[0];
    const float* Wq = (const float*)d_in[1];
    const float* Wk = (const float*)d_in[2];
    const float* Wv = (const float*)d_in[3];
    const float* Wo = (const float*)d_in[4];
    float* out = (float*)d_out;

    uint32_t *xT, *Wqkv, *WoT, *Qr, *Kr, *Vr, *Yp;
    cudaGetSymbolAddress((void**)&xT,   g_xT);
    cudaGetSymbolAddress((void**)&Wqkv, g_Wqkv);
    cudaGetSymbolAddress((void**)&WoT,  g_WoT);
    cudaGetSymbolAddress((void**)&Qr,   g_Qr);
    cudaGetSymbolAddress((void**)&Kr,   g_Kr);
    cudaGetSymbolAddress((void**)&Vr,   g_Vr);
    cudaGetSymbolAddress((void**)&Yp,   g_Y);

    static bool attr_set = false;
    if (!attr_set) {
        cudaFuncSetAttribute(gemm_qkv,
                             cudaFuncAttributeMaxDynamicSharedMemorySize,
                             GEMM_SMEM);
        cudaFuncSetAttribute(gemm_pre,
                             cudaFuncAttributeMaxDynamicSharedMemorySize,
                             GEMM_SMEM);
        cudaFuncSetAttribute(attn_tc,
                             cudaFuncAttributeMaxDynamicSharedMemorySize,
                             ATTN_SMEM);
        attr_set = true;
    }

    rope_table_kernel<<<TT, 64>>>();
    cvt_kernel<<<(MROWS * DD) / 1024, 256>>>(x, xT);
    pack_w_kernel<<<(DD * NQKV) / 1024, 256>>>(Wq, Wk, Wv, Wqkv);
    cvt_kernel<<<(DD * DD) / 1024, 256>>>(Wo, WoT);

    // Fused Q|K|V projection + RoPE + head-major tf32 scatter
    gemm_qkv<<<dim3(NQKV / 128, MROWS / 128), 128, GEMM_SMEM>>>(
        xT, Wqkv, Qr, Kr, Vr);

    attn_tc<<<dim3(TT / 128, NH, BB), 256, ATTN_SMEM>>>(Qr, Kr, Vr, Yp);

    // Output projection
    gemm_pre<<<dim3(DD / 128, MROWS / 128), 128, GEMM_SMEM>>>(
        Yp, WoT, out, MROWS, DD, DD);
}

// round 9
// speedup vs baseline: 9.3178x; 1.2970x over previous
#include <cuda_runtime.h>
#include <cuda_fp16.h>
#include <math.h>
#include <stdint.h>

#define BB 4
#define TT 1024
#define DD 2048
#define NH 16
#define NKV 4
#define HD 128
#define MROWS (BB*TT)    // 4096
#define NQKV 3072

// Scratch (device globals; no runtime allocation)
__device__ __half   g_xh[MROWS * DD];          // x fp16 [4096][2048] row-major
__device__ __half   g_Wqkvh[NQKV * DD];        // [Wq|Wk|Wv]^T fp16 [3072][2048]
__device__ __half   g_Woh[DD * DD];            // Wo^T fp16 [2048][2048]
__device__ uint32_t g_Qr[BB * NH * TT * HD];   // roped Q tf32 [b][h][t][d]
__device__ uint32_t g_Kr[BB * NKV * TT * HD];  // roped K tf32
__device__ uint32_t g_Vr[BB * NKV * TT * HD];  // V tf32
__device__ uint32_t g_Y[MROWS * DD];           // attention out (tf32 bits)
__device__ float    g_cos[TT * 64];
__device__ float    g_sin[TT * 64];

__device__ __forceinline__ uint32_t f2tf32(float f) {
    uint32_t r;
    asm("cvt.rna.tf32.f32 %0, %1;" : "=r"(r) : "f"(f));
    return r;
}

#define MMA_TF32(ACC, A0, A1, A2, A3, B0, B1)                                  \
    asm volatile(                                                              \
        "mma.sync.aligned.m16n8k8.row.col.f32.tf32.tf32.f32 "                  \
        "{%0,%1,%2,%3}, {%4,%5,%6,%7}, {%8,%9}, {%0,%1,%2,%3};"                \
        : "+f"((ACC)[0]), "+f"((ACC)[1]), "+f"((ACC)[2]), "+f"((ACC)[3])       \
        : "r"(A0), "r"(A1), "r"(A2), "r"(A3), "r"(B0), "r"(B1))

#define MMA_F16(ACC, A0, A1, A2, A3, B0, B1)                                   \
    asm volatile(                                                              \
        "mma.sync.aligned.m16n8k16.row.col.f32.f16.f16.f32 "                   \
        "{%0,%1,%2,%3}, {%4,%5,%6,%7}, {%8,%9}, {%0,%1,%2,%3};"                \
        : "+f"((ACC)[0]), "+f"((ACC)[1]), "+f"((ACC)[2]), "+f"((ACC)[3])       \
        : "r"(A0), "r"(A1), "r"(A2), "r"(A3), "r"(B0), "r"(B1))

__device__ __forceinline__ void cp16(uint32_t dst, const void* src) {
    asm volatile("cp.async.cg.shared.global [%0], [%1], 16;" ::
                 "r"(dst), "l"(src));
}
#define CP_COMMIT() asm volatile("cp.async.commit_group;")
#define CP_WAIT(n)  asm volatile("cp.async.wait_group %0;" :: "n"(n) : "memory")

// ---------------------------------------------------------------------------
// FP16 GEMM: C = A[half, M x 2048 row-major] @ B^T[half, N x 2048 n-major].
// CTA 128x128, 128 threads (4 warps, 2Mx2N, warp 64x64), KT=32, 4 stages.
// smem row stride 20 u32 (16 data + 4 pad) -> conflict-free fragment LDS.
// ---------------------------------------------------------------------------
#define HSTR 20                   // u32 per row
#define HAW  (128*HSTR)           // 2560 u32 per A (or B) stage
#define HSTG (2*HAW)              // 5120 u32 per stage
#define GEMM_SMEM (4*HSTG*4)      // 81920 B

#define GEMM_MAINLOOP_H(Aptr, Bptr)                                            \
    auto LOAD = [&](int kt, int s) {                                           \
        uint32_t abase = smaddr + (uint32_t)(s * HSTG) * 4;                    \
        _Pragma("unroll")                                                      \
        for (int p = 0; p < 4; p++) {                                          \
            int id = tid + p * 128;                                            \
            int row = id >> 2, ch = id & 3;                                    \
            cp16(abase + (uint32_t)(row * 80 + ch * 16),                       \
                 (Aptr) + (size_t)(bm + row) * DD + kt * 32 + ch * 8);         \
        }                                                                      \
        uint32_t bbase = abase + HAW * 4;                                      \
        _Pragma("unroll")                                                      \
        for (int p = 0; p < 4; p++) {                                          \
            int id = tid + p * 128;                                            \
            int row = id >> 2, ch = id & 3;                                    \
            cp16(bbase + (uint32_t)(row * 80 + ch * 16),                       \
                 (Bptr) + (size_t)(bn + row) * DD + kt * 32 + ch * 8);         \
        }                                                                      \
        CP_COMMIT();                                                           \
    };                                                                         \
    LOAD(0, 0); LOAD(1, 1); LOAD(2, 2);                                        \
    for (int kt = 0; kt < 64; kt++) {                                          \
        CP_WAIT(2);                                                            \
        __syncthreads();                                                       \
        if (kt + 3 < 64) LOAD(kt + 3, (kt + 3) & 3);                           \
        else CP_COMMIT();                                                      \
        const uint32_t* as = smg + (kt & 3) * HSTG + (wm + gID) * HSTR;        \
        const uint32_t* bs = smg + (kt & 3) * HSTG + HAW + (wn + gID) * HSTR;  \
        _Pragma("unroll")                                                      \
        for (int kk = 0; kk < 2; kk++) {                                       \
            const int k0 = kk * 8;                                             \
            uint32_t af[4][4], bf[8][2];                                       \
            _Pragma("unroll")                                                  \
            for (int mi = 0; mi < 4; mi++) {                                   \
                const uint32_t* ap = as + mi * 16 * HSTR + k0 + tig;           \
                af[mi][0] = ap[0];                                             \
                af[mi][1] = ap[8 * HSTR];                                      \
                af[mi][2] = ap[4];                                             \
                af[mi][3] = ap[8 * HSTR + 4];                                  \
            }                                                                  \
            _Pragma("unroll")                                                  \
            for (int ni = 0; ni < 8; ni++) {                                   \
                const uint32_t* bp = bs + ni * 8 * HSTR + k0 + tig;            \
                bf[ni][0] = bp[0];                                             \
                bf[ni][1] = bp[4];                                             \
            }                                                                  \
            _Pragma("unroll")                                                  \
            for (int mi = 0; mi < 4; mi++)                                     \
                _Pragma("unroll")                                              \
                for (int ni = 0; ni < 8; ni++)                                 \
                    MMA_F16(acc[mi][ni], af[mi][0], af[mi][1], af[mi][2],      \
                            af[mi][3], bf[ni][0], bf[ni][1]);                  \
        }                                                                      \
    }

// ---------------------------------------------------------------------------
// Fused QKV projection (fp16) + RoPE epilogue -> head-major tf32 Qr/Kr/Vr.
// ---------------------------------------------------------------------------
__global__ __launch_bounds__(128, 2) void gemm_qkv_h(
    const __half* __restrict__ A, const __half* __restrict__ B,
    uint32_t* __restrict__ Qr, uint32_t* __restrict__ Kr,
    uint32_t* __restrict__ Vr)
{
    extern __shared__ uint32_t smg[];
    const uint32_t smaddr = (uint32_t)__cvta_generic_to_shared(smg);

    const int tid  = threadIdx.x;
    const int bm   = blockIdx.y * 128;
    const int bn   = blockIdx.x * 128;
    const int warp = tid >> 5, lane = tid & 31;
    const int wm   = (warp & 1) * 64;
    const int wn   = (warp >> 1) * 64;
    const int gID  = lane >> 2, tig = lane & 3;

    float acc[4][8][4];
#pragma unroll
    for (int i = 0; i < 4; i++)
#pragma unroll
        for (int j = 0; j < 8; j++)
#pragma unroll
            for (int l = 0; l < 4; l++) acc[i][j][l] = 0.f;

    GEMM_MAINLOOP_H(A, B)

    // ---- epilogue: stage fp32 tile in smem, rope+cvt, write head-major ----
    __syncthreads();
    uint32_t* Cs = smg;           // 128*132 = 16896 u32 < 4*5120
#pragma unroll
    for (int mi = 0; mi < 4; mi++) {
        const int r0 = wm + mi * 16 + gID;
#pragma unroll
        for (int ni = 0; ni < 8; ni++) {
            const int c = wn + ni * 8 + tig * 2;
            Cs[r0 * 132 + c]     = __float_as_uint(acc[mi][ni][0]);
            Cs[r0 * 132 + c + 1] = __float_as_uint(acc[mi][ni][1]);
            Cs[(r0 + 8) * 132 + c]     = __float_as_uint(acc[mi][ni][2]);
            Cs[(r0 + 8) * 132 + c + 1] = __float_as_uint(acc[mi][ni][3]);
        }
    }
    __syncthreads();

    uint32_t* dst;
    int head, hs, doRope;
    if (bn < 2048)      { head = bn >> 7;          dst = Qr; hs = NH;  doRope = 1; }
    else if (bn < 2560) { head = (bn - 2048) >> 7; dst = Kr; hs = NKV; doRope = 1; }
    else                { head = (bn - 2560) >> 7; dst = Vr; hs = NKV; doRope = 0; }

#pragma unroll 4
    for (int p = 0; p < 32; p++) {
        int idx = tid + p * 128;
        int r = idx >> 5;
        int d2 = (idx & 31) << 1;
        int bt = bm + r;
        int bb = bt >> 10;
        int t  = bt & (TT - 1);
        float lo0 = __uint_as_float(Cs[r * 132 + d2]);
        float lo1 = __uint_as_float(Cs[r * 132 + d2 + 1]);
        float hi0 = __uint_as_float(Cs[r * 132 + d2 + 64]);
        float hi1 = __uint_as_float(Cs[r * 132 + d2 + 65]);
        float c0 = 1.f, c1 = 1.f, s0 = 0.f, s1 = 0.f;
        if (doRope) {
            float2 cc = *(const float2*)(g_cos + t * 64 + d2);
            float2 ss = *(const float2*)(g_sin + t * 64 + d2);
            c0 = cc.x; c1 = cc.y; s0 = ss.x; s1 = ss.y;
        }
        uint32_t* o = dst + ((size_t)(bb * hs + head) * TT + t) * HD;
        uint2 olo, ohi;
        olo.x = f2tf32(lo0 * c0 - hi0 * s0);
        olo.y = f2tf32(lo1 * c1 - hi1 * s1);
        ohi.x = f2tf32(hi0 * c0 + lo0 * s0);
        ohi.y = f2tf32(hi1 * c1 + lo1 * s1);
        *(uint2*)(o + d2)      = olo;
        *(uint2*)(o + d2 + 64) = ohi;
    }
}

// ---------------------------------------------------------------------------
// Wo projection (fp16): out fp32 = Y(half) @ Woh^T-tile
// ---------------------------------------------------------------------------
__global__ __launch_bounds__(128, 2) void gemm_wo_h(
    const __half* __restrict__ A, const __half* __restrict__ B,
    float* __restrict__ C)
{
    extern __shared__ uint32_t smg[];
    const uint32_t smaddr = (uint32_t)__cvta_generic_to_shared(smg);

    const int tid  = threadIdx.x;
    const int bm   = blockIdx.y * 128;
    const int bn   = blockIdx.x * 128;
    const int warp = tid >> 5, lane = tid & 31;
    const int wm   = (warp & 1) * 64;
    const int wn   = (warp >> 1) * 64;
    const int gID  = lane >> 2, tig = lane & 3;

    float acc[4][8][4];
#pragma unroll
    for (int i = 0; i < 4; i++)
#pragma unroll
        for (int j = 0; j < 8; j++)
#pragma unroll
            for (int l = 0; l < 4; l++) acc[i][j][l] = 0.f;

    GEMM_MAINLOOP_H(A, B)

#pragma unroll
    for (int mi = 0; mi < 4; mi++) {
        const int r0 = bm + wm + mi * 16 + gID;
#pragma unroll
        for (int ni = 0; ni < 8; ni++) {
            const int c = bn + wn + ni * 8 + tig * 2;
            *(float2*)&C[(size_t)r0 * DD + c] =
                make_float2(acc[mi][ni][0], acc[mi][ni][1]);
            *(float2*)&C[(size_t)(r0 + 8) * DD + c] =
                make_float2(acc[mi][ni][2], acc[mi][ni][3]);
        }
    }
}

// ---------------------------------------------------------------------------
// Prep kernels
// ---------------------------------------------------------------------------
__global__ void cvt_h(const float* __restrict__ in, __half* __restrict__ out)
{
    int i = (blockIdx.x * 256 + threadIdx.x) * 4;
    float4 v = *(const float4*)(in + i);
    __half2 h0 = __floats2half2_rn(v.x, v.y);
    __half2 h1 = __floats2half2_rn(v.z, v.w);
    *(__half2*)(out + i)     = h0;
    *(__half2*)(out + i + 2) = h1;
}

// Y tf32 bits -> half (for Wo GEMM A operand)
__global__ void cvt_u2h(const uint32_t* __restrict__ in, __half* __restrict__ out)
{
    int i = (blockIdx.x * 256 + threadIdx.x) * 4;
    uint4 v = *(const uint4*)(in + i);
    __half2 h0 = __floats2half2_rn(__uint_as_float(v.x), __uint_as_float(v.y));
    __half2 h1 = __floats2half2_rn(__uint_as_float(v.z), __uint_as_float(v.w));
    *(__half2*)(out + i)     = h0;
    *(__half2*)(out + i + 2) = h1;
}

// dst[(row_off + col)*2048 + row] = half(src[row*C + col]); src rows = 2048.
__global__ void tr_cvt_h(const float* __restrict__ src, __half* __restrict__ dst,
                         int C, int row_off)
{
    __shared__ float tile[32][33];
    int bx = blockIdx.x * 32;
    int by = blockIdx.y * 32;
    int x = threadIdx.x, y = threadIdx.y;   // 32 x 8
#pragma unroll
    for (int j = 0; j < 32; j += 8)
        tile[y + j][x] = src[(size_t)(by + y + j) * C + bx + x];
    __syncthreads();
#pragma unroll
    for (int j = 0; j < 32; j += 8)
        dst[(size_t)(row_off + bx + y + j) * 2048 + by + x] =
            __float2half(tile[x][y + j]);
}

__global__ void rope_table_kernel()
{
    int t = blockIdx.x;
    int i = threadIdx.x;
    float inv = powf(10000.0f, -(float)i / 64.0f);
    float ang = (float)t * inv;
    g_cos[t * 64 + i] = cosf(ang);
    g_sin[t * 64 + i] = sinf(ang);
}

// ---------------------------------------------------------------------------
// Tensor-core flash attention (tf32, unchanged from round 7)
// ---------------------------------------------------------------------------
#define AQ_STR 132
#define AK_STR 132
#define AV_STR 136
#define AP_STR 68
#define ATTN_SMEM (51456 * 4)

__global__ __launch_bounds__(256, 1) void attn_tc(
    const uint32_t* __restrict__ Qr, const uint32_t* __restrict__ Kr,
    const uint32_t* __restrict__ Vr, uint32_t* __restrict__ Y)
{
    extern __shared__ uint32_t sma[];
    uint32_t* Qs  = sma;
    uint32_t* Ks  = Qs + 128 * AQ_STR;
    uint32_t* Vsb = Ks + 64 * AK_STR;
    uint32_t* Ps  = Vsb + 2 * 64 * AV_STR;
    const uint32_t smaddr = (uint32_t)__cvta_generic_to_shared(sma);
    const uint32_t Qs_a = smaddr;
    const uint32_t Ks_a = Qs_a + 128 * AQ_STR * 4;
    const uint32_t Vs_a = Ks_a + 64 * AK_STR * 4;

    const int tid  = threadIdx.x;
    const int warp = tid >> 5, lane = tid & 31;
    const int gID  = lane >> 2, tig = lane & 3;
    const int qt   = (gridDim.x - 1) - blockIdx.x;
    const int hh   = blockIdx.y;
    const int b    = blockIdx.z;
    const int gkv  = hh >> 2;
    const int q0   = qt * 128;
    const int wm   = warp * 16;
    const int row0 = q0 + wm + gID;

    const uint32_t* Qbase = Qr + ((size_t)(b * NH + hh) * TT + q0) * HD;
    const uint32_t* Kbase = Kr + (size_t)(b * NKV + gkv) * TT * HD;
    const uint32_t* Vbase = Vr + (size_t)(b * NKV + gkv) * TT * HD;

    auto LOADQ = [&]() {
#pragma unroll
        for (int p = 0; p < 16; p++) {
            int id = tid + p * 256;
            int q = id >> 5, c = (id & 31) << 2;
            cp16(Qs_a + (uint32_t)(q * AQ_STR + c) * 4, Qbase + q * HD + c);
        }
    };
    auto LOADK = [&](int st) {
        const uint32_t* src = Kbase + (size_t)st * 64 * HD;
#pragma unroll
        for (int p = 0; p < 8; p++) {
            int id = tid + p * 256;
            int s = id >> 5, c = (id & 31) << 2;
            cp16(Ks_a + (uint32_t)(s * AK_STR + c) * 4, src + s * HD + c);
        }
    };
    auto LOADV = [&](int st) {
        const uint32_t* src = Vbase + (size_t)st * 64 * HD;
        uint32_t dbase = Vs_a + (uint32_t)((st & 1) * 64 * AV_STR) * 4;
#pragma unroll
        for (int p = 0; p < 8; p++) {
            int id = tid + p * 256;
            int s = id >> 5, c = (id & 31) << 2;
            cp16(dbase + (uint32_t)(s * AV_STR + c) * 4, src + s * HD + c);
        }
    };

    const int ntiles = 2 * qt + 2;

    LOADQ(); LOADK(0); LOADV(0); CP_COMMIT();
    LOADV(1); CP_COMMIT();

    float m0 = -1e30f, m1 = -1e30f, l0 = 0.f, l1 = 0.f;
    float oacc[16][4];
#pragma unroll
    for (int i = 0; i < 16; i++)
#pragma unroll
        for (int j = 0; j < 4; j++) oacc[i][j] = 0.f;

    const float scale = 0.08838834764831845f;

    for (int st = 0; st < ntiles; st++) {
        const int s0 = st * 64;
        const bool active = (q0 + wm + 15 >= s0);

        CP_WAIT(1);
        __syncthreads();

        float sacc[8][4];
        if (active) {
#pragma unroll
            for (int i = 0; i < 8; i++)
#pragma unroll
                for (int j = 0; j < 4; j++) sacc[i][j] = 0.f;

            const uint32_t* qrow = Qs + (wm + gID) * AQ_STR;
#pragma unroll
            for (int kk = 0; kk < 16; kk++) {
                const int k0 = kk * 8;
                uint32_t a0 = qrow[k0 + tig];
                uint32_t a1 = qrow[8 * AQ_STR + k0 + tig];
                uint32_t a2 = qrow[k0 + tig + 4];
                uint32_t a3 = qrow[8 * AQ_STR + k0 + tig + 4];
#pragma unroll
                for (int ni = 0; ni < 8; ni++) {
                    const uint32_t* kp2 = Ks + (gID + ni * 8) * AK_STR + k0 + tig;
                    MMA_TF32(sacc[ni], a0, a1, a2, a3, kp2[0], kp2[4]);
                }
            }
        }
        __syncthreads();

        if (st + 1 < ntiles) LOADK(st + 1);
        CP_COMMIT();

        if (active) {
            const int lim0 = row0 - s0;
            const int lim1 = lim0 + 8;
            const bool diag = (st >= 2 * qt);
            float mx0 = -1e30f, mx1 = -1e30f;
#pragma unroll
            for (int ni = 0; ni < 8; ni++) {
#pragma unroll
                for (int c = 0; c < 2; c++) {
                    int j = ni * 8 + tig * 2 + c;
                    float v0 = sacc[ni][c] * scale;
                    float v1 = sacc[ni][2 + c] * scale;
                    if (diag) {
                        if (j > lim0) v0 = -1e30f;
                        if (j > lim1) v1 = -1e30f;
                    }
                    sacc[ni][c]     = v0;
                    sacc[ni][2 + c] = v1;
                    mx0 = fmaxf(mx0, v0);
                    mx1 = fmaxf(mx1, v1);
                }
            }
            mx0 = fmaxf(mx0, __shfl_xor_sync(0xffffffffu, mx0, 1));
            mx0 = fmaxf(mx0, __shfl_xor_sync(0xffffffffu, mx0, 2));
            mx1 = fmaxf(mx1, __shfl_xor_sync(0xffffffffu, mx1, 1));
            mx1 = fmaxf(mx1, __shfl_xor_sync(0xffffffffu, mx1, 2));
            float mn0 = fmaxf(m0, mx0), mn1 = fmaxf(m1, mx1);
            float cr0 = __expf(m0 - mn0), cr1 = __expf(m1 - mn1);
            float sum0 = 0.f, sum1 = 0.f;
#pragma unroll
            for (int ni = 0; ni < 8; ni++) {
#pragma unroll
                for (int c = 0; c < 2; c++) {
                    float p0 = __expf(sacc[ni][c] - mn0);
                    float p1 = __expf(sacc[ni][2 + c] - mn1);
                    sacc[ni][c]     = p0;
                    sacc[ni][2 + c] = p1;
                    sum0 += p0;
                    sum1 += p1;
                }
            }
            sum0 += __shfl_xor_sync(0xffffffffu, sum0, 1);
            sum0 += __shfl_xor_sync(0xffffffffu, sum0, 2);
            sum1 += __shfl_xor_sync(0xffffffffu, sum1, 1);
            sum1 += __shfl_xor_sync(0xffffffffu, sum1, 2);
            l0 = l0 * cr0 + sum0;
            l1 = l1 * cr1 + sum1;
            m0 = mn0; m1 = mn1;

#pragma unroll
            for (int ni = 0; ni < 16; ni++) {
                oacc[ni][0] *= cr0; oacc[ni][1] *= cr0;
                oacc[ni][2] *= cr1; oacc[ni][3] *= cr1;
            }

            uint32_t* pr0 = Ps + (wm + gID) * AP_STR;
            uint32_t* pr1 = pr0 + 8 * AP_STR;
#pragma unroll
            for (int ni = 0; ni < 8; ni++) {
                int c = ni * 8 + tig * 2;
                pr0[c]     = f2tf32(sacc[ni][0]);
                pr0[c + 1] = f2tf32(sacc[ni][1]);
                pr1[c]     = f2tf32(sacc[ni][2]);
                pr1[c + 1] = f2tf32(sacc[ni][3]);
            }
            __syncwarp();

            const uint32_t* vbuf = Vsb + (st & 1) * 64 * AV_STR;
            const uint32_t* prow = Ps + (wm + gID) * AP_STR;
#pragma unroll
            for (int kk = 0; kk < 8; kk++) {
                const int k0 = kk * 8;
                uint32_t a0 = prow[k0 + tig];
                uint32_t a1 = prow[8 * AP_STR + k0 + tig];
                uint32_t a2 = prow[k0 + tig + 4];
                uint32_t a3 = prow[8 * AP_STR + k0 + tig + 4];
#pragma unroll
                for (int ni = 0; ni < 16; ni++) {
                    const uint32_t* vp2 = vbuf + (k0 + tig) * AV_STR + gID + ni * 8;
                    MMA_TF32(oacc[ni], a0, a1, a2, a3, vp2[0], vp2[4 * AV_STR]);
                }
            }
        }
        __syncthreads();

        if (st + 2 < ntiles) LOADV(st + 2);
        CP_COMMIT();
    }

    float li0 = 1.f / l0, li1 = 1.f / l1;
    uint32_t* y0 = Y + (size_t)(b * TT + row0) * DD + hh * HD;
    uint32_t* y1 = y0 + (size_t)8 * DD;
#pragma unroll
    for (int ni = 0; ni < 16; ni++) {
        int c = ni * 8 + tig * 2;
        uint2 o0, o1;
        o0.x = f2tf32(oacc[ni][0] * li0); o0.y = f2tf32(oacc[ni][1] * li0);
        o1.x = f2tf32(oacc[ni][2] * li1); o1.y = f2tf32(oacc[ni][3] * li1);
        *(uint2*)(y0 + c) = o0;
        *(uint2*)(y1 + c) = o1;
    }
}

// ---------------------------------------------------------------------------
extern "C" void kernel_launch(void* const* d_in, const int* in_sizes, int n_in,
                              void* d_out, int out_size)
{
    const float* x  = (const float*)d_in[0];
    const float* Wq = (const float*)d_in[1];
    const float* Wk = (const float*)d_in[2];
    const float* Wv = (const float*)d_in[3];
    const float* Wo = (const float*)d_in[4];
    float* out = (float*)d_out;

    __half *xh, *Wqkvh, *Woh;
    uint32_t *Qr, *Kr, *Vr, *Yp;
    cudaGetSymbolAddress((void**)&xh,    g_xh);
    cudaGetSymbolAddress((void**)&Wqkvh, g_Wqkvh);
    cudaGetSymbolAddress((void**)&Woh,   g_Woh);
    cudaGetSymbolAddress((void**)&Qr,    g_Qr);
    cudaGetSymbolAddress((void**)&Kr,    g_Kr);
    cudaGetSymbolAddress((void**)&Vr,    g_Vr);
    cudaGetSymbolAddress((void**)&Yp,    g_Y);

    static bool attr_set = false;
    if (!attr_set) {
        cudaFuncSetAttribute(gemm_qkv_h,
                             cudaFuncAttributeMaxDynamicSharedMemorySize,
                             GEMM_SMEM);
        cudaFuncSetAttribute(gemm_wo_h,
                             cudaFuncAttributeMaxDynamicSharedMemorySize,
                             GEMM_SMEM);
        cudaFuncSetAttribute(attn_tc,
                             cudaFuncAttributeMaxDynamicSharedMemorySize,
                             ATTN_SMEM);
        attr_set = true;
    }

    rope_table_kernel<<<TT, 64>>>();
    cvt_h<<<(MROWS * DD) / 1024, 256>>>(x, xh);
    tr_cvt_h<<<dim3(64, 64), dim3(32, 8)>>>(Wq, Wqkvh, 2048, 0);
    tr_cvt_h<<<dim3(16, 64), dim3(32, 8)>>>(Wk, Wqkvh, 512, 2048);
    tr_cvt_h<<<dim3(16, 64), dim3(32, 8)>>>(Wv, Wqkvh, 512, 2560);
    tr_cvt_h<<<dim3(64, 64), dim3(32, 8)>>>(Wo, Woh, 2048, 0);

    // Fused QKV projection (fp16 MMA) + RoPE + head-major tf32 scatter
    gemm_qkv_h<<<dim3(NQKV / 128, MROWS / 128), 128, GEMM_SMEM>>>(
        xh, Wqkvh, Qr, Kr, Vr);

    attn_tc<<<dim3(TT / 128, NH, BB), 256, ATTN_SMEM>>>(Qr, Kr, Vr, Yp);

    // Y (tf32 bits) -> half, then Wo projection (fp16 MMA)
    cvt_u2h<<<(MROWS * DD) / 1024, 256>>>(Yp, xh);   // reuse g_xh as Yh
    gemm_wo_h<<<dim3(DD / 128, MROWS / 128), 128, GEMM_SMEM>>>(
        xh, Woh, out);
}

// round 10
// speedup vs baseline: 10.6744x; 1.1456x over previous
#include <cuda_runtime.h>
#include <cuda_fp16.h>
#include <math.h>
#include <stdint.h>

#define BB 4
#define TT 1024
#define DD 2048
#define NH 16
#define NKV 4
#define HD 128
#define MROWS (BB*TT)    // 4096
#define NQKV 3072

// Scratch (device globals; no runtime allocation)
__device__ __half   g_xh[MROWS * DD];          // x fp16 [4096][2048]
__device__ __half   g_Wqkvh[NQKV * DD];        // [Wq|Wk|Wv]^T fp16 [3072][2048]
__device__ __half   g_Woh[DD * DD];            // Wo^T fp16
__device__ __half   g_Qh[BB * NH * TT * HD];   // roped Q half [b][h][t][d]
__device__ __half   g_Kh[BB * NKV * TT * HD];  // roped K half [b][g][t][d]
__device__ __half   g_Vt[BB * NKV * HD * TT];  // V half TRANSPOSED [b][g][d][t]
__device__ __half   g_Yh[MROWS * DD];          // attention out half
__device__ float    g_cos[TT * 64];
__device__ float    g_sin[TT * 64];

#define MMA_F16(ACC, A0, A1, A2, A3, B0, B1)                                   \
    asm volatile(                                                              \
        "mma.sync.aligned.m16n8k16.row.col.f32.f16.f16.f32 "                   \
        "{%0,%1,%2,%3}, {%4,%5,%6,%7}, {%8,%9}, {%0,%1,%2,%3};"                \
        : "+f"((ACC)[0]), "+f"((ACC)[1]), "+f"((ACC)[2]), "+f"((ACC)[3])       \
        : "r"(A0), "r"(A1), "r"(A2), "r"(A3), "r"(B0), "r"(B1))

__device__ __forceinline__ void cp16(uint32_t dst, const void* src) {
    asm volatile("cp.async.cg.shared.global [%0], [%1], 16;" ::
                 "r"(dst), "l"(src));
}
#define CP_COMMIT() asm volatile("cp.async.commit_group;")
#define CP_WAIT(n)  asm volatile("cp.async.wait_group %0;" :: "n"(n) : "memory")

__device__ __forceinline__ uint32_t h2bits(float a, float b) {
    __half2 h = __floats2half2_rn(a, b);
    return *(uint32_t*)&h;
}

// ---------------------------------------------------------------------------
// FP16 GEMM: C = A[half, M x 2048 row-major] @ B^T[half, N x 2048 n-major].
// CTA 128x128, 128 threads (4 warps, 2Mx2N, warp 64x64), KT=32, 4 stages.
// ---------------------------------------------------------------------------
#define HSTR 20                   // u32 per row
#define HAW  (128*HSTR)
#define HSTG (2*HAW)
#define GEMM_SMEM (4*HSTG*4)      // 81920 B

#define GEMM_MAINLOOP_H(Aptr, Bptr)                                            \
    auto LOAD = [&](int kt, int s) {                                           \
        uint32_t abase = smaddr + (uint32_t)(s * HSTG) * 4;                    \
        _Pragma("unroll")                                                      \
        for (int p = 0; p < 4; p++) {                                          \
            int id = tid + p * 128;                                            \
            int row = id >> 2, ch = id & 3;                                    \
            cp16(abase + (uint32_t)(row * 80 + ch * 16),                       \
                 (Aptr) + (size_t)(bm + row) * DD + kt * 32 + ch * 8);         \
        }                                                                      \
        uint32_t bbase = abase + HAW * 4;                                      \
        _Pragma("unroll")                                                      \
        for (int p = 0; p < 4; p++) {                                          \
            int id = tid + p * 128;                                            \
            int row = id >> 2, ch = id & 3;                                    \
            cp16(bbase + (uint32_t)(row * 80 + ch * 16),                       \
                 (Bptr) + (size_t)(bn + row) * DD + kt * 32 + ch * 8);         \
        }                                                                      \
        CP_COMMIT();                                                           \
    };                                                                         \
    LOAD(0, 0); LOAD(1, 1); LOAD(2, 2);                                        \
    for (int kt = 0; kt < 64; kt++) {                                          \
        CP_WAIT(2);                                                            \
        __syncthreads();                                                       \
        if (kt + 3 < 64) LOAD(kt + 3, (kt + 3) & 3);                           \
        else CP_COMMIT();                                                      \
        const uint32_t* as = smg + (kt & 3) * HSTG + (wm + gID) * HSTR;        \
        const uint32_t* bs = smg + (kt & 3) * HSTG + HAW + (wn + gID) * HSTR;  \
        _Pragma("unroll")                                                      \
        for (int kk = 0; kk < 2; kk++) {                                       \
            const int k0 = kk * 8;                                             \
            uint32_t af[4][4], bf[8][2];                                       \
            _Pragma("unroll")                                                  \
            for (int mi = 0; mi < 4; mi++) {                                   \
                const uint32_t* ap = as + mi * 16 * HSTR + k0 + tig;           \
                af[mi][0] = ap[0];                                             \
                af[mi][1] = ap[8 * HSTR];                                      \
                af[mi][2] = ap[4];                                             \
                af[mi][3] = ap[8 * HSTR + 4];                                  \
            }                                                                  \
            _Pragma("unroll")                                                  \
            for (int ni = 0; ni < 8; ni++) {                                   \
                const uint32_t* bp = bs + ni * 8 * HSTR + k0 + tig;            \
                bf[ni][0] = bp[0];                                             \
                bf[ni][1] = bp[4];                                             \
            }                                                                  \
            _Pragma("unroll")                                                  \
            for (int mi = 0; mi < 4; mi++)                                     \
                _Pragma("unroll")                                              \
                for (int ni = 0; ni < 8; ni++)                                 \
                    MMA_F16(acc[mi][ni], af[mi][0], af[mi][1], af[mi][2],      \
                            af[mi][3], bf[ni][0], bf[ni][1]);                  \
        }                                                                      \
    }

// ---------------------------------------------------------------------------
// Fused QKV projection (fp16) + RoPE epilogue -> half Qh/Kh head-major,
// V transposed to Vt[b][g][d][t].
// ---------------------------------------------------------------------------
__global__ __launch_bounds__(128, 2) void gemm_qkv_h(
    const __half* __restrict__ A, const __half* __restrict__ B,
    __half* __restrict__ Qh, __half* __restrict__ Kh,
    __half* __restrict__ Vt)
{
    extern __shared__ uint32_t smg[];
    const uint32_t smaddr = (uint32_t)__cvta_generic_to_shared(smg);

    const int tid  = threadIdx.x;
    const int bm   = blockIdx.y * 128;
    const int bn   = blockIdx.x * 128;
    const int warp = tid >> 5, lane = tid & 31;
    const int wm   = (warp & 1) * 64;
    const int wn   = (warp >> 1) * 64;
    const int gID  = lane >> 2, tig = lane & 3;

    float acc[4][8][4];
#pragma unroll
    for (int i = 0; i < 4; i++)
#pragma unroll
        for (int j = 0; j < 8; j++)
#pragma unroll
            for (int l = 0; l < 4; l++) acc[i][j][l] = 0.f;

    GEMM_MAINLOOP_H(A, B)

    // stage fp32 tile in smem
    __syncthreads();
    float* Cs = (float*)smg;       // 128*132 = 16896 u32 < 4*5120
#pragma unroll
    for (int mi = 0; mi < 4; mi++) {
        const int r0 = wm + mi * 16 + gID;
#pragma unroll
        for (int ni = 0; ni < 8; ni++) {
            const int c = wn + ni * 8 + tig * 2;
            Cs[r0 * 132 + c]     = acc[mi][ni][0];
            Cs[r0 * 132 + c + 1] = acc[mi][ni][1];
            Cs[(r0 + 8) * 132 + c]     = acc[mi][ni][2];
            Cs[(r0 + 8) * 132 + c + 1] = acc[mi][ni][3];
        }
    }
    __syncthreads();

    const int bb = bm >> 10;           // batch (tile never crosses batch)
    if (bn < 2560) {
        // Q or K branch: rope + half write, head-major [.,head][t][d]
        __half* dst;
        int head, hs;
        if (bn < 2048) { dst = Qh; head = bn >> 7;          hs = NH;  }
        else           { dst = Kh; head = (bn - 2048) >> 7; hs = NKV; }
#pragma unroll 4
        for (int p = 0; p < 32; p++) {
            int idx = tid + p * 128;
            int r = idx >> 5;
            int d2 = (idx & 31) << 1;
            int t = (bm + r) & (TT - 1);
            float lo0 = Cs[r * 132 + d2];
            float lo1 = Cs[r * 132 + d2 + 1];
            float hi0 = Cs[r * 132 + d2 + 64];
            float hi1 = Cs[r * 132 + d2 + 65];
            float2 cc = *(const float2*)(g_cos + t * 64 + d2);
            float2 ss = *(const float2*)(g_sin + t * 64 + d2);
            __half* o = dst + ((size_t)(bb * hs + head) * TT + t) * HD;
            *(__half2*)(o + d2) =
                __floats2half2_rn(lo0 * cc.x - hi0 * ss.x,
                                  lo1 * cc.y - hi1 * ss.y);
            *(__half2*)(o + d2 + 64) =
                __floats2half2_rn(hi0 * cc.x + lo0 * ss.x,
                                  hi1 * cc.y + lo1 * ss.y);
        }
    } else {
        // V branch: transpose through smem -> Vt[d][t], coalesced row writes
        const int head = (bn - 2560) >> 7;
        const int d = tid;             // 0..127
        const int t0 = bm & (TT - 1);
        __half* o = Vt + ((size_t)(bb * NKV + head) * HD + d) * TT + t0;
#pragma unroll 8
        for (int tq = 0; tq < 128; tq += 2) {
            float v0 = Cs[tq * 132 + d];
            float v1 = Cs[(tq + 1) * 132 + d];
            *(__half2*)(o + tq) = __floats2half2_rn(v0, v1);
        }
    }
}

// ---------------------------------------------------------------------------
// Wo projection (fp16): out fp32 = Yh @ Woh^T-tile
// ---------------------------------------------------------------------------
__global__ __launch_bounds__(128, 2) void gemm_wo_h(
    const __half* __restrict__ A, const __half* __restrict__ B,
    float* __restrict__ C)
{
    extern __shared__ uint32_t smg[];
    const uint32_t smaddr = (uint32_t)__cvta_generic_to_shared(smg);

    const int tid  = threadIdx.x;
    const int bm   = blockIdx.y * 128;
    const int bn   = blockIdx.x * 128;
    const int warp = tid >> 5, lane = tid & 31;
    const int wm   = (warp & 1) * 64;
    const int wn   = (warp >> 1) * 64;
    const int gID  = lane >> 2, tig = lane & 3;

    float acc[4][8][4];
#pragma unroll
    for (int i = 0; i < 4; i++)
#pragma unroll
        for (int j = 0; j < 8; j++)
#pragma unroll
            for (int l = 0; l < 4; l++) acc[i][j][l] = 0.f;

    GEMM_MAINLOOP_H(A, B)

#pragma unroll
    for (int mi = 0; mi < 4; mi++) {
        const int r0 = bm + wm + mi * 16 + gID;
#pragma unroll
        for (int ni = 0; ni < 8; ni++) {
            const int c = bn + wn + ni * 8 + tig * 2;
            *(float2*)&C[(size_t)r0 * DD + c] =
                make_float2(acc[mi][ni][0], acc[mi][ni][1]);
            *(float2*)&C[(size_t)(r0 + 8) * DD + c] =
                make_float2(acc[mi][ni][2], acc[mi][ni][3]);
        }
    }
}

// ---------------------------------------------------------------------------
// Prep kernels
// ---------------------------------------------------------------------------
__global__ void cvt_h(const float* __restrict__ in, __half* __restrict__ out)
{
    int i = (blockIdx.x * 256 + threadIdx.x) * 4;
    float4 v = *(const float4*)(in + i);
    *(__half2*)(out + i)     = __floats2half2_rn(v.x, v.y);
    *(__half2*)(out + i + 2) = __floats2half2_rn(v.z, v.w);
}

__global__ void tr_cvt_h(const float* __restrict__ src, __half* __restrict__ dst,
                         int C, int row_off)
{
    __shared__ float tile[32][33];
    int bx = blockIdx.x * 32;
    int by = blockIdx.y * 32;
    int x = threadIdx.x, y = threadIdx.y;   // 32 x 8
#pragma unroll
    for (int j = 0; j < 32; j += 8)
        tile[y + j][x] = src[(size_t)(by + y + j) * C + bx + x];
    __syncthreads();
#pragma unroll
    for (int j = 0; j < 32; j += 8)
        dst[(size_t)(row_off + bx + y + j) * 2048 + by + x] =
            __float2half(tile[x][y + j]);
}

__global__ void rope_table_kernel()
{
    int t = blockIdx.x;
    int i = threadIdx.x;
    float inv = powf(10000.0f, -(float)i / 64.0f);
    float ang = (float)t * inv;
    g_cos[t * 64 + i] = cosf(ang);
    g_sin[t * 64 + i] = sinf(ang);
}

// ---------------------------------------------------------------------------
// FP16 tensor-core flash attention, causal, GQA.
// Q half [b][h][t][d], K half [b][g][t][d], V half TRANSPOSED [b][g][d][t].
// 256 threads = 8 warps x 16 q-rows, BQ=128, BS=64.
// ---------------------------------------------------------------------------
#define QSTR 68     // u32 per 128-half row (64 data + 4 pad)
#define KSTR 68
#define VSTR 36     // u32 per 64-half row (32 data + 4 pad)
#define PSTR 36
// Qs 128*68 + Ks 64*68 + Vs 2*128*36 + Ps 128*36 = 26880 u32
#define ATTN_SMEM (26880 * 4)

__global__ __launch_bounds__(256, 1) void attn_h(
    const __half* __restrict__ Qh, const __half* __restrict__ Kh,
    const __half* __restrict__ Vt, __half* __restrict__ Y)
{
    extern __shared__ uint32_t sma[];
    uint32_t* Qs  = sma;                        // [128][QSTR]
    uint32_t* Ks  = Qs + 128 * QSTR;            // [64][KSTR]
    uint32_t* Vsb = Ks + 64 * KSTR;             // [2][128][VSTR], rows = d
    uint32_t* Ps  = Vsb + 2 * 128 * VSTR;       // [128][PSTR]
    const uint32_t smaddr = (uint32_t)__cvta_generic_to_shared(sma);
    const uint32_t Qs_a = smaddr;
    const uint32_t Ks_a = Qs_a + 128 * QSTR * 4;
    const uint32_t Vs_a = Ks_a + 64 * KSTR * 4;

    const int tid  = threadIdx.x;
    const int warp = tid >> 5, lane = tid & 31;
    const int gID  = lane >> 2, tig = lane & 3;
    const int qt   = (gridDim.x - 1) - blockIdx.x;   // heavy first
    const int hh   = blockIdx.y;
    const int b    = blockIdx.z;
    const int gkv  = hh >> 2;
    const int q0   = qt * 128;
    const int wm   = warp * 16;
    const int row0 = q0 + wm + gID;

    const __half* Qbase = Qh + ((size_t)(b * NH + hh) * TT + q0) * HD;
    const __half* Kbase = Kh + (size_t)(b * NKV + gkv) * TT * HD;
    const __half* Vbase = Vt + (size_t)(b * NKV + gkv) * HD * TT;

    auto LOADQ = [&]() {
#pragma unroll
        for (int p = 0; p < 8; p++) {
            int id = tid + p * 256;
            int q = id >> 4, ch = id & 15;
            cp16(Qs_a + (uint32_t)(q * QSTR + ch * 4) * 4,
                 Qbase + q * HD + ch * 8);
        }
    };
    auto LOADK = [&](int st) {
        const __half* src = Kbase + (size_t)st * 64 * HD;
#pragma unroll
        for (int p = 0; p < 4; p++) {
            int id = tid + p * 256;
            int s = id >> 4, ch = id & 15;
            cp16(Ks_a + (uint32_t)(s * KSTR + ch * 4) * 4,
                 src + s * HD + ch * 8);
        }
    };
    auto LOADV = [&](int st) {
        const __half* src = Vbase + st * 64;     // column slice [d][s0..s0+63]
        uint32_t dbase = Vs_a + (uint32_t)((st & 1) * 128 * VSTR) * 4;
#pragma unroll
        for (int p = 0; p < 4; p++) {
            int id = tid + p * 256;
            int d = id >> 3, ch = id & 7;
            cp16(dbase + (uint32_t)(d * VSTR + ch * 4) * 4,
                 src + (size_t)d * TT + ch * 8);
        }
    };

    const int ntiles = 2 * qt + 2;

    LOADQ(); LOADK(0); LOADV(0); CP_COMMIT();
    LOADV(1); CP_COMMIT();

    float m0 = -1e30f, m1 = -1e30f, l0 = 0.f, l1 = 0.f;
    float oacc[16][4];
#pragma unroll
    for (int i = 0; i < 16; i++)
#pragma unroll
        for (int j = 0; j < 4; j++) oacc[i][j] = 0.f;

    const float scale = 0.08838834764831845f;   // 1/sqrt(128)

    for (int st = 0; st < ntiles; st++) {
        const int s0 = st * 64;
        const bool active = (q0 + wm + 15 >= s0);

        CP_WAIT(1);          // K(st), V(st) (and Q on st=0) ready
        __syncthreads();

        float sacc[8][4];
        if (active) {
#pragma unroll
            for (int i = 0; i < 8; i++)
#pragma unroll
                for (int j = 0; j < 4; j++) sacc[i][j] = 0.f;

            const uint32_t* qrow = Qs + (wm + gID) * QSTR;
#pragma unroll
            for (int kk = 0; kk < 8; kk++) {
                const int k0 = kk * 8;
                uint32_t a0 = qrow[k0 + tig];
                uint32_t a1 = qrow[8 * QSTR + k0 + tig];
                uint32_t a2 = qrow[k0 + tig + 4];
                uint32_t a3 = qrow[8 * QSTR + k0 + tig + 4];
#pragma unroll
                for (int ni = 0; ni < 8; ni++) {
                    const uint32_t* kp = Ks + (gID + ni * 8) * KSTR + k0;
                    MMA_F16(sacc[ni], a0, a1, a2, a3, kp[tig], kp[tig + 4]);
                }
            }
        }
        __syncthreads();     // all warps done reading Ks

        if (st + 1 < ntiles) LOADK(st + 1);
        CP_COMMIT();

        if (active) {
            const int lim0 = row0 - s0;
            const int lim1 = lim0 + 8;
            const bool diag = (st >= 2 * qt);
            float mx0 = -1e30f, mx1 = -1e30f;
#pragma unroll
            for (int ni = 0; ni < 8; ni++) {
#pragma unroll
                for (int c = 0; c < 2; c++) {
                    int j = ni * 8 + tig * 2 + c;
                    float v0 = sacc[ni][c] * scale;
                    float v1 = sacc[ni][2 + c] * scale;
                    if (diag) {
                        if (j > lim0) v0 = -1e30f;
                        if (j > lim1) v1 = -1e30f;
                    }
                    sacc[ni][c]     = v0;
                    sacc[ni][2 + c] = v1;
                    mx0 = fmaxf(mx0, v0);
                    mx1 = fmaxf(mx1, v1);
                }
            }
            mx0 = fmaxf(mx0, __shfl_xor_sync(0xffffffffu, mx0, 1));
            mx0 = fmaxf(mx0, __shfl_xor_sync(0xffffffffu, mx0, 2));
            mx1 = fmaxf(mx1, __shfl_xor_sync(0xffffffffu, mx1, 1));
            mx1 = fmaxf(mx1, __shfl_xor_sync(0xffffffffu, mx1, 2));
            float mn0 = fmaxf(m0, mx0), mn1 = fmaxf(m1, mx1);
            float cr0 = __expf(m0 - mn0), cr1 = __expf(m1 - mn1);
            float sum0 = 0.f, sum1 = 0.f;
#pragma unroll
            for (int ni = 0; ni < 8; ni++) {
#pragma unroll
                for (int c = 0; c < 2; c++) {
                    float p0 = __expf(sacc[ni][c] - mn0);
                    float p1 = __expf(sacc[ni][2 + c] - mn1);
                    sacc[ni][c]     = p0;
                    sacc[ni][2 + c] = p1;
                    sum0 += p0;
                    sum1 += p1;
                }
            }
            sum0 += __shfl_xor_sync(0xffffffffu, sum0, 1);
            sum0 += __shfl_xor_sync(0xffffffffu, sum0, 2);
            sum1 += __shfl_xor_sync(0xffffffffu, sum1, 1);
            sum1 += __shfl_xor_sync(0xffffffffu, sum1, 2);
            l0 = l0 * cr0 + sum0;
            l1 = l1 * cr1 + sum1;
            m0 = mn0; m1 = mn1;

#pragma unroll
            for (int ni = 0; ni < 16; ni++) {
                oacc[ni][0] *= cr0; oacc[ni][1] *= cr0;
                oacc[ni][2] *= cr1; oacc[ni][3] *= cr1;
            }

            // write P (half2 packs)
            uint32_t* pr0 = Ps + (wm + gID) * PSTR;
            uint32_t* pr1 = pr0 + 8 * PSTR;
#pragma unroll
            for (int ni = 0; ni < 8; ni++) {
                pr0[ni * 4 + tig] = h2bits(sacc[ni][0], sacc[ni][1]);
                pr1[ni * 4 + tig] = h2bits(sacc[ni][2], sacc[ni][3]);
            }
            __syncwarp();

            // O += P @ V   (V rows = d, k = s contiguous)
            const uint32_t* vbuf = Vsb + (st & 1) * 128 * VSTR;
            const uint32_t* prow = Ps + (wm + gID) * PSTR;
#pragma unroll
            for (int kk = 0; kk < 4; kk++) {
                const int k0 = kk * 8;
                uint32_t a0 = prow[k0 + tig];
                uint32_t a1 = prow[8 * PSTR + k0 + tig];
                uint32_t a2 = prow[k0 + tig + 4];
                uint32_t a3 = prow[8 * PSTR + k0 + tig + 4];
#pragma unroll
                for (int ni = 0; ni < 16; ni++) {
                    const uint32_t* vp = vbuf + (gID + ni * 8) * VSTR + k0;
                    MMA_F16(oacc[ni], a0, a1, a2, a3, vp[tig], vp[tig + 4]);
                }
            }
        }
        __syncthreads();     // PV done -> V(st) buffer free

        if (st + 2 < ntiles) LOADV(st + 2);
        CP_COMMIT();
    }

    float li0 = 1.f / l0, li1 = 1.f / l1;
    __half* y0 = Y + (size_t)(b * TT + row0) * DD + hh * HD;
    __half* y1 = y0 + (size_t)8 * DD;
#pragma unroll
    for (int ni = 0; ni < 16; ni++) {
        int c = ni * 8 + tig * 2;
        *(__half2*)(y0 + c) = __floats2half2_rn(oacc[ni][0] * li0,
                                                oacc[ni][1] * li0);
        *(__half2*)(y1 + c) = __floats2half2_rn(oacc[ni][2] * li1,
                                                oacc[ni][3] * li1);
    }
}

// ---------------------------------------------------------------------------
extern "C" void kernel_launch(void* const* d_in, const int* in_sizes, int n_in,
                              void* d_out, int out_size)
{
    const float* x  = (const float*)d_in[0];
    const float* Wq = (const float*)d_in[1];
    const float* Wk = (const float*)d_in[2];
    const float* Wv = (const float*)d_in[3];
    const float* Wo = (const float*)d_in[4];
    float* out = (float*)d_out;

    __half *xh, *Wqkvh, *Woh, *Qh, *Kh, *Vt, *Yh;
    cudaGetSymbolAddress((void**)&xh,    g_xh);
    cudaGetSymbolAddress((void**)&Wqkvh, g_Wqkvh);
    cudaGetSymbolAddress((void**)&Woh,   g_Woh);
    cudaGetSymbolAddress((void**)&Qh,    g_Qh);
    cudaGetSymbolAddress((void**)&Kh,    g_Kh);
    cudaGetSymbolAddress((void**)&Vt,    g_Vt);
    cudaGetSymbolAddress((void**)&Yh,    g_Yh);

    static bool attr_set = false;
    if (!attr_set) {
        cudaFuncSetAttribute(gemm_qkv_h,
                             cudaFuncAttributeMaxDynamicSharedMemorySize,
                             GEMM_SMEM);
        cudaFuncSetAttribute(gemm_wo_h,
                             cudaFuncAttributeMaxDynamicSharedMemorySize,
                             GEMM_SMEM);
        cudaFuncSetAttribute(attn_h,
                             cudaFuncAttributeMaxDynamicSharedMemorySize,
                             ATTN_SMEM);
        attr_set = true;
    }

    rope_table_kernel<<<TT, 64>>>();
    cvt_h<<<(MROWS * DD) / 1024, 256>>>(x, xh);
    tr_cvt_h<<<dim3(64, 64), dim3(32, 8)>>>(Wq, Wqkvh, 2048, 0);
    tr_cvt_h<<<dim3(16, 64), dim3(32, 8)>>>(Wk, Wqkvh, 512, 2048);
    tr_cvt_h<<<dim3(16, 64), dim3(32, 8)>>>(Wv, Wqkvh, 512, 2560);
    tr_cvt_h<<<dim3(64, 64), dim3(32, 8)>>>(Wo, Woh, 2048, 0);

    // Fused QKV projection + RoPE -> half Qh/Kh, transposed half Vt
    gemm_qkv_h<<<dim3(NQKV / 128, MROWS / 128), 128, GEMM_SMEM>>>(
        xh, Wqkvh, Qh, Kh, Vt);

    // FP16 flash attention -> Yh (half)
    attn_h<<<dim3(TT / 128, NH, BB), 256, ATTN_SMEM>>>(Qh, Kh, Vt, Yh);

    // Output projection
    gemm_wo_h<<<dim3(DD / 128, MROWS / 128), 128, GEMM_SMEM>>>(Yh, Woh, out);
}

// round 11
// speedup vs baseline: 11.0220x; 1.0326x over previous
#include <cuda_runtime.h>
#include <cuda_fp16.h>
#include <math.h>
#include <stdint.h>

#define BB 4
#define TT 1024
#define DD 2048
#define NH 16
#define NKV 4
#define HD 128
#define MROWS (BB*TT)    // 4096
#define NQKV 3072
#define SCALE 0.08838834764831845f   // 1/sqrt(128)

// Scratch (device globals; no runtime allocation)
__device__ __half   g_xh[MROWS * DD];          // x fp16 [4096][2048]
__device__ __half   g_Wqkvh[NQKV * DD];        // [Wq|Wk|Wv]^T fp16 [3072][2048]
__device__ __half   g_Woh[DD * DD];            // Wo^T fp16
__device__ __half   g_Qh[BB * NH * TT * HD];   // roped+scaled Q half [b][h][t][d]
__device__ __half   g_Kh[BB * NKV * TT * HD];  // roped K half [b][g][t][d]
__device__ __half   g_Vt[BB * NKV * HD * TT];  // V half TRANSPOSED [b][g][d][t]
__device__ __half   g_Yh[MROWS * DD];          // attention out half
__device__ float    g_cos[TT * 64];
__device__ float    g_sin[TT * 64];

#define MMA_F16(ACC, A0, A1, A2, A3, B0, B1)                                   \
    asm volatile(                                                              \
        "mma.sync.aligned.m16n8k16.row.col.f32.f16.f16.f32 "                   \
        "{%0,%1,%2,%3}, {%4,%5,%6,%7}, {%8,%9}, {%0,%1,%2,%3};"                \
        : "+f"((ACC)[0]), "+f"((ACC)[1]), "+f"((ACC)[2]), "+f"((ACC)[3])       \
        : "r"(A0), "r"(A1), "r"(A2), "r"(A3), "r"(B0), "r"(B1))

__device__ __forceinline__ void cp16(uint32_t dst, const void* src) {
    asm volatile("cp.async.cg.shared.global [%0], [%1], 16;" ::
                 "r"(dst), "l"(src));
}
#define CP_COMMIT() asm volatile("cp.async.commit_group;")
#define CP_WAIT(n)  asm volatile("cp.async.wait_group %0;" :: "n"(n) : "memory")

__device__ __forceinline__ uint32_t h2bits(float a, float b) {
    __half2 h = __floats2half2_rn(a, b);
    return *(uint32_t*)&h;
}

// ---------------------------------------------------------------------------
// FP16 GEMM: C = A[half, M x 2048 row-major] @ B^T[half, N x 2048 n-major].
// CTA 128x128, 128 threads (4 warps, 2Mx2N, warp 64x64), KT=32, 4 stages.
// ---------------------------------------------------------------------------
#define HSTR 20
#define HAW  (128*HSTR)
#define HSTG (2*HAW)
#define GEMM_SMEM (4*HSTG*4)      // 81920 B

#define GEMM_MAINLOOP_H(Aptr, Bptr)                                            \
    auto LOAD = [&](int kt, int s) {                                           \
        uint32_t abase = smaddr + (uint32_t)(s * HSTG) * 4;                    \
        _Pragma("unroll")                                                      \
        for (int p = 0; p < 4; p++) {                                          \
            int id = tid + p * 128;                                            \
            int row = id >> 2, ch = id & 3;                                    \
            cp16(abase + (uint32_t)(row * 80 + ch * 16),                       \
                 (Aptr) + (size_t)(bm + row) * DD + kt * 32 + ch * 8);         \
        }                                                                      \
        uint32_t bbase = abase + HAW * 4;                                      \
        _Pragma("unroll")                                                      \
        for (int p = 0; p < 4; p++) {                                          \
            int id = tid + p * 128;                                            \
            int row = id >> 2, ch = id & 3;                                    \
            cp16(bbase + (uint32_t)(row * 80 + ch * 16),                       \
                 (Bptr) + (size_t)(bn + row) * DD + kt * 32 + ch * 8);         \
        }                                                                      \
        CP_COMMIT();                                                           \
    };                                                                         \
    LOAD(0, 0); LOAD(1, 1); LOAD(2, 2);                                        \
    for (int kt = 0; kt < 64; kt++) {                                          \
        CP_WAIT(2);                                                            \
        __syncthreads();                                                       \
        if (kt + 3 < 64) LOAD(kt + 3, (kt + 3) & 3);                           \
        else CP_COMMIT();                                                      \
        const uint32_t* as = smg + (kt & 3) * HSTG + (wm + gID) * HSTR;        \
        const uint32_t* bs = smg + (kt & 3) * HSTG + HAW + (wn + gID) * HSTR;  \
        _Pragma("unroll")                                                      \
        for (int kk = 0; kk < 2; kk++) {                                       \
            const int k0 = kk * 8;                                             \
            uint32_t af[4][4], bf[8][2];                                       \
            _Pragma("unroll")                                                  \
            for (int mi = 0; mi < 4; mi++) {                                   \
                const uint32_t* ap = as + mi * 16 * HSTR + k0 + tig;           \
                af[mi][0] = ap[0];                                             \
                af[mi][1] = ap[8 * HSTR];                                      \
                af[mi][2] = ap[4];                                             \
                af[mi][3] = ap[8 * HSTR + 4];                                  \
            }                                                                  \
            _Pragma("unroll")                                                  \
            for (int ni = 0; ni < 8; ni++) {                                   \
                const uint32_t* bp = bs + ni * 8 * HSTR + k0 + tig;            \
                bf[ni][0] = bp[0];                                             \
                bf[ni][1] = bp[4];                                             \
            }                                                                  \
            _Pragma("unroll")                                                  \
            for (int mi = 0; mi < 4; mi++)                                     \
                _Pragma("unroll")                                              \
                for (int ni = 0; ni < 8; ni++)                                 \
                    MMA_F16(acc[mi][ni], af[mi][0], af[mi][1], af[mi][2],      \
                            af[mi][3], bf[ni][0], bf[ni][1]);                  \
        }                                                                      \
    }

// ---------------------------------------------------------------------------
// Fused QKV projection (fp16) + RoPE epilogue. Q is pre-scaled by 1/sqrt(d).
// ---------------------------------------------------------------------------
__global__ __launch_bounds__(128, 2) void gemm_qkv_h(
    const __half* __restrict__ A, const __half* __restrict__ B,
    __half* __restrict__ Qh, __half* __restrict__ Kh,
    __half* __restrict__ Vt)
{
    extern __shared__ uint32_t smg[];
    const uint32_t smaddr = (uint32_t)__cvta_generic_to_shared(smg);

    const int tid  = threadIdx.x;
    const int bm   = blockIdx.y * 128;
    const int bn   = blockIdx.x * 128;
    const int warp = tid >> 5, lane = tid & 31;
    const int wm   = (warp & 1) * 64;
    const int wn   = (warp >> 1) * 64;
    const int gID  = lane >> 2, tig = lane & 3;

    float acc[4][8][4];
#pragma unroll
    for (int i = 0; i < 4; i++)
#pragma unroll
        for (int j = 0; j < 8; j++)
#pragma unroll
            for (int l = 0; l < 4; l++) acc[i][j][l] = 0.f;

    GEMM_MAINLOOP_H(A, B)

    __syncthreads();
    float* Cs = (float*)smg;       // 128*132 = 16896 u32 < 4*5120
#pragma unroll
    for (int mi = 0; mi < 4; mi++) {
        const int r0 = wm + mi * 16 + gID;
#pragma unroll
        for (int ni = 0; ni < 8; ni++) {
            const int c = wn + ni * 8 + tig * 2;
            Cs[r0 * 132 + c]     = acc[mi][ni][0];
            Cs[r0 * 132 + c + 1] = acc[mi][ni][1];
            Cs[(r0 + 8) * 132 + c]     = acc[mi][ni][2];
            Cs[(r0 + 8) * 132 + c + 1] = acc[mi][ni][3];
        }
    }
    __syncthreads();

    const int bb = bm >> 10;
    if (bn < 2560) {
        __half* dst;
        int head, hs;
        float sc;
        if (bn < 2048) { dst = Qh; head = bn >> 7;          hs = NH;  sc = SCALE; }
        else           { dst = Kh; head = (bn - 2048) >> 7; hs = NKV; sc = 1.f;   }
#pragma unroll 4
        for (int p = 0; p < 32; p++) {
            int idx = tid + p * 128;
            int r = idx >> 5;
            int d2 = (idx & 31) << 1;
            int t = (bm + r) & (TT - 1);
            float lo0 = Cs[r * 132 + d2] * sc;
            float lo1 = Cs[r * 132 + d2 + 1] * sc;
            float hi0 = Cs[r * 132 + d2 + 64] * sc;
            float hi1 = Cs[r * 132 + d2 + 65] * sc;
            float2 cc = *(const float2*)(g_cos + t * 64 + d2);
            float2 ss = *(const float2*)(g_sin + t * 64 + d2);
            __half* o = dst + ((size_t)(bb * hs + head) * TT + t) * HD;
            *(__half2*)(o + d2) =
                __floats2half2_rn(lo0 * cc.x - hi0 * ss.x,
                                  lo1 * cc.y - hi1 * ss.y);
            *(__half2*)(o + d2 + 64) =
                __floats2half2_rn(hi0 * cc.x + lo0 * ss.x,
                                  hi1 * cc.y + lo1 * ss.y);
        }
    } else {
        const int head = (bn - 2560) >> 7;
        const int d = tid;
        const int t0 = bm & (TT - 1);
        __half* o = Vt + ((size_t)(bb * NKV + head) * HD + d) * TT + t0;
#pragma unroll 8
        for (int tq = 0; tq < 128; tq += 2) {
            float v0 = Cs[tq * 132 + d];
            float v1 = Cs[(tq + 1) * 132 + d];
            *(__half2*)(o + tq) = __floats2half2_rn(v0, v1);
        }
    }
}

// ---------------------------------------------------------------------------
// Wo projection (fp16): out fp32 = Yh @ Woh^T-tile
// ---------------------------------------------------------------------------
__global__ __launch_bounds__(128, 2) void gemm_wo_h(
    const __half* __restrict__ A, const __half* __restrict__ B,
    float* __restrict__ C)
{
    extern __shared__ uint32_t smg[];
    const uint32_t smaddr = (uint32_t)__cvta_generic_to_shared(smg);

    const int tid  = threadIdx.x;
    const int bm   = blockIdx.y * 128;
    const int bn   = blockIdx.x * 128;
    const int warp = tid >> 5, lane = tid & 31;
    const int wm   = (warp & 1) * 64;
    const int wn   = (warp >> 1) * 64;
    const int gID  = lane >> 2, tig = lane & 3;

    float acc[4][8][4];
#pragma unroll
    for (int i = 0; i < 4; i++)
#pragma unroll
        for (int j = 0; j < 8; j++)
#pragma unroll
            for (int l = 0; l < 4; l++) acc[i][j][l] = 0.f;

    GEMM_MAINLOOP_H(A, B)

#pragma unroll
    for (int mi = 0; mi < 4; mi++) {
        const int r0 = bm + wm + mi * 16 + gID;
#pragma unroll
        for (int ni = 0; ni < 8; ni++) {
            const int c = bn + wn + ni * 8 + tig * 2;
            *(float2*)&C[(size_t)r0 * DD + c] =
                make_float2(acc[mi][ni][0], acc[mi][ni][1]);
            *(float2*)&C[(size_t)(r0 + 8) * DD + c] =
                make_float2(acc[mi][ni][2], acc[mi][ni][3]);
        }
    }
}

// ---------------------------------------------------------------------------
// Prep kernels
// ---------------------------------------------------------------------------
__global__ void cvt_h(const float* __restrict__ in, __half* __restrict__ out)
{
    int i = (blockIdx.x * 256 + threadIdx.x) * 4;
    float4 v = *(const float4*)(in + i);
    *(__half2*)(out + i)     = __floats2half2_rn(v.x, v.y);
    *(__half2*)(out + i + 2) = __floats2half2_rn(v.z, v.w);
}

// Fused transpose+cvt for all 4 weights; blockIdx.z selects the weight.
__global__ void tr_cvt_all(const float* __restrict__ Wq,
                           const float* __restrict__ Wk,
                           const float* __restrict__ Wv,
                           const float* __restrict__ Wo,
                           __half* __restrict__ Wqkvh,
                           __half* __restrict__ Woh)
{
    __shared__ float tile[32][33];
    const int z = blockIdx.z;
    const float* src;
    __half* dst;
    int C, row_off;
    if      (z == 0) { src = Wq; dst = Wqkvh; C = 2048; row_off = 0;    }
    else if (z == 1) { src = Wk; dst = Wqkvh; C = 512;  row_off = 2048; }
    else if (z == 2) { src = Wv; dst = Wqkvh; C = 512;  row_off = 2560; }
    else             { src = Wo; dst = Woh;   C = 2048; row_off = 0;    }

    int bx = blockIdx.x * 32;
    if (bx >= C) return;
    int by = blockIdx.y * 32;
    int x = threadIdx.x, y = threadIdx.y;   // 32 x 8
#pragma unroll
    for (int j = 0; j < 32; j += 8)
        tile[y + j][x] = src[(size_t)(by + y + j) * C + bx + x];
    __syncthreads();
#pragma unroll
    for (int j = 0; j < 32; j += 8)
        dst[(size_t)(row_off + bx + y + j) * 2048 + by + x] =
            __float2half(tile[x][y + j]);
}

__global__ void rope_table_kernel()
{
    int t = blockIdx.x;
    int i = threadIdx.x;
    float inv = powf(10000.0f, -(float)i / 64.0f);
    float ang = (float)t * inv;
    g_cos[t * 64 + i] = cosf(ang);
    g_sin[t * 64 + i] = sinf(ang);
}

// ---------------------------------------------------------------------------
// FP16 flash attention, causal, GQA. BQ=128, BS=128.
// Q pre-scaled; K [b][g][t][d]; V transposed [b][g][d][t].
// 256 threads = 8 warps x 16 q-rows. K single-buffered, V double-buffered.
// ---------------------------------------------------------------------------
#define QSTR 68     // u32 per 128-half row
#define KSTR 68
#define VSTR 68     // V row = 128 t halfs
#define PSTR 68
// Qs 128*68 + Ks 128*68 + Vs 2*128*68 + Ps 128*68 = 43520 u32 = 174080 B
#define ATTN_SMEM (43520 * 4)

__global__ __launch_bounds__(256, 1) void attn_h(
    const __half* __restrict__ Qh, const __half* __restrict__ Kh,
    const __half* __restrict__ Vt, __half* __restrict__ Y)
{
    extern __shared__ uint32_t sma[];
    uint32_t* Qs  = sma;                        // [128][QSTR]
    uint32_t* Ks  = Qs + 128 * QSTR;            // [128][KSTR]
    uint32_t* Vsb = Ks + 128 * KSTR;            // [2][128][VSTR], rows = d
    uint32_t* Ps  = Vsb + 2 * 128 * VSTR;       // [128][PSTR]
    const uint32_t smaddr = (uint32_t)__cvta_generic_to_shared(sma);
    const uint32_t Qs_a = smaddr;
    const uint32_t Ks_a = Qs_a + 128 * QSTR * 4;
    const uint32_t Vs_a = Ks_a + 128 * KSTR * 4;

    const int tid  = threadIdx.x;
    const int warp = tid >> 5, lane = tid & 31;
    const int gID  = lane >> 2, tig = lane & 3;
    const int qt   = (gridDim.x - 1) - blockIdx.x;   // heavy first
    const int hh   = blockIdx.y;
    const int b    = blockIdx.z;
    const int gkv  = hh >> 2;
    const int q0   = qt * 128;
    const int wm   = warp * 16;
    const int row0 = q0 + wm + gID;

    const __half* Qbase = Qh + ((size_t)(b * NH + hh) * TT + q0) * HD;
    const __half* Kbase = Kh + (size_t)(b * NKV + gkv) * TT * HD;
    const __half* Vbase = Vt + (size_t)(b * NKV + gkv) * HD * TT;

    auto LOADQ = [&]() {
#pragma unroll
        for (int p = 0; p < 8; p++) {
            int id = tid + p * 256;
            int q = id >> 4, ch = id & 15;
            cp16(Qs_a + (uint32_t)(q * QSTR + ch * 4) * 4,
                 Qbase + q * HD + ch * 8);
        }
    };
    auto LOADK = [&](int st) {
        const __half* src = Kbase + (size_t)st * 128 * HD;
#pragma unroll
        for (int p = 0; p < 8; p++) {
            int id = tid + p * 256;
            int s = id >> 4, ch = id & 15;
            cp16(Ks_a + (uint32_t)(s * KSTR + ch * 4) * 4,
                 src + s * HD + ch * 8);
        }
    };
    auto LOADV = [&](int st) {
        const __half* src = Vbase + st * 128;    // column slice [d][s0..s0+127]
        uint32_t dbase = Vs_a + (uint32_t)((st & 1) * 128 * VSTR) * 4;
#pragma unroll
        for (int p = 0; p < 8; p++) {
            int id = tid + p * 256;
            int d = id >> 4, ch = id & 15;
            cp16(dbase + (uint32_t)(d * VSTR + ch * 4) * 4,
                 src + (size_t)d * TT + ch * 8);
        }
    };

    const int ntiles = qt + 1;

    LOADQ(); LOADK(0); LOADV(0); CP_COMMIT();
    if (ntiles > 1) LOADV(1);
    CP_COMMIT();

    float m0 = -1e30f, m1 = -1e30f, l0 = 0.f, l1 = 0.f;
    float oacc[16][4];
#pragma unroll
    for (int i = 0; i < 16; i++)
#pragma unroll
        for (int j = 0; j < 4; j++) oacc[i][j] = 0.f;

    for (int st = 0; st < ntiles; st++) {
        const int s0 = st * 128;

        CP_WAIT(1);          // K(st), V(st) (and Q on st=0) ready
        __syncthreads();

        // ---- S = Q @ K^T : per-warp 16x128 ----
        float sacc[16][4];
#pragma unroll
        for (int i = 0; i < 16; i++)
#pragma unroll
            for (int j = 0; j < 4; j++) sacc[i][j] = 0.f;

        const uint32_t* qrow = Qs + (wm + gID) * QSTR;
#pragma unroll
        for (int kk = 0; kk < 8; kk++) {
            const int k0 = kk * 8;
            uint32_t a0 = qrow[k0 + tig];
            uint32_t a1 = qrow[8 * QSTR + k0 + tig];
            uint32_t a2 = qrow[k0 + tig + 4];
            uint32_t a3 = qrow[8 * QSTR + k0 + tig + 4];
#pragma unroll
            for (int ni = 0; ni < 16; ni++) {
                const uint32_t* kp = Ks + (gID + ni * 8) * KSTR + k0;
                MMA_F16(sacc[ni], a0, a1, a2, a3, kp[tig], kp[tig + 4]);
            }
        }
        __syncthreads();     // all warps done reading Ks

        if (st + 1 < ntiles) LOADK(st + 1);
        CP_COMMIT();

        // ---- softmax ----
        const int lim0 = row0 - s0;
        const int lim1 = lim0 + 8;
        const bool diag = (st == qt);
        float mx0 = -1e30f, mx1 = -1e30f;
#pragma unroll
        for (int ni = 0; ni < 16; ni++) {
#pragma unroll
            for (int c = 0; c < 2; c++) {
                int j = ni * 8 + tig * 2 + c;
                float v0 = sacc[ni][c];
                float v1 = sacc[ni][2 + c];
                if (diag) {
                    if (j > lim0) v0 = -1e30f;
                    if (j > lim1) v1 = -1e30f;
                }
                sacc[ni][c]     = v0;
                sacc[ni][2 + c] = v1;
                mx0 = fmaxf(mx0, v0);
                mx1 = fmaxf(mx1, v1);
            }
        }
        mx0 = fmaxf(mx0, __shfl_xor_sync(0xffffffffu, mx0, 1));
        mx0 = fmaxf(mx0, __shfl_xor_sync(0xffffffffu, mx0, 2));
        mx1 = fmaxf(mx1, __shfl_xor_sync(0xffffffffu, mx1, 1));
        mx1 = fmaxf(mx1, __shfl_xor_sync(0xffffffffu, mx1, 2));
        float mn0 = fmaxf(m0, mx0), mn1 = fmaxf(m1, mx1);
        float cr0 = __expf(m0 - mn0), cr1 = __expf(m1 - mn1);
        float sum0 = 0.f, sum1 = 0.f;
#pragma unroll
        for (int ni = 0; ni < 16; ni++) {
#pragma unroll
            for (int c = 0; c < 2; c++) {
                float p0 = __expf(sacc[ni][c] - mn0);
                float p1 = __expf(sacc[ni][2 + c] - mn1);
                sacc[ni][c]     = p0;
                sacc[ni][2 + c] = p1;
                sum0 += p0;
                sum1 += p1;
            }
        }
        sum0 += __shfl_xor_sync(0xffffffffu, sum0, 1);
        sum0 += __shfl_xor_sync(0xffffffffu, sum0, 2);
        sum1 += __shfl_xor_sync(0xffffffffu, sum1, 1);
        sum1 += __shfl_xor_sync(0xffffffffu, sum1, 2);
        l0 = l0 * cr0 + sum0;
        l1 = l1 * cr1 + sum1;
        m0 = mn0; m1 = mn1;

#pragma unroll
        for (int ni = 0; ni < 16; ni++) {
            oacc[ni][0] *= cr0; oacc[ni][1] *= cr0;
            oacc[ni][2] *= cr1; oacc[ni][3] *= cr1;
        }

        // ---- write P (half2 packs) ----
        uint32_t* pr0 = Ps + (wm + gID) * PSTR;
        uint32_t* pr1 = pr0 + 8 * PSTR;
#pragma unroll
        for (int ni = 0; ni < 16; ni++) {
            pr0[ni * 4 + tig] = h2bits(sacc[ni][0], sacc[ni][1]);
            pr1[ni * 4 + tig] = h2bits(sacc[ni][2], sacc[ni][3]);
        }
        __syncwarp();

        // ---- O += P @ V  (V rows = d, k = s contiguous) ----
        const uint32_t* vbuf = Vsb + (st & 1) * 128 * VSTR;
        const uint32_t* prow = Ps + (wm + gID) * PSTR;
#pragma unroll
        for (int kk = 0; kk < 8; kk++) {
            const int k0 = kk * 8;
            uint32_t a0 = prow[k0 + tig];
            uint32_t a1 = prow[8 * PSTR + k0 + tig];
            uint32_t a2 = prow[k0 + tig + 4];
            uint32_t a3 = prow[8 * PSTR + k0 + tig + 4];
#pragma unroll
            for (int ni = 0; ni < 16; ni++) {
                const uint32_t* vp = vbuf + (gID + ni * 8) * VSTR + k0;
                MMA_F16(oacc[ni], a0, a1, a2, a3, vp[tig], vp[tig + 4]);
            }
        }
        __syncthreads();     // PV done -> V(st) buffer free

        if (st + 2 < ntiles) LOADV(st + 2);
        CP_COMMIT();
    }

    float li0 = 1.f / l0, li1 = 1.f / l1;
    __half* y0 = Y + (size_t)(b * TT + row0) * DD + hh * HD;
    __half* y1 = y0 + (size_t)8 * DD;
#pragma unroll
    for (int ni = 0; ni < 16; ni++) {
        int c = ni * 8 + tig * 2;
        *(__half2*)(y0 + c) = __floats2half2_rn(oacc[ni][0] * li0,
                                                oacc[ni][1] * li0);
        *(__half2*)(y1 + c) = __floats2half2_rn(oacc[ni][2] * li1,
                                                oacc[ni][3] * li1);
    }
}

// ---------------------------------------------------------------------------
extern "C" void kernel_launch(void* const* d_in, const int* in_sizes, int n_in,
                              void* d_out, int out_size)
{
    const float* x  = (const float*)d_in[0];
    const float* Wq = (const float*)d_in[1];
    const float* Wk = (const float*)d_in[2];
    const float* Wv = (const float*)d_in[3];
    const float* Wo = (const float*)d_in[4];
    float* out = (float*)d_out;

    __half *xh, *Wqkvh, *Woh, *Qh, *Kh, *Vt, *Yh;
    cudaGetSymbolAddress((void**)&xh,    g_xh);
    cudaGetSymbolAddress((void**)&Wqkvh, g_Wqkvh);
    cudaGetSymbolAddress((void**)&Woh,   g_Woh);
    cudaGetSymbolAddress((void**)&Qh,    g_Qh);
    cudaGetSymbolAddress((void**)&Kh,    g_Kh);
    cudaGetSymbolAddress((void**)&Vt,    g_Vt);
    cudaGetSymbolAddress((void**)&Yh,    g_Yh);

    static bool attr_set = false;
    if (!attr_set) {
        cudaFuncSetAttribute(gemm_qkv_h,
                             cudaFuncAttributeMaxDynamicSharedMemorySize,
                             GEMM_SMEM);
        cudaFuncSetAttribute(gemm_wo_h,
                             cudaFuncAttributeMaxDynamicSharedMemorySize,
                             GEMM_SMEM);
        cudaFuncSetAttribute(attn_h,
                             cudaFuncAttributeMaxDynamicSharedMemorySize,
                             ATTN_SMEM);
        attr_set = true;
    }

    rope_table_kernel<<<TT, 64>>>();
    cvt_h<<<(MROWS * DD) / 1024, 256>>>(x, xh);
    tr_cvt_all<<<dim3(64, 64, 4), dim3(32, 8)>>>(Wq, Wk, Wv, Wo, Wqkvh, Woh);

    // Fused QKV projection + RoPE (+Q scaling) -> half Qh/Kh, transposed Vt
    gemm_qkv_h<<<dim3(NQKV / 128, MROWS / 128), 128, GEMM_SMEM>>>(
        xh, Wqkvh, Qh, Kh, Vt);

    // FP16 flash attention (BQ=BS=128) -> Yh
    attn_h<<<dim3(TT / 128, NH, BB), 256, ATTN_SMEM>>>(Qh, Kh, Vt, Yh);

    // Output projection
    gemm_wo_h<<<dim3(DD / 128, MROWS / 128), 128, GEMM_SMEM>>>(Yh, Woh, out);
}

// round 13
// speedup vs baseline: 13.1959x; 1.1972x over previous
#include <cuda_runtime.h>
#include <cuda_fp16.h>
#include <math.h>
#include <stdint.h>

#define BB 4
#define TT 1024
#define DD 2048
#define NH 16
#define NKV 4
#define HD 128
#define MROWS (BB*TT)    // 4096
#define NQKV 3072
#define SCALE 0.08838834764831845f   // 1/sqrt(128)

// Scratch (device globals; no runtime allocation)
__device__ __half   g_xh[MROWS * DD];          // x fp16 [4096][2048]
__device__ __half   g_Wqkvh[NQKV * DD];        // [Wq|Wk|Wv]^T fp16 [3072][2048]
__device__ __half   g_Woh[DD * DD];            // Wo^T fp16
__device__ __half   g_Qh[BB * NH * TT * HD];   // roped+scaled Q half [b][h][t][d]
__device__ __half   g_Kh[BB * NKV * TT * HD];  // roped K half [b][g][t][d]
__device__ __half   g_Vt[BB * NKV * HD * TT];  // V half TRANSPOSED [b][g][d][t]
__device__ __half   g_Yh[MROWS * DD];          // attention out half
__device__ float    g_cos[TT * 64];
__device__ float    g_sin[TT * 64];

#define MMA_F16(ACC, A0, A1, A2, A3, B0, B1)                                   \
    asm volatile(                                                              \
        "mma.sync.aligned.m16n8k16.row.col.f32.f16.f16.f32 "                   \
        "{%0,%1,%2,%3}, {%4,%5,%6,%7}, {%8,%9}, {%0,%1,%2,%3};"                \
        : "+f"((ACC)[0]), "+f"((ACC)[1]), "+f"((ACC)[2]), "+f"((ACC)[3])       \
        : "r"(A0), "r"(A1), "r"(A2), "r"(A3), "r"(B0), "r"(B1))

#define LDSM_X4(R, ADDR)                                                       \
    asm volatile(                                                              \
        "ldmatrix.sync.aligned.m8n8.x4.shared.b16 {%0,%1,%2,%3}, [%4];"        \
        : "=r"((R)[0]), "=r"((R)[1]), "=r"((R)[2]), "=r"((R)[3])               \
        : "r"(ADDR))

__device__ __forceinline__ void cp16(uint32_t dst, const void* src) {
    asm volatile("cp.async.cg.shared.global [%0], [%1], 16;" ::
                 "r"(dst), "l"(src));
}
#define CP_COMMIT() asm volatile("cp.async.commit_group;")
#define CP_WAIT(n)  asm volatile("cp.async.wait_group %0;" :: "n"(n) : "memory")

__device__ __forceinline__ uint32_t h2bits(float a, float b) {
    __half2 h = __floats2half2_rn(a, b);
    return *(uint32_t*)&h;
}

// ---------------------------------------------------------------------------
// FP16 GEMM: C = A[half, M x 2048 row-major] @ B^T[half, N x 2048 n-major].
// CTA 128x128, 128 threads (4 warps, 2Mx2N, warp 64x64), KT=32, 4 stages.
// Fragment loads via ldmatrix.x4 (row stride 80 B, phase conflict-free).
// ---------------------------------------------------------------------------
#define HSTR 20
#define HAW  (128*HSTR)
#define HSTG (2*HAW)
#define GEMM_SMEM (4*HSTG*4)      // 81920 B

// Requires: a_off, b_off (lane-dependent LDSM byte offsets) defined by caller.
#define GEMM_MAINLOOP_H(Aptr, Bptr)                                            \
    auto LOAD = [&](int kt, int s) {                                           \
        uint32_t abase = smaddr + (uint32_t)(s * HSTG) * 4;                    \
        _Pragma("unroll")                                                      \
        for (int p = 0; p < 4; p++) {                                          \
            int id = tid + p * 128;                                            \
            int row = id >> 2, ch = id & 3;                                    \
            cp16(abase + (uint32_t)(row * 80 + ch * 16),                       \
                 (Aptr) + (size_t)(bm + row) * DD + kt * 32 + ch * 8);         \
        }                                                                      \
        uint32_t bbase = abase + HAW * 4;                                      \
        _Pragma("unroll")                                                      \
        for (int p = 0; p < 4; p++) {                                          \
            int id = tid + p * 128;                                            \
            int row = id >> 2, ch = id & 3;                                    \
            cp16(bbase + (uint32_t)(row * 80 + ch * 16),                       \
                 (Bptr) + (size_t)(bn + row) * DD + kt * 32 + ch * 8);         \
        }                                                                      \
        CP_COMMIT();                                                           \
    };                                                                         \
    LOAD(0, 0); LOAD(1, 1); LOAD(2, 2);                                        \
    for (int kt = 0; kt < 64; kt++) {                                          \
        CP_WAIT(2);                                                            \
        __syncthreads();                                                       \
        if (kt + 3 < 64) LOAD(kt + 3, (kt + 3) & 3);                           \
        else CP_COMMIT();                                                      \
        const uint32_t sbase = smaddr + (uint32_t)((kt & 3) * HSTG) * 4;       \
        const uint32_t aaddr = sbase + a_off;                                  \
        const uint32_t baddr = sbase + HAW * 4 + b_off;                        \
        _Pragma("unroll")                                                      \
        for (int kk = 0; kk < 2; kk++) {                                       \
            uint32_t af[4][4], bf[4][4];                                       \
            _Pragma("unroll")                                                  \
            for (int mi = 0; mi < 4; mi++)                                     \
                LDSM_X4(af[mi], aaddr + mi * 1280 + kk * 32);                  \
            _Pragma("unroll")                                                  \
            for (int np = 0; np < 4; np++)                                     \
                LDSM_X4(bf[np], baddr + np * 1280 + kk * 32);                  \
            _Pragma("unroll")                                                  \
            for (int mi = 0; mi < 4; mi++)                                     \
                _Pragma("unroll")                                              \
                for (int ni = 0; ni < 8; ni++)                                 \
                    MMA_F16(acc[mi][ni], af[mi][0], af[mi][1], af[mi][2],      \
                            af[mi][3], bf[ni >> 1][(ni & 1) * 2],              \
                            bf[ni >> 1][(ni & 1) * 2 + 1]);                    \
        }                                                                      \
    }

#define GEMM_LDSM_OFFS()                                                       \
    const uint32_t a_off = (uint32_t)((wm + (lane & 7) + ((lane >> 3) & 1) * 8)\
                                       * 80 + ((lane >> 4) & 1) * 16);         \
    const uint32_t b_off = (uint32_t)((wn + (lane & 7) + ((lane >> 4) & 1) * 8)\
                                       * 80 + ((lane >> 3) & 1) * 16)

// ---------------------------------------------------------------------------
// Fused QKV projection (fp16) + RoPE epilogue. Q is pre-scaled by 1/sqrt(d).
// ---------------------------------------------------------------------------
__global__ __launch_bounds__(128, 2) void gemm_qkv_h(
    const __half* __restrict__ A, const __half* __restrict__ B,
    __half* __restrict__ Qh, __half* __restrict__ Kh,
    __half* __restrict__ Vt)
{
    extern __shared__ uint32_t smg[];
    const uint32_t smaddr = (uint32_t)__cvta_generic_to_shared(smg);

    const int tid  = threadIdx.x;
    const int bm   = blockIdx.y * 128;
    const int bn   = blockIdx.x * 128;
    const int warp = tid >> 5, lane = tid & 31;
    const int wm   = (warp & 1) * 64;
    const int wn   = (warp >> 1) * 64;
    const int gID  = lane >> 2, tig = lane & 3;
    GEMM_LDSM_OFFS();

    float acc[4][8][4];
#pragma unroll
    for (int i = 0; i < 4; i++)
#pragma unroll
        for (int j = 0; j < 8; j++)
#pragma unroll
            for (int l = 0; l < 4; l++) acc[i][j][l] = 0.f;

    GEMM_MAINLOOP_H(A, B)

    __syncthreads();
    float* Cs = (float*)smg;       // 128*132 = 16896 u32 < 4*5120
#pragma unroll
    for (int mi = 0; mi < 4; mi++) {
        const int r0 = wm + mi * 16 + gID;
#pragma unroll
        for (int ni = 0; ni < 8; ni++) {
            const int c = wn + ni * 8 + tig * 2;
            Cs[r0 * 132 + c]     = acc[mi][ni][0];
            Cs[r0 * 132 + c + 1] = acc[mi][ni][1];
            Cs[(r0 + 8) * 132 + c]     = acc[mi][ni][2];
            Cs[(r0 + 8) * 132 + c + 1] = acc[mi][ni][3];
        }
    }
    __syncthreads();

    const int bb = bm >> 10;
    if (bn < 2560) {
        __half* dst;
        int head, hs;
        float sc;
        if (bn < 2048) { dst = Qh; head = bn >> 7;          hs = NH;  sc = SCALE; }
        else           { dst = Kh; head = (bn - 2048) >> 7; hs = NKV; sc = 1.f;   }
#pragma unroll 4
        for (int p = 0; p < 32; p++) {
            int idx = tid + p * 128;
            int r = idx >> 5;
            int d2 = (idx & 31) << 1;
            int t = (bm + r) & (TT - 1);
            float lo0 = Cs[r * 132 + d2] * sc;
            float lo1 = Cs[r * 132 + d2 + 1] * sc;
            float hi0 = Cs[r * 132 + d2 + 64] * sc;
            float hi1 = Cs[r * 132 + d2 + 65] * sc;
            float2 cc = *(const float2*)(g_cos + t * 64 + d2);
            float2 ss = *(const float2*)(g_sin + t * 64 + d2);
            __half* o = dst + ((size_t)(bb * hs + head) * TT + t) * HD;
            *(__half2*)(o + d2) =
                __floats2half2_rn(lo0 * cc.x - hi0 * ss.x,
                                  lo1 * cc.y - hi1 * ss.y);
            *(__half2*)(o + d2 + 64) =
                __floats2half2_rn(hi0 * cc.x + lo0 * ss.x,
                                  hi1 * cc.y + lo1 * ss.y);
        }
    } else {
        const int head = (bn - 2560) >> 7;
        const int d = tid;
        const int t0 = bm & (TT - 1);
        __half* o = Vt + ((size_t)(bb * NKV + head) * HD + d) * TT + t0;
#pragma unroll 8
        for (int tq = 0; tq < 128; tq += 2) {
            float v0 = Cs[tq * 132 + d];
            float v1 = Cs[(tq + 1) * 132 + d];
            *(__half2*)(o + tq) = __floats2half2_rn(v0, v1);
        }
    }
}

// ---------------------------------------------------------------------------
// Wo projection (fp16): out fp32 = Yh @ Woh^T-tile
// ---------------------------------------------------------------------------
__global__ __launch_bounds__(128, 2) void gemm_wo_h(
    const __half* __restrict__ A, const __half* __restrict__ B,
    float* __restrict__ C)
{
    extern __shared__ uint32_t smg[];
    const uint32_t smaddr = (uint32_t)__cvta_generic_to_shared(smg);

    const int tid  = threadIdx.x;
    const int bm   = blockIdx.y * 128;
    const int bn   = blockIdx.x * 128;
    const int warp = tid >> 5, lane = tid & 31;
    const int wm   = (warp & 1) * 64;
    const int wn   = (warp >> 1) * 64;
    const int gID  = lane >> 2, tig = lane & 3;
    GEMM_LDSM_OFFS();

    float acc[4][8][4];
#pragma unroll
    for (int i = 0; i < 4; i++)
#pragma unroll
        for (int j = 0; j < 8; j++)
#pragma unroll
            for (int l = 0; l < 4; l++) acc[i][j][l] = 0.f;

    GEMM_MAINLOOP_H(A, B)

#pragma unroll
    for (int mi = 0; mi < 4; mi++) {
        const int r0 = bm + wm + mi * 16 + gID;
#pragma unroll
        for (int ni = 0; ni < 8; ni++) {
            const int c = bn + wn + ni * 8 + tig * 2;
            *(float2*)&C[(size_t)r0 * DD + c] =
                make_float2(acc[mi][ni][0], acc[mi][ni][1]);
            *(float2*)&C[(size_t)(r0 + 8) * DD + c] =
                make_float2(acc[mi][ni][2], acc[mi][ni][3]);
        }
    }
}

// ---------------------------------------------------------------------------
// Prep kernels
// ---------------------------------------------------------------------------
__global__ void cvt_h(const float* __restrict__ in, __half* __restrict__ out)
{
    int i = (blockIdx.x * 256 + threadIdx.x) * 4;
    float4 v = *(const float4*)(in + i);
    *(__half2*)(out + i)     = __floats2half2_rn(v.x, v.y);
    *(__half2*)(out + i + 2) = __floats2half2_rn(v.z, v.w);
}

__global__ void tr_cvt_all(const float* __restrict__ Wq,
                           const float* __restrict__ Wk,
                           const float* __restrict__ Wv,
                           const float* __restrict__ Wo,
                           __half* __restrict__ Wqkvh,
                           __half* __restrict__ Woh)
{
    __shared__ float tile[32][33];
    const int z = blockIdx.z;
    const float* src;
    __half* dst;
    int C, row_off;
    if      (z == 0) { src = Wq; dst = Wqkvh; C = 2048; row_off = 0;    }
    else if (z == 1) { src = Wk; dst = Wqkvh; C = 512;  row_off = 2048; }
    else if (z == 2) { src = Wv; dst = Wqkvh; C = 512;  row_off = 2560; }
    else             { src = Wo; dst = Woh;   C = 2048; row_off = 0;    }

    int bx = blockIdx.x * 32;
    if (bx >= C) return;
    int by = blockIdx.y * 32;
    int x = threadIdx.x, y = threadIdx.y;   // 32 x 8
#pragma unroll
    for (int j = 0; j < 32; j += 8)
        tile[y + j][x] = src[(size_t)(by + y + j) * C + bx + x];
    __syncthreads();
#pragma unroll
    for (int j = 0; j < 32; j += 8)
        dst[(size_t)(row_off + bx + y + j) * 2048 + by + x] =
            __float2half(tile[x][y + j]);
}

__global__ void rope_table_kernel()
{
    int t = blockIdx.x;
    int i = threadIdx.x;
    float inv = powf(10000.0f, -(float)i / 64.0f);
    float ang = (float)t * inv;
    g_cos[t * 64 + i] = cosf(ang);
    g_sin[t * 64 + i] = sinf(ang);
}

// ---------------------------------------------------------------------------
// FP16 flash attention, causal, GQA. BQ=128, BS=128. (unchanged from R11)
// ---------------------------------------------------------------------------
#define QSTR 68
#define KSTR 68
#define VSTR 68
#define PSTR 68
#define ATTN_SMEM (43520 * 4)

__global__ __launch_bounds__(256, 1) void attn_h(
    const __half* __restrict__ Qh, const __half* __restrict__ Kh,
    const __half* __restrict__ Vt, __half* __restrict__ Y)
{
    extern __shared__ uint32_t sma[];
    uint32_t* Qs  = sma;
    uint32_t* Ks  = Qs + 128 * QSTR;
    uint32_t* Vsb = Ks + 128 * KSTR;
    uint32_t* Ps  = Vsb + 2 * 128 * VSTR;
    const uint32_t smaddr = (uint32_t)__cvta_generic_to_shared(sma);
    const uint32_t Qs_a = smaddr;
    const uint32_t Ks_a = Qs_a + 128 * QSTR * 4;
    const uint32_t Vs_a = Ks_a + 128 * KSTR * 4;

    const int tid  = threadIdx.x;
    const int warp = tid >> 5, lane = tid & 31;
    const int gID  = lane >> 2, tig = lane & 3;
    const int qt   = (gridDim.x - 1) - blockIdx.x;
    const int hh   = blockIdx.y;
    const int b    = blockIdx.z;
    const int gkv  = hh >> 2;
    const int q0   = qt * 128;
    const int wm   = warp * 16;
    const int row0 = q0 + wm + gID;

    const __half* Qbase = Qh + ((size_t)(b * NH + hh) * TT + q0) * HD;
    const __half* Kbase = Kh + (size_t)(b * NKV + gkv) * TT * HD;
    const __half* Vbase = Vt + (size_t)(b * NKV + gkv) * HD * TT;

    auto LOADQ = [&]() {
#pragma unroll
        for (int p = 0; p < 8; p++) {
            int id = tid + p * 256;
            int q = id >> 4, ch = id & 15;
            cp16(Qs_a + (uint32_t)(q * QSTR + ch * 4) * 4,
                 Qbase + q * HD + ch * 8);
        }
    };
    auto LOADK = [&](int st) {
        const __half* src = Kbase + (size_t)st * 128 * HD;
#pragma unroll
        for (int p = 0; p < 8; p++) {
            int id = tid + p * 256;
            int s = id >> 4, ch = id & 15;
            cp16(Ks_a + (uint32_t)(s * KSTR + ch * 4) * 4,
                 src + s * HD + ch * 8);
        }
    };
    auto LOADV = [&](int st) {
        const __half* src = Vbase + st * 128;
        uint32_t dbase = Vs_a + (uint32_t)((st & 1) * 128 * VSTR) * 4;
#pragma unroll
        for (int p = 0; p < 8; p++) {
            int id = tid + p * 256;
            int d = id >> 4, ch = id & 15;
            cp16(dbase + (uint32_t)(d * VSTR + ch * 4) * 4,
                 src + (size_t)d * TT + ch * 8);
        }
    };

    const int ntiles = qt + 1;

    LOADQ(); LOADK(0); LOADV(0); CP_COMMIT();
    if (ntiles > 1) LOADV(1);
    CP_COMMIT();

    float m0 = -1e30f, m1 = -1e30f, l0 = 0.f, l1 = 0.f;
    float oacc[16][4];
#pragma unroll
    for (int i = 0; i < 16; i++)
#pragma unroll
        for (int j = 0; j < 4; j++) oacc[i][j] = 0.f;

    for (int st = 0; st < ntiles; st++) {
        const int s0 = st * 128;

        CP_WAIT(1);
        __syncthreads();

        float sacc[16][4];
#pragma unroll
        for (int i = 0; i < 16; i++)
#pragma unroll
            for (int j = 0; j < 4; j++) sacc[i][j] = 0.f;

        const uint32_t* qrow = Qs + (wm + gID) * QSTR;
#pragma unroll
        for (int kk = 0; kk < 8; kk++) {
            const int k0 = kk * 8;
            uint32_t a0 = qrow[k0 + tig];
            uint32_t a1 = qrow[8 * QSTR + k0 + tig];
            uint32_t a2 = qrow[k0 + tig + 4];
            uint32_t a3 = qrow[8 * QSTR + k0 + tig + 4];
#pragma unroll
            for (int ni = 0; ni < 16; ni++) {
                const uint32_t* kp = Ks + (gID + ni * 8) * KSTR + k0;
                MMA_F16(sacc[ni], a0, a1, a2, a3, kp[tig], kp[tig + 4]);
            }
        }
        __syncthreads();

        if (st + 1 < ntiles) LOADK(st + 1);
        CP_COMMIT();

        const int lim0 = row0 - s0;
        const int lim1 = lim0 + 8;
        const bool diag = (st == qt);
        float mx0 = -1e30f, mx1 = -1e30f;
#pragma unroll
        for (int ni = 0; ni < 16; ni++) {
#pragma unroll
            for (int c = 0; c < 2; c++) {
                int j = ni * 8 + tig * 2 + c;
                float v0 = sacc[ni][c];
                float v1 = sacc[ni][2 + c];
                if (diag) {
                    if (j > lim0) v0 = -1e30f;
                    if (j > lim1) v1 = -1e30f;
                }
                sacc[ni][c]     = v0;
                sacc[ni][2 + c] = v1;
                mx0 = fmaxf(mx0, v0);
                mx1 = fmaxf(mx1, v1);
            }
        }
        mx0 = fmaxf(mx0, __shfl_xor_sync(0xffffffffu, mx0, 1));
        mx0 = fmaxf(mx0, __shfl_xor_sync(0xffffffffu, mx0, 2));
        mx1 = fmaxf(mx1, __shfl_xor_sync(0xffffffffu, mx1, 1));
        mx1 = fmaxf(mx1, __shfl_xor_sync(0xffffffffu, mx1, 2));
        float mn0 = fmaxf(m0, mx0), mn1 = fmaxf(m1, mx1);
        float cr0 = __expf(m0 - mn0), cr1 = __expf(m1 - mn1);
        float sum0 = 0.f, sum1 = 0.f;
#pragma unroll
        for (int ni = 0; ni < 16; ni++) {
#pragma unroll
            for (int c = 0; c < 2; c++) {
                float p0 = __expf(sacc[ni][c] - mn0);
                float p1 = __expf(sacc[ni][2 + c] - mn1);
                sacc[ni][c]     = p0;
                sacc[ni][2 + c] = p1;
                sum0 += p0;
                sum1 += p1;
            }
        }
        sum0 += __shfl_xor_sync(0xffffffffu, sum0, 1);
        sum0 += __shfl_xor_sync(0xffffffffu, sum0, 2);
        sum1 += __shfl_xor_sync(0xffffffffu, sum1, 1);
        sum1 += __shfl_xor_sync(0xffffffffu, sum1, 2);
        l0 = l0 * cr0 + sum0;
        l1 = l1 * cr1 + sum1;
        m0 = mn0; m1 = mn1;

#pragma unroll
        for (int ni = 0; ni < 16; ni++) {
            oacc[ni][0] *= cr0; oacc[ni][1] *= cr0;
            oacc[ni][2] *= cr1; oacc[ni][3] *= cr1;
        }

        uint32_t* pr0 = Ps + (wm + gID) * PSTR;
        uint32_t* pr1 = pr0 + 8 * PSTR;
#pragma unroll
        for (int ni = 0; ni < 16; ni++) {
            pr0[ni * 4 + tig] = h2bits(sacc[ni][0], sacc[ni][1]);
            pr1[ni * 4 + tig] = h2bits(sacc[ni][2], sacc[ni][3]);
        }
        __syncwarp();

        const uint32_t* vbuf = Vsb + (st & 1) * 128 * VSTR;
        const uint32_t* prow = Ps + (wm + gID) * PSTR;
#pragma unroll
        for (int kk = 0; kk < 8; kk++) {
            const int k0 = kk * 8;
            uint32_t a0 = prow[k0 + tig];
            uint32_t a1 = prow[8 * PSTR + k0 + tig];
            uint32_t a2 = prow[k0 + tig + 4];
            uint32_t a3 = prow[8 * PSTR + k0 + tig + 4];
#pragma unroll
            for (int ni = 0; ni < 16; ni++) {
                const uint32_t* vp = vbuf + (gID + ni * 8) * VSTR + k0;
                MMA_F16(oacc[ni], a0, a1, a2, a3, vp[tig], vp[tig + 4]);
            }
        }
        __syncthreads();

        if (st + 2 < ntiles) LOADV(st + 2);
        CP_COMMIT();
    }

    float li0 = 1.f / l0, li1 = 1.f / l1;
    __half* y0 = Y + (size_t)(b * TT + row0) * DD + hh * HD;
    __half* y1 = y0 + (size_t)8 * DD;
#pragma unroll
    for (int ni = 0; ni < 16; ni++) {
        int c = ni * 8 + tig * 2;
        *(__half2*)(y0 + c) = __floats2half2_rn(oacc[ni][0] * li0,
                                                oacc[ni][1] * li0);
        *(__half2*)(y1 + c) = __floats2half2_rn(oacc[ni][2] * li1,
                                                oacc[ni][3] * li1);
    }
}

// ---------------------------------------------------------------------------
extern "C" void kernel_launch(void* const* d_in, const int* in_sizes, int n_in,
                              void* d_out, int out_size)
{
    const float* x  = (const float*)d_in[0];
    const float* Wq = (const float*)d_in[1];
    const float* Wk = (const float*)d_in[2];
    const float* Wv = (const float*)d_in[3];
    const float* Wo = (const float*)d_in[4];
    float* out = (float*)d_out;

    __half *xh, *Wqkvh, *Woh, *Qh, *Kh, *Vt, *Yh;
    cudaGetSymbolAddress((void**)&xh,    g_xh);
    cudaGetSymbolAddress((void**)&Wqkvh, g_Wqkvh);
    cudaGetSymbolAddress((void**)&Woh,   g_Woh);
    cudaGetSymbolAddress((void**)&Qh,    g_Qh);
    cudaGetSymbolAddress((void**)&Kh,    g_Kh);
    cudaGetSymbolAddress((void**)&Vt,    g_Vt);
    cudaGetSymbolAddress((void**)&Yh,    g_Yh);

    static bool attr_set = false;
    if (!attr_set) {
        cudaFuncSetAttribute(gemm_qkv_h,
                             cudaFuncAttributeMaxDynamicSharedMemorySize,
                             GEMM_SMEM);
        cudaFuncSetAttribute(gemm_wo_h,
                             cudaFuncAttributeMaxDynamicSharedMemorySize,
                             GEMM_SMEM);
        cudaFuncSetAttribute(attn_h,
                             cudaFuncAttributeMaxDynamicSharedMemorySize,
                             ATTN_SMEM);
        attr_set = true;
    }

    rope_table_kernel<<<TT, 64>>>();
    cvt_h<<<(MROWS * DD) / 1024, 256>>>(x, xh);
    tr_cvt_all<<<dim3(64, 64, 4), dim3(32, 8)>>>(Wq, Wk, Wv, Wo, Wqkvh, Woh);

    // Fused QKV projection + RoPE (+Q scaling) -> half Qh/Kh, transposed Vt
    gemm_qkv_h<<<dim3(NQKV / 128, MROWS / 128), 128, GEMM_SMEM>>>(
        xh, Wqkvh, Qh, Kh, Vt);

    // FP16 flash attention (BQ=BS=128) -> Yh
    attn_h<<<dim3(TT / 128, NH, BB), 256, ATTN_SMEM>>>(Qh, Kh, Vt, Yh);

    // Output projection
    gemm_wo_h<<<dim3(DD / 128, MROWS / 128), 128, GEMM_SMEM>>>(Yh, Woh, out);
}